// round 11
// baseline (speedup 1.0000x reference)
#include <cuda_runtime.h>
#include <cuda_fp16.h>
#include <math.h>
#include <cstdint>

#define BB 2
#define TT 2048
#define DD 1024
#define NH 16
#define HD 64      // NOPE_D + ROPE_D
#define NOPE 48
#define ROPED 16
#define RR 128
#define VD 64
#define KVB_N (NH * (NOPE + VD))   // 1792
#define MTOT (BB * TT)             // 4096
#define W1_ROWS 1280               // 1024 (Wq) + 128 (latent) + 16 (rope) + 112 pad

// ---------------- device scratch ----------------
__device__ __align__(256) __half g_qh[BB*NH*TT*HD], g_ql[BB*NH*TT*HD];
__device__ __align__(256) __half g_kh[BB*NH*TT*HD], g_kl[BB*NH*TT*HD];
__device__ __align__(256) __half g_vh[BB*NH*TT*VD];

__device__ __align__(256) __half g_xh [MTOT * DD];
__device__ __align__(256) __half g_W1h[W1_ROWS * DD], g_W1l[W1_ROWS * DD];
__device__ __align__(256) __half g_Wbh[KVB_N * RR],   g_Wbl[KVB_N * RR];
__device__ __align__(256) __half g_Woh[DD * DD],      g_Wol[DD * DD];
__device__ __align__(256) __half g_lth[MTOT * RR];
__device__ __align__(256) __half g_aoh[MTOT * DD];

// ======================= helpers =======================
__device__ __forceinline__ uint32_t smem_u32(const void* p) {
    uint32_t a;
    asm("{ .reg .u64 t; cvta.to.shared.u64 t, %1; cvt.u32.u64 %0, t; }" : "=r"(a) : "l"(p));
    return a;
}
__device__ __forceinline__ void mma16816(float* c, const uint32_t* a, const uint32_t* b) {
    asm volatile("mma.sync.aligned.m16n8k16.row.col.f32.f16.f16.f32 "
        "{%0,%1,%2,%3}, {%4,%5,%6,%7}, {%8,%9}, {%0,%1,%2,%3};"
        : "+f"(c[0]), "+f"(c[1]), "+f"(c[2]), "+f"(c[3])
        : "r"(a[0]), "r"(a[1]), "r"(a[2]), "r"(a[3]), "r"(b[0]), "r"(b[1]));
}
// fp16-accumulate variant (rate probe)
__device__ __forceinline__ void mma16816h(uint32_t* c, const uint32_t* a, const uint32_t* b) {
    asm volatile("mma.sync.aligned.m16n8k16.row.col.f16.f16.f16.f16 "
        "{%0,%1}, {%2,%3,%4,%5}, {%6,%7}, {%0,%1};"
        : "+r"(c[0]), "+r"(c[1])
        : "r"(a[0]), "r"(a[1]), "r"(a[2]), "r"(a[3]), "r"(b[0]), "r"(b[1]));
}
__device__ __forceinline__ void ldsm4(uint32_t* r, uint32_t addr) {
    asm volatile("ldmatrix.sync.aligned.m8n8.x4.shared.b16 {%0,%1,%2,%3}, [%4];"
        : "=r"(r[0]), "=r"(r[1]), "=r"(r[2]), "=r"(r[3]) : "r"(addr));
}
__device__ __forceinline__ void ldsm4t(uint32_t* r, uint32_t addr) {
    asm volatile("ldmatrix.sync.aligned.m8n8.x4.trans.shared.b16 {%0,%1,%2,%3}, [%4];"
        : "=r"(r[0]), "=r"(r[1]), "=r"(r[2]), "=r"(r[3]) : "r"(addr));
}
__device__ __forceinline__ uint32_t packh(float lo, float hi) {
    uint32_t d;
    asm("cvt.rn.f16x2.f32 %0, %1, %2;" : "=r"(d) : "f"(hi), "f"(lo));
    return d;
}
__device__ __forceinline__ uint32_t pack_lo_resid(float v0, float v1) {
    float h0 = __half2float(__float2half(v0));
    float h1 = __half2float(__float2half(v1));
    return packh(v0 - h0, v1 - h1);
}
__device__ __forceinline__ void unpack2(uint32_t p, float& lo, float& hi) {
    __half2 h = *(__half2*)&p;
    lo = __low2float(h); hi = __high2float(h);
}

// ======================= fused conversions =======================
#define QX  (MTOT * DD / 4)
#define QW1 (W1_ROWS * DD / 4)
#define QWB (KVB_N * RR / 4)
#define QWO (DD * DD / 4)
#define QTOT (QX + QW1 + QWB + QWO)

__device__ __forceinline__ void do_hl(const float* s, __half* dh, __half* dl, int e) {
    float4 v = *(const float4*)(s + e);
    __half h0 = __float2half(v.x), h1 = __float2half(v.y);
    __half h2 = __float2half(v.z), h3 = __float2half(v.w);
    ((__half2*)(dh + e))[0] = __half2(h0, h1);
    ((__half2*)(dh + e))[1] = __half2(h2, h3);
    ((__half2*)(dl + e))[0] = __half2(__float2half(v.x - __half2float(h0)),
                                      __float2half(v.y - __half2float(h1)));
    ((__half2*)(dl + e))[1] = __half2(__float2half(v.z - __half2float(h2)),
                                      __float2half(v.w - __half2float(h3)));
}

__global__ __launch_bounds__(256) void cvt_all(
    const float* __restrict__ x,    const float* __restrict__ Wq,
    const float* __restrict__ Wkva, const float* __restrict__ Wkvb,
    const float* __restrict__ Wo)
{
    int qi = blockIdx.x * blockDim.x + threadIdx.x;
    if (qi >= QTOT) return;
    if (qi < QX) {
        int e = qi * 4;
        float4 v = *(const float4*)(x + e);
        ((__half2*)(g_xh + e))[0] = __half2(__float2half(v.x), __float2half(v.y));
        ((__half2*)(g_xh + e))[1] = __half2(__float2half(v.z), __float2half(v.w));
        return;
    }
    qi -= QX;
    if (qi < QW1) {
        int e = qi * 4;
        if (e < DD * DD) { do_hl(Wq, g_W1h, g_W1l, e); }
        else if (e < (DD + 144) * DD) {
            float4 v = *(const float4*)(Wkva + (e - DD * DD));
            __half h0 = __float2half(v.x), h1 = __float2half(v.y);
            __half h2 = __float2half(v.z), h3 = __float2half(v.w);
            ((__half2*)(g_W1h + e))[0] = __half2(h0, h1);
            ((__half2*)(g_W1h + e))[1] = __half2(h2, h3);
            ((__half2*)(g_W1l + e))[0] = __half2(__float2half(v.x - __half2float(h0)),
                                                 __float2half(v.y - __half2float(h1)));
            ((__half2*)(g_W1l + e))[1] = __half2(__float2half(v.z - __half2float(h2)),
                                                 __float2half(v.w - __half2float(h3)));
        } else {
            __half2 z(__half(0.f), __half(0.f));
            ((__half2*)(g_W1h + e))[0] = z; ((__half2*)(g_W1h + e))[1] = z;
            ((__half2*)(g_W1l + e))[0] = z; ((__half2*)(g_W1l + e))[1] = z;
        }
        return;
    }
    qi -= QW1;
    if (qi < QWB) { do_hl(Wkvb, g_Wbh, g_Wbl, qi * 4); return; }
    qi -= QWB;
    do_hl(Wo, g_Woh, g_Wol, qi * 4);
}

// ======================= shared GEMM plumbing =======================
#define GPAD 40
#define GTILE_B (128 * GPAD * 2)
#define GBUF_B  (3 * GTILE_B)
#define NSTAGE 3

#define GEMM_LOAD_CHUNK(ch, buf)                                               \
    do {                                                                       \
        const int k0b = ((ch) << 5) * 2;                                       \
        _Pragma("unroll")                                                      \
        for (int it = 0; it < 6; it++) {                                       \
            int i = tid + it * 256;                                            \
            int mat = i >> 9, rem = i & 511;                                   \
            int row = rem >> 2, seg = rem & 3;                                 \
            const char* src = base[mat] + (size_t)row * ldbytes + k0b + seg * 16; \
            uint32_t dst = smem_base + (buf) * GBUF_B + mat * GTILE_B          \
                         + (row * GPAD + seg * 8) * 2;                         \
            asm volatile("cp.async.cg.shared.global [%0], [%1], 16;" :: "r"(dst), "l"(src)); \
        }                                                                      \
        asm volatile("cp.async.commit_group;");                                \
    } while (0)

// ======================= proj1 =======================
__global__ __launch_bounds__(256, 2) void proj1_gemm(
    const float* __restrict__ cosp, const float* __restrict__ sinp,
    const float* __restrict__ qw,   const float* __restrict__ kvaw)
{
    extern __shared__ __align__(16) char smem[];
    const int tid = threadIdx.x, wid = tid >> 5, lane = tid & 31;
    const int m0 = blockIdx.y * 128, n0 = blockIdx.x * 128;
    uint32_t smem_base = smem_u32(smem);

    const char* base[3] = { (const char*)(g_xh  + (size_t)m0 * DD),
                            (const char*)(g_W1h + (size_t)n0 * DD),
                            (const char*)(g_W1l + (size_t)n0 * DD) };
    const size_t ldbytes = (size_t)DD * 2;
    const int nch = DD >> 5;

    const int lm = lane & 15, lh = lane >> 4;
    const int g = lane >> 3, r8 = lane & 7;
    const int r4 = lane >> 2, c2 = (lane & 3) * 2;

    float acc[16][4];
    #pragma unroll
    for (int i = 0; i < 16; i++)
        #pragma unroll
        for (int e = 0; e < 4; e++) acc[i][e] = 0.f;

    GEMM_LOAD_CHUNK(0, 0);
    GEMM_LOAD_CHUNK(1, 1);

    for (int ch = 0; ch < nch; ch++) {
        asm volatile("cp.async.wait_group 1;");
        __syncthreads();
        if (ch + 2 < nch) { GEMM_LOAD_CHUNK(ch + 2, (ch + 2) % NSTAGE); }
        else asm volatile("cp.async.commit_group;");
        const uint32_t smA  = smem_base + (ch % NSTAGE) * GBUF_B;
        const uint32_t smBh = smA + GTILE_B;
        const uint32_t smBl = smBh + GTILE_B;
        #pragma unroll
        for (int k16 = 0; k16 < 2; k16++) {
            uint32_t a[4];
            ldsm4(a, smA + ((wid * 16 + lm) * GPAD + k16 * 16 + lh * 8) * 2);
            #pragma unroll
            for (int fp = 0; fp < 8; fp++) {
                int row = fp * 16 + ((g >> 1) << 3) + r8;
                int off = (row * GPAD + (g & 1) * 8 + k16 * 16) * 2;
                uint32_t t4[4];
                ldsm4(t4, smBh + off);
                mma16816(acc[fp*2],   a, t4);
                mma16816(acc[fp*2+1], a, t4 + 2);
                ldsm4(t4, smBl + off);
                mma16816(acc[fp*2],   a, t4);
                mma16816(acc[fp*2+1], a, t4 + 2);
            }
        }
    }

    const int bt0 = m0 + wid * 16 + r4;
    const int bt1 = bt0 + 8;
    const int t0 = bt0 & (TT - 1), t1 = bt1 & (TT - 1);
    const int b  = bt0 >> 11;

    if (blockIdx.x < 8) {
        float s00 = 0, s01 = 0, s10 = 0, s11 = 0;
        #pragma unroll
        for (int fn = 0; fn < 16; fn++) {
            float a0 = acc[fn][0]*acc[fn][0] + acc[fn][1]*acc[fn][1];
            float a1 = acc[fn][2]*acc[fn][2] + acc[fn][3]*acc[fn][3];
            if (fn < 8) { s00 += a0; s10 += a1; } else { s01 += a0; s11 += a1; }
        }
        #pragma unroll
        for (int o = 1; o <= 2; o <<= 1) {
            s00 += __shfl_xor_sync(~0u, s00, o);
            s01 += __shfl_xor_sync(~0u, s01, o);
            s10 += __shfl_xor_sync(~0u, s10, o);
            s11 += __shfl_xor_sync(~0u, s11, o);
        }
        float n00 = rsqrtf(s00 * (1.f/HD) + 1e-6f), n01 = rsqrtf(s01 * (1.f/HD) + 1e-6f);
        float n10 = rsqrtf(s10 * (1.f/HD) + 1e-6f), n11 = rsqrtf(s11 * (1.f/HD) + 1e-6f);
        #pragma unroll
        for (int fn = 0; fn < 16; fn++) {
            int d0 = (fn & 7) * 8 + c2;
            float w0 = qw[d0], w1 = qw[d0 + 1];
            float f0 = (fn < 8) ? n00 : n01, f1 = (fn < 8) ? n10 : n11;
            acc[fn][0] *= f0 * w0; acc[fn][1] *= f0 * w1;
            acc[fn][2] *= f1 * w0; acc[fn][3] *= f1 * w1;
        }
        float c00 = cosp[t0*8 + c2], c01 = cosp[t0*8 + c2 + 1];
        float sn00 = sinp[t0*8 + c2], sn01 = sinp[t0*8 + c2 + 1];
        float c10 = cosp[t1*8 + c2], c11 = cosp[t1*8 + c2 + 1];
        float sn10 = sinp[t1*8 + c2], sn11 = sinp[t1*8 + c2 + 1];
        #pragma unroll
        for (int hp = 0; hp < 2; hp++) {
            int f1i = hp * 8 + 6, f2i = f1i + 1;
            float x10 = acc[f1i][0], x11 = acc[f1i][1], x12 = acc[f1i][2], x13 = acc[f1i][3];
            float x20 = acc[f2i][0], x21 = acc[f2i][1], x22 = acc[f2i][2], x23 = acc[f2i][3];
            acc[f1i][0] = x10*c00 - x20*sn00; acc[f1i][1] = x11*c01 - x21*sn01;
            acc[f1i][2] = x12*c10 - x22*sn10; acc[f1i][3] = x13*c11 - x23*sn11;
            acc[f2i][0] = x20*c00 + x10*sn00; acc[f2i][1] = x21*c01 + x11*sn01;
            acc[f2i][2] = x22*c10 + x12*sn10; acc[f2i][3] = x23*c11 + x13*sn11;
        }
        #pragma unroll
        for (int fn = 0; fn < 16; fn++) {
            #pragma unroll
            for (int e = 0; e < 4; e++) acc[fn][e] *= 0.125f;
        }
        #pragma unroll
        for (int fn = 0; fn < 16; fn++) {
            int hg = (n0 >> 6) + (fn >> 3);
            int d  = (fn & 7) * 8 + c2;
            size_t a0 = (((size_t)(b * NH + hg)) * TT + t0) * HD + d;
            size_t a1 = (((size_t)(b * NH + hg)) * TT + t1) * HD + d;
            *(uint32_t*)(g_qh + a0) = packh(acc[fn][0], acc[fn][1]);
            *(uint32_t*)(g_ql + a0) = pack_lo_resid(acc[fn][0], acc[fn][1]);
            *(uint32_t*)(g_qh + a1) = packh(acc[fn][2], acc[fn][3]);
            *(uint32_t*)(g_ql + a1) = pack_lo_resid(acc[fn][2], acc[fn][3]);
        }
    } else if (blockIdx.x == 8) {
        float s0 = 0, s1 = 0;
        #pragma unroll
        for (int fn = 0; fn < 16; fn++) {
            s0 += acc[fn][0]*acc[fn][0] + acc[fn][1]*acc[fn][1];
            s1 += acc[fn][2]*acc[fn][2] + acc[fn][3]*acc[fn][3];
        }
        #pragma unroll
        for (int o = 1; o <= 2; o <<= 1) {
            s0 += __shfl_xor_sync(~0u, s0, o);
            s1 += __shfl_xor_sync(~0u, s1, o);
        }
        float n0f = rsqrtf(s0 * (1.f/RR) + 1e-6f), n1f = rsqrtf(s1 * (1.f/RR) + 1e-6f);
        #pragma unroll
        for (int fn = 0; fn < 16; fn++) {
            int r = fn * 8 + c2;
            float w0 = kvaw[r], w1 = kvaw[r + 1];
            *(uint32_t*)(g_lth + (size_t)bt0 * RR + r) =
                packh(acc[fn][0] * n0f * w0, acc[fn][1] * n0f * w1);
            *(uint32_t*)(g_lth + (size_t)bt1 * RR + r) =
                packh(acc[fn][2] * n1f * w0, acc[fn][3] * n1f * w1);
        }
    } else {
        float c00 = cosp[t0*8 + c2], c01 = cosp[t0*8 + c2 + 1];
        float sn00 = sinp[t0*8 + c2], sn01 = sinp[t0*8 + c2 + 1];
        float c10 = cosp[t1*8 + c2], c11 = cosp[t1*8 + c2 + 1];
        float sn10 = sinp[t1*8 + c2], sn11 = sinp[t1*8 + c2 + 1];
        float x10 = acc[0][0], x11 = acc[0][1], x12 = acc[0][2], x13 = acc[0][3];
        float x20 = acc[1][0], x21 = acc[1][1], x22 = acc[1][2], x23 = acc[1][3];
        float o10 = x10*c00 - x20*sn00, o11 = x11*c01 - x21*sn01;
        float o12 = x12*c10 - x22*sn10, o13 = x13*c11 - x23*sn11;
        float o20 = x20*c00 + x10*sn00, o21 = x21*c01 + x11*sn01;
        float o22 = x22*c10 + x12*sn10, o23 = x23*c11 + x13*sn11;
        uint32_t h1a = packh(o10, o11), l1a = pack_lo_resid(o10, o11);
        uint32_t h1b = packh(o12, o13), l1b = pack_lo_resid(o12, o13);
        uint32_t h2a = packh(o20, o21), l2a = pack_lo_resid(o20, o21);
        uint32_t h2b = packh(o22, o23), l2b = pack_lo_resid(o22, o23);
        #pragma unroll
        for (int h = 0; h < NH; h++) {
            size_t a0 = (((size_t)(b * NH + h)) * TT + t0) * HD + 48 + c2;
            size_t a1 = (((size_t)(b * NH + h)) * TT + t1) * HD + 48 + c2;
            *(uint32_t*)(g_kh + a0)     = h1a; *(uint32_t*)(g_kl + a0)     = l1a;
            *(uint32_t*)(g_kh + a0 + 8) = h2a; *(uint32_t*)(g_kl + a0 + 8) = l2a;
            *(uint32_t*)(g_kh + a1)     = h1b; *(uint32_t*)(g_kl + a1)     = l1b;
            *(uint32_t*)(g_kh + a1 + 8) = h2b; *(uint32_t*)(g_kl + a1 + 8) = l2b;
        }
    }
}

// ======================= kvb GEMM with fused scatter =======================
__global__ __launch_bounds__(256, 2) void kvb_gemm()
{
    extern __shared__ __align__(16) char smem[];
    const int tid = threadIdx.x, wid = tid >> 5, lane = tid & 31;
    const int warp_m = wid >> 2, warp_n = wid & 3;
    const int m0 = blockIdx.y * 128, n0 = blockIdx.x * 128;
    uint32_t smem_base = smem_u32(smem);

    const char* base[3] = { (const char*)(g_lth + (size_t)m0 * RR),
                            (const char*)(g_Wbh + (size_t)n0 * RR),
                            (const char*)(g_Wbl + (size_t)n0 * RR) };
    const size_t ldbytes = (size_t)RR * 2;
    const int nch = RR >> 5;

    const int lm = lane & 15, lh = lane >> 4;
    const int g = lane >> 3, r = lane & 7;
    const int r4 = lane >> 2, c2 = (lane & 3) * 2;

    float acc[4][4][4];
    #pragma unroll
    for (int i = 0; i < 4; i++)
        #pragma unroll
        for (int j = 0; j < 4; j++)
            #pragma unroll
            for (int e = 0; e < 4; e++) acc[i][j][e] = 0.f;

    GEMM_LOAD_CHUNK(0, 0);
    GEMM_LOAD_CHUNK(1, 1);

    for (int ch = 0; ch < nch; ch++) {
        asm volatile("cp.async.wait_group 1;");
        __syncthreads();
        if (ch + 2 < nch) { GEMM_LOAD_CHUNK(ch + 2, (ch + 2) % NSTAGE); }
        else asm volatile("cp.async.commit_group;");
        const uint32_t smA  = smem_base + (ch % NSTAGE) * GBUF_B;
        const uint32_t smBh = smA + GTILE_B;
        const uint32_t smBl = smBh + GTILE_B;
        #pragma unroll
        for (int k16 = 0; k16 < 2; k16++) {
            uint32_t a[4][4];
            #pragma unroll
            for (int fm = 0; fm < 4; fm++)
                ldsm4(a[fm], smA + ((warp_m * 64 + fm * 16 + lm) * GPAD
                                    + k16 * 16 + lh * 8) * 2);
            uint32_t bh[4][2], bl[4][2];
            #pragma unroll
            for (int fp = 0; fp < 2; fp++) {
                int row = warp_n * 32 + fp * 16 + ((g >> 1) << 3) + r;
                int off = (row * GPAD + (g & 1) * 8 + k16 * 16) * 2;
                uint32_t t4[4];
                ldsm4(t4, smBh + off);
                bh[fp*2][0]=t4[0]; bh[fp*2][1]=t4[1]; bh[fp*2+1][0]=t4[2]; bh[fp*2+1][1]=t4[3];
                ldsm4(t4, smBl + off);
                bl[fp*2][0]=t4[0]; bl[fp*2][1]=t4[1]; bl[fp*2+1][0]=t4[2]; bl[fp*2+1][1]=t4[3];
            }
            #pragma unroll
            for (int fm = 0; fm < 4; fm++)
                #pragma unroll
                for (int fn = 0; fn < 4; fn++) {
                    mma16816(acc[fm][fn], a[fm], bh[fn]);
                    mma16816(acc[fm][fn], a[fm], bl[fn]);
                }
        }
    }

    #pragma unroll
    for (int fm = 0; fm < 4; fm++) {
        int bt0 = m0 + warp_m * 64 + fm * 16 + r4;
        int bt1 = bt0 + 8;
        int t0 = bt0 & (TT - 1), t1 = bt1 & (TT - 1);
        int b  = bt0 >> 11;
        #pragma unroll
        for (int fn = 0; fn < 4; fn++) {
            int n = n0 + warp_n * 32 + fn * 8 + c2;
            int h = n / 112, rr2 = n % 112;
            size_t hb = (size_t)(b * NH + h) * TT;
            if (rr2 < NOPE) {
                size_t a0 = (hb + t0) * HD + rr2, a1 = (hb + t1) * HD + rr2;
                *(uint32_t*)(g_kh + a0) = packh(acc[fm][fn][0], acc[fm][fn][1]);
                *(uint32_t*)(g_kl + a0) = pack_lo_resid(acc[fm][fn][0], acc[fm][fn][1]);
                *(uint32_t*)(g_kh + a1) = packh(acc[fm][fn][2], acc[fm][fn][3]);
                *(uint32_t*)(g_kl + a1) = pack_lo_resid(acc[fm][fn][2], acc[fm][fn][3]);
            } else {
                int d = rr2 - NOPE;
                size_t a0 = (hb + t0) * VD + d, a1 = (hb + t1) * VD + d;
                *(uint32_t*)(g_vh + a0) = packh(acc[fm][fn][0], acc[fm][fn][1]);
                *(uint32_t*)(g_vh + a1) = packh(acc[fm][fn][2], acc[fm][fn][3]);
            }
        }
    }
}

// ======================= Wo GEMM =======================
__global__ __launch_bounds__(256, 2) void wo_gemm(float* __restrict__ C)
{
    extern __shared__ __align__(16) char smem[];
    const int tid = threadIdx.x, wid = tid >> 5, lane = tid & 31;
    const int warp_m = wid >> 2, warp_n = wid & 3;
    const int m0 = blockIdx.y * 128, n0 = blockIdx.x * 128;
    uint32_t smem_base = smem_u32(smem);

    const char* base[3] = { (const char*)(g_aoh + (size_t)m0 * DD),
                            (const char*)(g_Woh + (size_t)n0 * DD),
                            (const char*)(g_Wol + (size_t)n0 * DD) };
    const size_t ldbytes = (size_t)DD * 2;
    const int nch = DD >> 5;

    const int lm = lane & 15, lh = lane >> 4;
    const int g = lane >> 3, r = lane & 7;

    float acc[4][4][4];
    #pragma unroll
    for (int i = 0; i < 4; i++)
        #pragma unroll
        for (int j = 0; j < 4; j++)
            #pragma unroll
            for (int e = 0; e < 4; e++) acc[i][j][e] = 0.f;

    GEMM_LOAD_CHUNK(0, 0);
    GEMM_LOAD_CHUNK(1, 1);

    for (int ch = 0; ch < nch; ch++) {
        asm volatile("cp.async.wait_group 1;");
        __syncthreads();
        if (ch + 2 < nch) { GEMM_LOAD_CHUNK(ch + 2, (ch + 2) % NSTAGE); }
        else asm volatile("cp.async.commit_group;");
        const uint32_t smA  = smem_base + (ch % NSTAGE) * GBUF_B;
        const uint32_t smBh = smA + GTILE_B;
        const uint32_t smBl = smBh + GTILE_B;
        #pragma unroll
        for (int k16 = 0; k16 < 2; k16++) {
            uint32_t a[4][4];
            #pragma unroll
            for (int fm = 0; fm < 4; fm++)
                ldsm4(a[fm], smA + ((warp_m * 64 + fm * 16 + lm) * GPAD
                                    + k16 * 16 + lh * 8) * 2);
            uint32_t bh[4][2], bl[4][2];
            #pragma unroll
            for (int fp = 0; fp < 2; fp++) {
                int row = warp_n * 32 + fp * 16 + ((g >> 1) << 3) + r;
                int off = (row * GPAD + (g & 1) * 8 + k16 * 16) * 2;
                uint32_t t4[4];
                ldsm4(t4, smBh + off);
                bh[fp*2][0]=t4[0]; bh[fp*2][1]=t4[1]; bh[fp*2+1][0]=t4[2]; bh[fp*2+1][1]=t4[3];
                ldsm4(t4, smBl + off);
                bl[fp*2][0]=t4[0]; bl[fp*2][1]=t4[1]; bl[fp*2+1][0]=t4[2]; bl[fp*2+1][1]=t4[3];
            }
            #pragma unroll
            for (int fm = 0; fm < 4; fm++)
                #pragma unroll
                for (int fn = 0; fn < 4; fn++) {
                    mma16816(acc[fm][fn], a[fm], bh[fn]);
                    mma16816(acc[fm][fn], a[fm], bl[fn]);
                }
        }
    }

    const int r4 = lane >> 2, c2 = (lane & 3) * 2;
    #pragma unroll
    for (int fm = 0; fm < 4; fm++) {
        #pragma unroll
        for (int fn = 0; fn < 4; fn++) {
            int m = m0 + warp_m * 64 + fm * 16 + r4;
            int n = n0 + warp_n * 32 + fn * 8 + c2;
            *(float2*)&C[(size_t)m * DD + n] = make_float2(acc[fm][fn][0], acc[fm][fn][1]);
            *(float2*)&C[(size_t)(m + 8) * DD + n] = make_float2(acc[fm][fn][2], acc[fm][fn][3]);
        }
    }
}

// ---------------- flash attention: f16-acc correction probe ----------------
// smem: Kh(64x72) Kl(64x72) Vh(64x72) Qh(128x72) Ql(128x72) = 64512 B static
#define FPAD 72
#define OKH 0
#define OKL (64 * FPAD)
#define OVH (2 * 64 * FPAD)
#define OQH (3 * 64 * FPAD)
#define OQL (OQH + 128 * FPAD)

__global__ __launch_bounds__(256, 2) void flash_mma()
{
    __shared__ __align__(16) __half sm[OQL + 128 * FPAD];

    const int tid = threadIdx.x, wid = tid >> 5, lane = tid & 31;
    const int bh = blockIdx.y;
    const int b = bh >> 4, h = bh & (NH - 1);
    const int qtile = gridDim.x - 1 - blockIdx.x;
    const int qb = qtile * 128;
    const uint32_t sb = smem_u32(sm);

    const int lm = lane & 15, lh = lane >> 4;
    const int g = lane >> 3, r8 = lane & 7;
    const int r4 = lane >> 2, c2 = (lane & 3) * 2;

    // stage Q hi + lo into persistent smem
    {
        const __half* qhp = g_qh + ((size_t)bh * TT + qb) * HD;
        const __half* qlp = g_ql + ((size_t)bh * TT + qb) * HD;
        for (int i = tid; i < 128 * 8; i += 256) {
            int r = i >> 3, s = i & 7;
            *(uint4*)(sm + OQH + r * FPAD + s * 8) = *(const uint4*)(qhp + r * 64 + s * 8);
            *(uint4*)(sm + OQL + r * FPAD + s * 8) = *(const uint4*)(qlp + r * 64 + s * 8);
        }
    }

    float o[8][4];
    #pragma unroll
    for (int i = 0; i < 8; i++)
        #pragma unroll
        for (int e = 0; e < 4; e++) o[i][e] = 0.f;
    float mrow[2] = { -1e30f, -1e30f };
    float lsum[2] = { 0.f, 0.f };

    const __half* khb = g_kh + (size_t)bh * TT * HD;
    const __half* klb = g_kl + (size_t)bh * TT * HD;
    const __half* vhb = g_vh + (size_t)bh * TT * VD;

    const int ntiles = qtile * 2 + 2;
    const int q0 = qb + wid * 16 + r4;
    const int q1 = q0 + 8;
    const uint32_t qhi_addr = sb + (OQH + (wid * 16 + lm) * FPAD + lh * 8) * 2;
    const uint32_t qlo_addr = sb + (OQL + (wid * 16 + lm) * FPAD + lh * 8) * 2;

    for (int it = 0; it < ntiles; it++) {
        const int j0 = it * 64;
        __syncthreads();
        for (int i = tid; i < 64 * 8; i += 256) {
            int r = i >> 3, s = i & 7;
            size_t gsrc = (size_t)(j0 + r) * 64 + s * 8;
            int dsh = r * FPAD + s * 8;
            *(uint4*)(sm + OKH + dsh) = *(const uint4*)(khb + gsrc);
            *(uint4*)(sm + OKL + dsh) = *(const uint4*)(klb + gsrc);
            *(uint4*)(sm + OVH + dsh) = *(const uint4*)(vhb + gsrc);
        }
        __syncthreads();

        // ---- S: main f32 (qh*kh) + corrections f16 (qh*kl + ql*kh) ----
        float s[8][4];
        uint32_t sc[8][2];
        #pragma unroll
        for (int i = 0; i < 8; i++) {
            s[i][0] = s[i][1] = s[i][2] = s[i][3] = 0.f;
            sc[i][0] = sc[i][1] = 0u;
        }

        #pragma unroll
        for (int ks = 0; ks < 4; ks++) {
            uint32_t qhf[4], qlf[4];
            ldsm4(qhf, qhi_addr + ks * 32);
            ldsm4(qlf, qlo_addr + ks * 32);
            #pragma unroll
            for (int fp = 0; fp < 4; fp++) {
                const int krow = fp * 16 + ((g >> 1) << 3) + r8;
                uint32_t addr = sb + (krow * FPAD + (g & 1) * 8 + ks * 16) * 2;
                uint32_t bhf[4], blf[4];
                ldsm4(bhf, addr + OKH * 2);
                ldsm4(blf, addr + OKL * 2);
                mma16816 (s[fp*2],    qhf, bhf);
                mma16816h(sc[fp*2],   qhf, blf);
                mma16816h(sc[fp*2],   qlf, bhf);
                mma16816 (s[fp*2+1],  qhf, bhf + 2);
                mma16816h(sc[fp*2+1], qhf, blf + 2);
                mma16816h(sc[fp*2+1], qlf, bhf + 2);
            }
        }
        // fold corrections into f32 s
        #pragma unroll
        for (int fn = 0; fn < 8; fn++) {
            float l0, h0, l1, h1;
            unpack2(sc[fn][0], l0, h0);
            unpack2(sc[fn][1], l1, h1);
            s[fn][0] += l0; s[fn][1] += h0;
            s[fn][2] += l1; s[fn][3] += h1;
        }

        const bool need_mask = (it >= ntiles - 2);
        if (need_mask) {
            #pragma unroll
            for (int fn = 0; fn < 8; fn++) {
                #pragma unroll
                for (int e = 0; e < 4; e++) {
                    int kv = j0 + fn * 8 + c2 + (e & 1);
                    int qq = (e < 2) ? q0 : q1;
                    if (kv > qq) s[fn][e] = -1e30f;
                }
            }
        }

        float tm0 = -1e30f, tm1 = -1e30f;
        #pragma unroll
        for (int fn = 0; fn < 8; fn++) {
            tm0 = fmaxf(tm0, fmaxf(s[fn][0], s[fn][1]));
            tm1 = fmaxf(tm1, fmaxf(s[fn][2], s[fn][3]));
        }
        tm0 = fmaxf(tm0, __shfl_xor_sync(~0u, tm0, 1));
        tm0 = fmaxf(tm0, __shfl_xor_sync(~0u, tm0, 2));
        tm1 = fmaxf(tm1, __shfl_xor_sync(~0u, tm1, 1));
        tm1 = fmaxf(tm1, __shfl_xor_sync(~0u, tm1, 2));

        float mn0 = fmaxf(mrow[0], tm0), mn1 = fmaxf(mrow[1], tm1);
        float cr0 = __expf(mrow[0] - mn0), cr1 = __expf(mrow[1] - mn1);
        mrow[0] = mn0; mrow[1] = mn1;
        lsum[0] *= cr0; lsum[1] *= cr1;
        #pragma unroll
        for (int fn = 0; fn < 8; fn++) {
            o[fn][0] *= cr0; o[fn][1] *= cr0;
            o[fn][2] *= cr1; o[fn][3] *= cr1;
        }

        #pragma unroll
        for (int fn = 0; fn < 8; fn++) {
            s[fn][0] = __expf(s[fn][0] - mn0);
            s[fn][1] = __expf(s[fn][1] - mn0);
            s[fn][2] = __expf(s[fn][2] - mn1);
            s[fn][3] = __expf(s[fn][3] - mn1);
            lsum[0] += s[fn][0] + s[fn][1];
            lsum[1] += s[fn][2] + s[fn][3];
        }

        // ---- PV: main f32 (ph*vh) + correction f16 (pl*vh) ----
        uint32_t oc[8][2];
        #pragma unroll
        for (int i = 0; i < 8; i++) { oc[i][0] = 0u; oc[i][1] = 0u; }

        #pragma unroll
        for (int ks = 0; ks < 4; ks++) {
            uint32_t aph[4], apl[4];
            aph[0] = packh(s[ks*2][0], s[ks*2][1]);
            aph[1] = packh(s[ks*2][2], s[ks*2][3]);
            aph[2] = packh(s[ks*2+1][0], s[ks*2+1][1]);
            aph[3] = packh(s[ks*2+1][2], s[ks*2+1][3]);
            apl[0] = pack_lo_resid(s[ks*2][0], s[ks*2][1]);
            apl[1] = pack_lo_resid(s[ks*2][2], s[ks*2][3]);
            apl[2] = pack_lo_resid(s[ks*2+1][0], s[ks*2+1][1]);
            apl[3] = pack_lo_resid(s[ks*2+1][2], s[ks*2+1][3]);

            const int vrow = ks * 16 + (g & 1) * 8 + r8;
            #pragma unroll
            for (int np = 0; np < 4; np++) {
                const int vcol = np * 16 + lh * 8;
                uint32_t addr = sb + (OVH + vrow * FPAD + vcol) * 2;
                uint32_t bvh[4];
                ldsm4t(bvh, addr);
                mma16816 (o[np*2],     aph, bvh);
                mma16816h(oc[np*2],    apl, bvh);
                mma16816 (o[np*2+1],   aph, bvh + 2);
                mma16816h(oc[np*2+1],  apl, bvh + 2);
            }
        }
        #pragma unroll
        for (int fn = 0; fn < 8; fn++) {
            float l0, h0, l1, h1;
            unpack2(oc[fn][0], l0, h0);
            unpack2(oc[fn][1], l1, h1);
            o[fn][0] += l0; o[fn][1] += h0;
            o[fn][2] += l1; o[fn][3] += h1;
        }
    }

    lsum[0] += __shfl_xor_sync(~0u, lsum[0], 1);
    lsum[0] += __shfl_xor_sync(~0u, lsum[0], 2);
    lsum[1] += __shfl_xor_sync(~0u, lsum[1], 1);
    lsum[1] += __shfl_xor_sync(~0u, lsum[1], 2);
    const float inv0 = 1.f / lsum[0], inv1 = 1.f / lsum[1];

    __half* ob0 = g_aoh + ((size_t)(b * TT + q0)) * (NH * VD) + h * VD;
    __half* ob1 = g_aoh + ((size_t)(b * TT + q1)) * (NH * VD) + h * VD;
    #pragma unroll
    for (int fn = 0; fn < 8; fn++) {
        *(uint32_t*)(ob0 + fn * 8 + c2) = packh(o[fn][0] * inv0, o[fn][1] * inv0);
        *(uint32_t*)(ob1 + fn * 8 + c2) = packh(o[fn][2] * inv1, o[fn][3] * inv1);
    }
}

// ---------------- launch ----------------
extern "C" void kernel_launch(void* const* d_in, const int* in_sizes, int n_in,
                              void* d_out, int out_size)
{
    const float* x    = (const float*)d_in[0];
    const float* cosp = (const float*)d_in[1];
    const float* sinp = (const float*)d_in[2];
    const float* Wq   = (const float*)d_in[3];
    const float* qw   = (const float*)d_in[4];
    const float* Wkva = (const float*)d_in[5];
    const float* kvaw = (const float*)d_in[6];
    const float* Wkvb = (const float*)d_in[7];
    const float* Wo   = (const float*)d_in[8];
    float* out = (float*)d_out;

    cudaFuncSetAttribute(proj1_gemm, cudaFuncAttributeMaxDynamicSharedMemorySize, NSTAGE * GBUF_B);
    cudaFuncSetAttribute(kvb_gemm,   cudaFuncAttributeMaxDynamicSharedMemorySize, NSTAGE * GBUF_B);
    cudaFuncSetAttribute(wo_gemm,    cudaFuncAttributeMaxDynamicSharedMemorySize, NSTAGE * GBUF_B);

    cvt_all<<<(QTOT + 255) / 256, 256>>>(x, Wq, Wkva, Wkvb, Wo);

    {
        dim3 g(W1_ROWS / 128, MTOT / 128);
        proj1_gemm<<<g, 256, NSTAGE * GBUF_B>>>(cosp, sinp, qw, kvaw);
    }
    {
        dim3 g(KVB_N / 128, MTOT / 128);
        kvb_gemm<<<g, 256, NSTAGE * GBUF_B>>>();
    }
    {
        dim3 g(TT / 128, BB * NH);
        flash_mma<<<g, 256>>>();
    }
    {
        dim3 g(DD / 128, MTOT / 128);
        wo_gemm<<<g, 256, NSTAGE * GBUF_B>>>(out);
    }
}

// round 12
// speedup vs baseline: 1.0254x; 1.0254x over previous
#include <cuda_runtime.h>
#include <cuda_fp16.h>
#include <math.h>
#include <cstdint>

#define BB 2
#define TT 2048
#define DD 1024
#define NH 16
#define HD 64      // NOPE_D + ROPE_D
#define NOPE 48
#define ROPED 16
#define RR 128
#define VD 64
#define KVB_N (NH * (NOPE + VD))   // 1792
#define MTOT (BB * TT)             // 4096
#define W1_ROWS 1280               // 1024 (Wq) + 128 (latent) + 16 (rope) + 112 pad
#define QSCALE 0.18033688011112042f   // 0.125 * log2(e)

// ---------------- device scratch ----------------
__device__ __align__(256) __half g_qh[BB*NH*TT*HD], g_ql[BB*NH*TT*HD];
__device__ __align__(256) __half g_kh[BB*NH*TT*HD], g_kl[BB*NH*TT*HD];
__device__ __align__(256) __half g_vh[BB*NH*TT*VD];

__device__ __align__(256) __half g_xh [MTOT * DD];
__device__ __align__(256) __half g_W1h[W1_ROWS * DD], g_W1l[W1_ROWS * DD];
__device__ __align__(256) __half g_Wbh[KVB_N * RR],   g_Wbl[KVB_N * RR];
__device__ __align__(256) __half g_Woh[DD * DD],      g_Wol[DD * DD];
__device__ __align__(256) __half g_lth[MTOT * RR];
__device__ __align__(256) __half g_aoh[MTOT * DD];

// ======================= helpers =======================
__device__ __forceinline__ uint32_t smem_u32(const void* p) {
    uint32_t a;
    asm("{ .reg .u64 t; cvta.to.shared.u64 t, %1; cvt.u32.u64 %0, t; }" : "=r"(a) : "l"(p));
    return a;
}
__device__ __forceinline__ void mma16816(float* c, const uint32_t* a, const uint32_t* b) {
    asm volatile("mma.sync.aligned.m16n8k16.row.col.f32.f16.f16.f32 "
        "{%0,%1,%2,%3}, {%4,%5,%6,%7}, {%8,%9}, {%0,%1,%2,%3};"
        : "+f"(c[0]), "+f"(c[1]), "+f"(c[2]), "+f"(c[3])
        : "r"(a[0]), "r"(a[1]), "r"(a[2]), "r"(a[3]), "r"(b[0]), "r"(b[1]));
}
__device__ __forceinline__ void ldsm4(uint32_t* r, uint32_t addr) {
    asm volatile("ldmatrix.sync.aligned.m8n8.x4.shared.b16 {%0,%1,%2,%3}, [%4];"
        : "=r"(r[0]), "=r"(r[1]), "=r"(r[2]), "=r"(r[3]) : "r"(addr));
}
__device__ __forceinline__ void ldsm4t(uint32_t* r, uint32_t addr) {
    asm volatile("ldmatrix.sync.aligned.m8n8.x4.trans.shared.b16 {%0,%1,%2,%3}, [%4];"
        : "=r"(r[0]), "=r"(r[1]), "=r"(r[2]), "=r"(r[3]) : "r"(addr));
}
__device__ __forceinline__ uint32_t packh(float lo, float hi) {
    uint32_t d;
    asm("cvt.rn.f16x2.f32 %0, %1, %2;" : "=r"(d) : "f"(hi), "f"(lo));
    return d;
}
__device__ __forceinline__ uint32_t pack_lo_resid(float v0, float v1) {
    float h0 = __half2float(__float2half(v0));
    float h1 = __half2float(__float2half(v1));
    return packh(v0 - h0, v1 - h1);
}

// ======================= fused conversions =======================
#define QX  (MTOT * DD / 4)
#define QW1 (W1_ROWS * DD / 4)
#define QWB (KVB_N * RR / 4)
#define QWO (DD * DD / 4)
#define QTOT (QX + QW1 + QWB + QWO)

__device__ __forceinline__ void do_hl(const float* s, __half* dh, __half* dl, int e) {
    float4 v = *(const float4*)(s + e);
    __half h0 = __float2half(v.x), h1 = __float2half(v.y);
    __half h2 = __float2half(v.z), h3 = __float2half(v.w);
    ((__half2*)(dh + e))[0] = __half2(h0, h1);
    ((__half2*)(dh + e))[1] = __half2(h2, h3);
    ((__half2*)(dl + e))[0] = __half2(__float2half(v.x - __half2float(h0)),
                                      __float2half(v.y - __half2float(h1)));
    ((__half2*)(dl + e))[1] = __half2(__float2half(v.z - __half2float(h2)),
                                      __float2half(v.w - __half2float(h3)));
}

__global__ __launch_bounds__(256) void cvt_all(
    const float* __restrict__ x,    const float* __restrict__ Wq,
    const float* __restrict__ Wkva, const float* __restrict__ Wkvb,
    const float* __restrict__ Wo)
{
    int qi = blockIdx.x * blockDim.x + threadIdx.x;
    if (qi >= QTOT) return;
    if (qi < QX) {
        int e = qi * 4;
        float4 v = *(const float4*)(x + e);
        ((__half2*)(g_xh + e))[0] = __half2(__float2half(v.x), __float2half(v.y));
        ((__half2*)(g_xh + e))[1] = __half2(__float2half(v.z), __float2half(v.w));
        return;
    }
    qi -= QX;
    if (qi < QW1) {
        int e = qi * 4;
        if (e < DD * DD) { do_hl(Wq, g_W1h, g_W1l, e); }
        else if (e < (DD + 144) * DD) {
            float4 v = *(const float4*)(Wkva + (e - DD * DD));
            __half h0 = __float2half(v.x), h1 = __float2half(v.y);
            __half h2 = __float2half(v.z), h3 = __float2half(v.w);
            ((__half2*)(g_W1h + e))[0] = __half2(h0, h1);
            ((__half2*)(g_W1h + e))[1] = __half2(h2, h3);
            ((__half2*)(g_W1l + e))[0] = __half2(__float2half(v.x - __half2float(h0)),
                                                 __float2half(v.y - __half2float(h1)));
            ((__half2*)(g_W1l + e))[1] = __half2(__float2half(v.z - __half2float(h2)),
                                                 __float2half(v.w - __half2float(h3)));
        } else {
            __half2 z(__half(0.f), __half(0.f));
            ((__half2*)(g_W1h + e))[0] = z; ((__half2*)(g_W1h + e))[1] = z;
            ((__half2*)(g_W1l + e))[0] = z; ((__half2*)(g_W1l + e))[1] = z;
        }
        return;
    }
    qi -= QW1;
    if (qi < QWB) { do_hl(Wkvb, g_Wbh, g_Wbl, qi * 4); return; }
    qi -= QWB;
    do_hl(Wo, g_Woh, g_Wol, qi * 4);
}

// ======================= shared GEMM plumbing =======================
#define GPAD 40
#define GTILE_B (128 * GPAD * 2)
#define GBUF_B  (3 * GTILE_B)
#define NSTAGE 3

#define GEMM_LOAD_CHUNK(ch, buf)                                               \
    do {                                                                       \
        const int k0b = ((ch) << 5) * 2;                                       \
        _Pragma("unroll")                                                      \
        for (int it = 0; it < 6; it++) {                                       \
            int i = tid + it * 256;                                            \
            int mat = i >> 9, rem = i & 511;                                   \
            int row = rem >> 2, seg = rem & 3;                                 \
            const char* src = base[mat] + (size_t)row * ldbytes + k0b + seg * 16; \
            uint32_t dst = smem_base + (buf) * GBUF_B + mat * GTILE_B          \
                         + (row * GPAD + seg * 8) * 2;                         \
            asm volatile("cp.async.cg.shared.global [%0], [%1], 16;" :: "r"(dst), "l"(src)); \
        }                                                                      \
        asm volatile("cp.async.commit_group;");                                \
    } while (0)

// ======================= proj1 =======================
__global__ __launch_bounds__(256, 2) void proj1_gemm(
    const float* __restrict__ cosp, const float* __restrict__ sinp,
    const float* __restrict__ qw,   const float* __restrict__ kvaw)
{
    extern __shared__ __align__(16) char smem[];
    const int tid = threadIdx.x, wid = tid >> 5, lane = tid & 31;
    const int m0 = blockIdx.y * 128, n0 = blockIdx.x * 128;
    uint32_t smem_base = smem_u32(smem);

    const char* base[3] = { (const char*)(g_xh  + (size_t)m0 * DD),
                            (const char*)(g_W1h + (size_t)n0 * DD),
                            (const char*)(g_W1l + (size_t)n0 * DD) };
    const size_t ldbytes = (size_t)DD * 2;
    const int nch = DD >> 5;

    const int lm = lane & 15, lh = lane >> 4;
    const int g = lane >> 3, r8 = lane & 7;
    const int r4 = lane >> 2, c2 = (lane & 3) * 2;

    float acc[16][4];
    #pragma unroll
    for (int i = 0; i < 16; i++)
        #pragma unroll
        for (int e = 0; e < 4; e++) acc[i][e] = 0.f;

    GEMM_LOAD_CHUNK(0, 0);
    GEMM_LOAD_CHUNK(1, 1);

    for (int ch = 0; ch < nch; ch++) {
        asm volatile("cp.async.wait_group 1;");
        __syncthreads();
        if (ch + 2 < nch) { GEMM_LOAD_CHUNK(ch + 2, (ch + 2) % NSTAGE); }
        else asm volatile("cp.async.commit_group;");
        const uint32_t smA  = smem_base + (ch % NSTAGE) * GBUF_B;
        const uint32_t smBh = smA + GTILE_B;
        const uint32_t smBl = smBh + GTILE_B;
        #pragma unroll
        for (int k16 = 0; k16 < 2; k16++) {
            uint32_t a[4];
            ldsm4(a, smA + ((wid * 16 + lm) * GPAD + k16 * 16 + lh * 8) * 2);
            #pragma unroll
            for (int fp = 0; fp < 8; fp++) {
                int row = fp * 16 + ((g >> 1) << 3) + r8;
                int off = (row * GPAD + (g & 1) * 8 + k16 * 16) * 2;
                uint32_t t4[4];
                ldsm4(t4, smBh + off);
                mma16816(acc[fp*2],   a, t4);
                mma16816(acc[fp*2+1], a, t4 + 2);
                ldsm4(t4, smBl + off);
                mma16816(acc[fp*2],   a, t4);
                mma16816(acc[fp*2+1], a, t4 + 2);
            }
        }
    }

    const int bt0 = m0 + wid * 16 + r4;
    const int bt1 = bt0 + 8;
    const int t0 = bt0 & (TT - 1), t1 = bt1 & (TT - 1);
    const int b  = bt0 >> 11;

    if (blockIdx.x < 8) {
        float s00 = 0, s01 = 0, s10 = 0, s11 = 0;
        #pragma unroll
        for (int fn = 0; fn < 16; fn++) {
            float a0 = acc[fn][0]*acc[fn][0] + acc[fn][1]*acc[fn][1];
            float a1 = acc[fn][2]*acc[fn][2] + acc[fn][3]*acc[fn][3];
            if (fn < 8) { s00 += a0; s10 += a1; } else { s01 += a0; s11 += a1; }
        }
        #pragma unroll
        for (int o = 1; o <= 2; o <<= 1) {
            s00 += __shfl_xor_sync(~0u, s00, o);
            s01 += __shfl_xor_sync(~0u, s01, o);
            s10 += __shfl_xor_sync(~0u, s10, o);
            s11 += __shfl_xor_sync(~0u, s11, o);
        }
        float n00 = rsqrtf(s00 * (1.f/HD) + 1e-6f), n01 = rsqrtf(s01 * (1.f/HD) + 1e-6f);
        float n10 = rsqrtf(s10 * (1.f/HD) + 1e-6f), n11 = rsqrtf(s11 * (1.f/HD) + 1e-6f);
        #pragma unroll
        for (int fn = 0; fn < 16; fn++) {
            int d0 = (fn & 7) * 8 + c2;
            float w0 = qw[d0], w1 = qw[d0 + 1];
            float f0 = (fn < 8) ? n00 : n01, f1 = (fn < 8) ? n10 : n11;
            acc[fn][0] *= f0 * w0; acc[fn][1] *= f0 * w1;
            acc[fn][2] *= f1 * w0; acc[fn][3] *= f1 * w1;
        }
        float c00 = cosp[t0*8 + c2], c01 = cosp[t0*8 + c2 + 1];
        float sn00 = sinp[t0*8 + c2], sn01 = sinp[t0*8 + c2 + 1];
        float c10 = cosp[t1*8 + c2], c11 = cosp[t1*8 + c2 + 1];
        float sn10 = sinp[t1*8 + c2], sn11 = sinp[t1*8 + c2 + 1];
        #pragma unroll
        for (int hp = 0; hp < 2; hp++) {
            int f1i = hp * 8 + 6, f2i = f1i + 1;
            float x10 = acc[f1i][0], x11 = acc[f1i][1], x12 = acc[f1i][2], x13 = acc[f1i][3];
            float x20 = acc[f2i][0], x21 = acc[f2i][1], x22 = acc[f2i][2], x23 = acc[f2i][3];
            acc[f1i][0] = x10*c00 - x20*sn00; acc[f1i][1] = x11*c01 - x21*sn01;
            acc[f1i][2] = x12*c10 - x22*sn10; acc[f1i][3] = x13*c11 - x23*sn11;
            acc[f2i][0] = x20*c00 + x10*sn00; acc[f2i][1] = x21*c01 + x11*sn01;
            acc[f2i][2] = x22*c10 + x12*sn10; acc[f2i][3] = x23*c11 + x13*sn11;
        }
        #pragma unroll
        for (int fn = 0; fn < 16; fn++) {
            #pragma unroll
            for (int e = 0; e < 4; e++) acc[fn][e] *= QSCALE;   // 0.125 * log2(e)
        }
        #pragma unroll
        for (int fn = 0; fn < 16; fn++) {
            int hg = (n0 >> 6) + (fn >> 3);
            int d  = (fn & 7) * 8 + c2;
            size_t a0 = (((size_t)(b * NH + hg)) * TT + t0) * HD + d;
            size_t a1 = (((size_t)(b * NH + hg)) * TT + t1) * HD + d;
            *(uint32_t*)(g_qh + a0) = packh(acc[fn][0], acc[fn][1]);
            *(uint32_t*)(g_ql + a0) = pack_lo_resid(acc[fn][0], acc[fn][1]);
            *(uint32_t*)(g_qh + a1) = packh(acc[fn][2], acc[fn][3]);
            *(uint32_t*)(g_ql + a1) = pack_lo_resid(acc[fn][2], acc[fn][3]);
        }
    } else if (blockIdx.x == 8) {
        float s0 = 0, s1 = 0;
        #pragma unroll
        for (int fn = 0; fn < 16; fn++) {
            s0 += acc[fn][0]*acc[fn][0] + acc[fn][1]*acc[fn][1];
            s1 += acc[fn][2]*acc[fn][2] + acc[fn][3]*acc[fn][3];
        }
        #pragma unroll
        for (int o = 1; o <= 2; o <<= 1) {
            s0 += __shfl_xor_sync(~0u, s0, o);
            s1 += __shfl_xor_sync(~0u, s1, o);
        }
        float n0f = rsqrtf(s0 * (1.f/RR) + 1e-6f), n1f = rsqrtf(s1 * (1.f/RR) + 1e-6f);
        #pragma unroll
        for (int fn = 0; fn < 16; fn++) {
            int r = fn * 8 + c2;
            float w0 = kvaw[r], w1 = kvaw[r + 1];
            *(uint32_t*)(g_lth + (size_t)bt0 * RR + r) =
                packh(acc[fn][0] * n0f * w0, acc[fn][1] * n0f * w1);
            *(uint32_t*)(g_lth + (size_t)bt1 * RR + r) =
                packh(acc[fn][2] * n1f * w0, acc[fn][3] * n1f * w1);
        }
    } else {
        float c00 = cosp[t0*8 + c2], c01 = cosp[t0*8 + c2 + 1];
        float sn00 = sinp[t0*8 + c2], sn01 = sinp[t0*8 + c2 + 1];
        float c10 = cosp[t1*8 + c2], c11 = cosp[t1*8 + c2 + 1];
        float sn10 = sinp[t1*8 + c2], sn11 = sinp[t1*8 + c2 + 1];
        float x10 = acc[0][0], x11 = acc[0][1], x12 = acc[0][2], x13 = acc[0][3];
        float x20 = acc[1][0], x21 = acc[1][1], x22 = acc[1][2], x23 = acc[1][3];
        float o10 = x10*c00 - x20*sn00, o11 = x11*c01 - x21*sn01;
        float o12 = x12*c10 - x22*sn10, o13 = x13*c11 - x23*sn11;
        float o20 = x20*c00 + x10*sn00, o21 = x21*c01 + x11*sn01;
        float o22 = x22*c10 + x12*sn10, o23 = x23*c11 + x13*sn11;
        uint32_t h1a = packh(o10, o11), l1a = pack_lo_resid(o10, o11);
        uint32_t h1b = packh(o12, o13), l1b = pack_lo_resid(o12, o13);
        uint32_t h2a = packh(o20, o21), l2a = pack_lo_resid(o20, o21);
        uint32_t h2b = packh(o22, o23), l2b = pack_lo_resid(o22, o23);
        #pragma unroll
        for (int h = 0; h < NH; h++) {
            size_t a0 = (((size_t)(b * NH + h)) * TT + t0) * HD + 48 + c2;
            size_t a1 = (((size_t)(b * NH + h)) * TT + t1) * HD + 48 + c2;
            *(uint32_t*)(g_kh + a0)     = h1a; *(uint32_t*)(g_kl + a0)     = l1a;
            *(uint32_t*)(g_kh + a0 + 8) = h2a; *(uint32_t*)(g_kl + a0 + 8) = l2a;
            *(uint32_t*)(g_kh + a1)     = h1b; *(uint32_t*)(g_kl + a1)     = l1b;
            *(uint32_t*)(g_kh + a1 + 8) = h2b; *(uint32_t*)(g_kl + a1 + 8) = l2b;
        }
    }
}

// ======================= kvb GEMM with fused scatter =======================
__global__ __launch_bounds__(256, 2) void kvb_gemm()
{
    extern __shared__ __align__(16) char smem[];
    const int tid = threadIdx.x, wid = tid >> 5, lane = tid & 31;
    const int warp_m = wid >> 2, warp_n = wid & 3;
    const int m0 = blockIdx.y * 128, n0 = blockIdx.x * 128;
    uint32_t smem_base = smem_u32(smem);

    const char* base[3] = { (const char*)(g_lth + (size_t)m0 * RR),
                            (const char*)(g_Wbh + (size_t)n0 * RR),
                            (const char*)(g_Wbl + (size_t)n0 * RR) };
    const size_t ldbytes = (size_t)RR * 2;
    const int nch = RR >> 5;

    const int lm = lane & 15, lh = lane >> 4;
    const int g = lane >> 3, r = lane & 7;
    const int r4 = lane >> 2, c2 = (lane & 3) * 2;

    float acc[4][4][4];
    #pragma unroll
    for (int i = 0; i < 4; i++)
        #pragma unroll
        for (int j = 0; j < 4; j++)
            #pragma unroll
            for (int e = 0; e < 4; e++) acc[i][j][e] = 0.f;

    GEMM_LOAD_CHUNK(0, 0);
    GEMM_LOAD_CHUNK(1, 1);

    for (int ch = 0; ch < nch; ch++) {
        asm volatile("cp.async.wait_group 1;");
        __syncthreads();
        if (ch + 2 < nch) { GEMM_LOAD_CHUNK(ch + 2, (ch + 2) % NSTAGE); }
        else asm volatile("cp.async.commit_group;");
        const uint32_t smA  = smem_base + (ch % NSTAGE) * GBUF_B;
        const uint32_t smBh = smA + GTILE_B;
        const uint32_t smBl = smBh + GTILE_B;
        #pragma unroll
        for (int k16 = 0; k16 < 2; k16++) {
            uint32_t a[4][4];
            #pragma unroll
            for (int fm = 0; fm < 4; fm++)
                ldsm4(a[fm], smA + ((warp_m * 64 + fm * 16 + lm) * GPAD
                                    + k16 * 16 + lh * 8) * 2);
            uint32_t bh[4][2], bl[4][2];
            #pragma unroll
            for (int fp = 0; fp < 2; fp++) {
                int row = warp_n * 32 + fp * 16 + ((g >> 1) << 3) + r;
                int off = (row * GPAD + (g & 1) * 8 + k16 * 16) * 2;
                uint32_t t4[4];
                ldsm4(t4, smBh + off);
                bh[fp*2][0]=t4[0]; bh[fp*2][1]=t4[1]; bh[fp*2+1][0]=t4[2]; bh[fp*2+1][1]=t4[3];
                ldsm4(t4, smBl + off);
                bl[fp*2][0]=t4[0]; bl[fp*2][1]=t4[1]; bl[fp*2+1][0]=t4[2]; bl[fp*2+1][1]=t4[3];
            }
            #pragma unroll
            for (int fm = 0; fm < 4; fm++)
                #pragma unroll
                for (int fn = 0; fn < 4; fn++) {
                    mma16816(acc[fm][fn], a[fm], bh[fn]);
                    mma16816(acc[fm][fn], a[fm], bl[fn]);
                }
        }
    }

    #pragma unroll
    for (int fm = 0; fm < 4; fm++) {
        int bt0 = m0 + warp_m * 64 + fm * 16 + r4;
        int bt1 = bt0 + 8;
        int t0 = bt0 & (TT - 1), t1 = bt1 & (TT - 1);
        int b  = bt0 >> 11;
        #pragma unroll
        for (int fn = 0; fn < 4; fn++) {
            int n = n0 + warp_n * 32 + fn * 8 + c2;
            int h = n / 112, rr2 = n % 112;
            size_t hb = (size_t)(b * NH + h) * TT;
            if (rr2 < NOPE) {
                size_t a0 = (hb + t0) * HD + rr2, a1 = (hb + t1) * HD + rr2;
                *(uint32_t*)(g_kh + a0) = packh(acc[fm][fn][0], acc[fm][fn][1]);
                *(uint32_t*)(g_kl + a0) = pack_lo_resid(acc[fm][fn][0], acc[fm][fn][1]);
                *(uint32_t*)(g_kh + a1) = packh(acc[fm][fn][2], acc[fm][fn][3]);
                *(uint32_t*)(g_kl + a1) = pack_lo_resid(acc[fm][fn][2], acc[fm][fn][3]);
            } else {
                int d = rr2 - NOPE;
                size_t a0 = (hb + t0) * VD + d, a1 = (hb + t1) * VD + d;
                *(uint32_t*)(g_vh + a0) = packh(acc[fm][fn][0], acc[fm][fn][1]);
                *(uint32_t*)(g_vh + a1) = packh(acc[fm][fn][2], acc[fm][fn][3]);
            }
        }
    }
}

// ======================= Wo GEMM =======================
__global__ __launch_bounds__(256, 2) void wo_gemm(float* __restrict__ C)
{
    extern __shared__ __align__(16) char smem[];
    const int tid = threadIdx.x, wid = tid >> 5, lane = tid & 31;
    const int warp_m = wid >> 2, warp_n = wid & 3;
    const int m0 = blockIdx.y * 128, n0 = blockIdx.x * 128;
    uint32_t smem_base = smem_u32(smem);

    const char* base[3] = { (const char*)(g_aoh + (size_t)m0 * DD),
                            (const char*)(g_Woh + (size_t)n0 * DD),
                            (const char*)(g_Wol + (size_t)n0 * DD) };
    const size_t ldbytes = (size_t)DD * 2;
    const int nch = DD >> 5;

    const int lm = lane & 15, lh = lane >> 4;
    const int g = lane >> 3, r = lane & 7;

    float acc[4][4][4];
    #pragma unroll
    for (int i = 0; i < 4; i++)
        #pragma unroll
        for (int j = 0; j < 4; j++)
            #pragma unroll
            for (int e = 0; e < 4; e++) acc[i][j][e] = 0.f;

    GEMM_LOAD_CHUNK(0, 0);
    GEMM_LOAD_CHUNK(1, 1);

    for (int ch = 0; ch < nch; ch++) {
        asm volatile("cp.async.wait_group 1;");
        __syncthreads();
        if (ch + 2 < nch) { GEMM_LOAD_CHUNK(ch + 2, (ch + 2) % NSTAGE); }
        else asm volatile("cp.async.commit_group;");
        const uint32_t smA  = smem_base + (ch % NSTAGE) * GBUF_B;
        const uint32_t smBh = smA + GTILE_B;
        const uint32_t smBl = smBh + GTILE_B;
        #pragma unroll
        for (int k16 = 0; k16 < 2; k16++) {
            uint32_t a[4][4];
            #pragma unroll
            for (int fm = 0; fm < 4; fm++)
                ldsm4(a[fm], smA + ((warp_m * 64 + fm * 16 + lm) * GPAD
                                    + k16 * 16 + lh * 8) * 2);
            uint32_t bh[4][2], bl[4][2];
            #pragma unroll
            for (int fp = 0; fp < 2; fp++) {
                int row = warp_n * 32 + fp * 16 + ((g >> 1) << 3) + r;
                int off = (row * GPAD + (g & 1) * 8 + k16 * 16) * 2;
                uint32_t t4[4];
                ldsm4(t4, smBh + off);
                bh[fp*2][0]=t4[0]; bh[fp*2][1]=t4[1]; bh[fp*2+1][0]=t4[2]; bh[fp*2+1][1]=t4[3];
                ldsm4(t4, smBl + off);
                bl[fp*2][0]=t4[0]; bl[fp*2][1]=t4[1]; bl[fp*2+1][0]=t4[2]; bl[fp*2+1][1]=t4[3];
            }
            #pragma unroll
            for (int fm = 0; fm < 4; fm++)
                #pragma unroll
                for (int fn = 0; fn < 4; fn++) {
                    mma16816(acc[fm][fn], a[fm], bh[fn]);
                    mma16816(acc[fm][fn], a[fm], bl[fn]);
                }
        }
    }

    const int r4 = lane >> 2, c2 = (lane & 3) * 2;
    #pragma unroll
    for (int fm = 0; fm < 4; fm++) {
        #pragma unroll
        for (int fn = 0; fn < 4; fn++) {
            int m = m0 + warp_m * 64 + fm * 16 + r4;
            int n = n0 + warp_n * 32 + fn * 8 + c2;
            *(float2*)&C[(size_t)m * DD + n] = make_float2(acc[fm][fn][0], acc[fm][fn][1]);
            *(float2*)&C[(size_t)(m + 8) * DD + n] = make_float2(acc[fm][fn][2], acc[fm][fn][3]);
        }
    }
}

// ---------------- flash attention: causal-skip tail + exp2 ----------------
#define FPAD 72
#define FQLO (3 * 64 * FPAD)    // half offset of persistent Q-lo region

__global__ __launch_bounds__(256, 2) void flash_mma()
{
    __shared__ __align__(16) __half sm[FQLO + 128 * FPAD];   // 46080 B

    const int tid = threadIdx.x, wid = tid >> 5, lane = tid & 31;
    const int bh = blockIdx.y;
    const int b = bh >> 4, h = bh & (NH - 1);
    const int qtile = gridDim.x - 1 - blockIdx.x;
    const int qb = qtile * 128;
    const uint32_t sb = smem_u32(sm);

    const int lm = lane & 15, lh = lane >> 4;
    const int g = lane >> 3, r8 = lane & 7;
    const int r4 = lane >> 2, c2 = (lane & 3) * 2;

    // stage Q hi (scratch region) + Q lo (persistent region)
    {
        const __half* qhp = g_qh + ((size_t)bh * TT + qb) * HD;
        const __half* qlp = g_ql + ((size_t)bh * TT + qb) * HD;
        for (int i = tid; i < 128 * 8; i += 256) {
            int r = i >> 3, s = i & 7;
            *(uint4*)(sm + r * FPAD + s * 8) = *(const uint4*)(qhp + r * 64 + s * 8);
            *(uint4*)(sm + FQLO + r * FPAD + s * 8) = *(const uint4*)(qlp + r * 64 + s * 8);
        }
    }
    __syncthreads();

    uint32_t qh[4][4];
    #pragma unroll
    for (int ks = 0; ks < 4; ks++)
        ldsm4(qh[ks], sb + ((wid * 16 + lm) * FPAD + ks * 16 + lh * 8) * 2);

    float o[8][4];
    #pragma unroll
    for (int i = 0; i < 8; i++)
        #pragma unroll
        for (int e = 0; e < 4; e++) o[i][e] = 0.f;
    float mrow[2] = { -1e30f, -1e30f };
    float lsum[2] = { 0.f, 0.f };

    const __half* khb = g_kh + (size_t)bh * TT * HD;
    const __half* klb = g_kl + (size_t)bh * TT * HD;
    const __half* vhb = g_vh + (size_t)bh * TT * VD;

    const int ntiles = qtile * 2 + 2;
    const int q0 = qb + wid * 16 + r4;
    const int q1 = q0 + 8;

    const uint32_t oKl = 64 * FPAD * 2;
    const uint32_t oVh = 2 * 64 * FPAD * 2;
    const uint32_t qlo_addr = sb + (FQLO + (wid * 16 + lm) * FPAD + lh * 8) * 2;

    for (int it = 0; it < ntiles; it++) {
        const int j0 = it * 64;
        const bool tail = (it >= ntiles - 2);
        // live n-frag limit for this warp in this tile (8 = all live)
        int fn_lim = 8;
        if (tail) {
            int loc = j0 - qb;                       // 0 or 64
            fn_lim = (wid * 16 + 16 - loc + 7) >> 3;
            if (fn_lim < 0) fn_lim = 0;
            if (fn_lim > 8) fn_lim = 8;
        }
        const int fp_lim = (fn_lim + 1) >> 1;

        __syncthreads();
        for (int i = tid; i < 64 * 8; i += 256) {
            int r = i >> 3, s = i & 7;
            size_t gsrc = (size_t)(j0 + r) * 64 + s * 8;
            int dsh = r * FPAD + s * 8;
            *(uint4*)(sm + dsh) = *(const uint4*)(khb + gsrc);
            *(uint4*)(sm + 64 * FPAD + dsh) = *(const uint4*)(klb + gsrc);
            *(uint4*)(sm + 2 * 64 * FPAD + dsh) = *(const uint4*)(vhb + gsrc);
        }
        __syncthreads();

        float s[8][4];
        #pragma unroll
        for (int i = 0; i < 8; i++)
            #pragma unroll
            for (int e = 0; e < 4; e++) s[i][e] = 0.f;

        if (fp_lim > 0) {
            #pragma unroll
            for (int ks = 0; ks < 4; ks++) {
                uint32_t qlf[4];
                ldsm4(qlf, qlo_addr + ks * 32);
                #pragma unroll
                for (int fp = 0; fp < 4; fp++) {
                    if (fp >= fp_lim) break;        // warp-uniform
                    const int krow = fp * 16 + ((g >> 1) << 3) + r8;
                    uint32_t addr = sb + (krow * FPAD + (g & 1) * 8 + ks * 16) * 2;
                    uint32_t bhf[4], blf[4];
                    ldsm4(bhf, addr);
                    ldsm4(blf, addr + oKl);
                    mma16816(s[fp*2],   qh[ks], bhf);
                    mma16816(s[fp*2],   qh[ks], blf);
                    mma16816(s[fp*2],   qlf,    bhf);
                    mma16816(s[fp*2+1], qh[ks], bhf + 2);
                    mma16816(s[fp*2+1], qh[ks], blf + 2);
                    mma16816(s[fp*2+1], qlf,    bhf + 2);
                }
            }
        }

        if (tail) {
            #pragma unroll
            for (int fn = 0; fn < 8; fn++) {
                #pragma unroll
                for (int e = 0; e < 4; e++) {
                    int kv = j0 + fn * 8 + c2 + (e & 1);
                    int qq = (e < 2) ? q0 : q1;
                    if (fn >= fn_lim || kv > qq) s[fn][e] = -1e30f;
                }
            }
        }

        float tm0 = -1e30f, tm1 = -1e30f;
        #pragma unroll
        for (int fn = 0; fn < 8; fn++) {
            tm0 = fmaxf(tm0, fmaxf(s[fn][0], s[fn][1]));
            tm1 = fmaxf(tm1, fmaxf(s[fn][2], s[fn][3]));
        }
        tm0 = fmaxf(tm0, __shfl_xor_sync(~0u, tm0, 1));
        tm0 = fmaxf(tm0, __shfl_xor_sync(~0u, tm0, 2));
        tm1 = fmaxf(tm1, __shfl_xor_sync(~0u, tm1, 1));
        tm1 = fmaxf(tm1, __shfl_xor_sync(~0u, tm1, 2));

        float mn0 = fmaxf(mrow[0], tm0), mn1 = fmaxf(mrow[1], tm1);
        float cr0 = exp2f(mrow[0] - mn0), cr1 = exp2f(mrow[1] - mn1);
        mrow[0] = mn0; mrow[1] = mn1;
        lsum[0] *= cr0; lsum[1] *= cr1;
        #pragma unroll
        for (int fn = 0; fn < 8; fn++) {
            o[fn][0] *= cr0; o[fn][1] *= cr0;
            o[fn][2] *= cr1; o[fn][3] *= cr1;
        }

        #pragma unroll
        for (int fn = 0; fn < 8; fn++) {
            if (fn >= fn_lim) {                     // dead frag: p = 0 exactly
                s[fn][0] = s[fn][1] = s[fn][2] = s[fn][3] = 0.f;
                continue;
            }
            s[fn][0] = exp2f(s[fn][0] - mn0);
            s[fn][1] = exp2f(s[fn][1] - mn0);
            s[fn][2] = exp2f(s[fn][2] - mn1);
            s[fn][3] = exp2f(s[fn][3] - mn1);
            lsum[0] += s[fn][0] + s[fn][1];
            lsum[1] += s[fn][2] + s[fn][3];
        }

        #pragma unroll
        for (int ks = 0; ks < 4; ks++) {
            if (ks >= fp_lim) break;                // P columns ks*16.. dead
            uint32_t aph[4], apl[4];
            aph[0] = packh(s[ks*2][0], s[ks*2][1]);
            aph[1] = packh(s[ks*2][2], s[ks*2][3]);
            aph[2] = packh(s[ks*2+1][0], s[ks*2+1][1]);
            aph[3] = packh(s[ks*2+1][2], s[ks*2+1][3]);
            apl[0] = pack_lo_resid(s[ks*2][0], s[ks*2][1]);
            apl[1] = pack_lo_resid(s[ks*2][2], s[ks*2][3]);
            apl[2] = pack_lo_resid(s[ks*2+1][0], s[ks*2+1][1]);
            apl[3] = pack_lo_resid(s[ks*2+1][2], s[ks*2+1][3]);

            const int vrow = ks * 16 + (g & 1) * 8 + r8;
            #pragma unroll
            for (int np = 0; np < 4; np++) {
                const int vcol = np * 16 + lh * 8;
                uint32_t addr = sb + oVh + (vrow * FPAD + vcol) * 2;
                uint32_t bvh[4];
                ldsm4t(bvh, addr);
                mma16816(o[np*2],   aph, bvh);
                mma16816(o[np*2],   apl, bvh);
                mma16816(o[np*2+1], aph, bvh + 2);
                mma16816(o[np*2+1], apl, bvh + 2);
            }
        }
    }

    lsum[0] += __shfl_xor_sync(~0u, lsum[0], 1);
    lsum[0] += __shfl_xor_sync(~0u, lsum[0], 2);
    lsum[1] += __shfl_xor_sync(~0u, lsum[1], 1);
    lsum[1] += __shfl_xor_sync(~0u, lsum[1], 2);
    const float inv0 = 1.f / lsum[0], inv1 = 1.f / lsum[1];

    __half* ob0 = g_aoh + ((size_t)(b * TT + q0)) * (NH * VD) + h * VD;
    __half* ob1 = g_aoh + ((size_t)(b * TT + q1)) * (NH * VD) + h * VD;
    #pragma unroll
    for (int fn = 0; fn < 8; fn++) {
        *(uint32_t*)(ob0 + fn * 8 + c2) = packh(o[fn][0] * inv0, o[fn][1] * inv0);
        *(uint32_t*)(ob1 + fn * 8 + c2) = packh(o[fn][2] * inv1, o[fn][3] * inv1);
    }
}

// ---------------- launch ----------------
extern "C" void kernel_launch(void* const* d_in, const int* in_sizes, int n_in,
                              void* d_out, int out_size)
{
    const float* x    = (const float*)d_in[0];
    const float* cosp = (const float*)d_in[1];
    const float* sinp = (const float*)d_in[2];
    const float* Wq   = (const float*)d_in[3];
    const float* qw   = (const float*)d_in[4];
    const float* Wkva = (const float*)d_in[5];
    const float* kvaw = (const float*)d_in[6];
    const float* Wkvb = (const float*)d_in[7];
    const float* Wo   = (const float*)d_in[8];
    float* out = (float*)d_out;

    cudaFuncSetAttribute(proj1_gemm, cudaFuncAttributeMaxDynamicSharedMemorySize, NSTAGE * GBUF_B);
    cudaFuncSetAttribute(kvb_gemm,   cudaFuncAttributeMaxDynamicSharedMemorySize, NSTAGE * GBUF_B);
    cudaFuncSetAttribute(wo_gemm,    cudaFuncAttributeMaxDynamicSharedMemorySize, NSTAGE * GBUF_B);

    cvt_all<<<(QTOT + 255) / 256, 256>>>(x, Wq, Wkva, Wkvb, Wo);

    {
        dim3 g(W1_ROWS / 128, MTOT / 128);
        proj1_gemm<<<g, 256, NSTAGE * GBUF_B>>>(cosp, sinp, qw, kvaw);
    }
    {
        dim3 g(KVB_N / 128, MTOT / 128);
        kvb_gemm<<<g, 256, NSTAGE * GBUF_B>>>();
    }
    {
        dim3 g(TT / 128, BB * NH);
        flash_mma<<<g, 256>>>();
    }
    {
        dim3 g(DD / 128, MTOT / 128);
        wo_gemm<<<g, 256, NSTAGE * GBUF_B>>>(out);
    }
}

// round 13
// speedup vs baseline: 1.0809x; 1.0541x over previous
#include <cuda_runtime.h>
#include <cuda_fp16.h>
#include <math.h>
#include <cstdint>

#define BB 2
#define TT 2048
#define DD 1024
#define NH 16
#define HD 64      // NOPE_D + ROPE_D
#define NOPE 48
#define ROPED 16
#define RR 128
#define VD 64
#define KVB_N (NH * (NOPE + VD))   // 1792
#define MTOT (BB * TT)             // 4096
#define W1_ROWS 1280               // 1024 (Wq) + 128 (latent) + 16 (rope) + 112 pad
#define QSCALE 0.18033688011112042f   // 0.125 * log2(e)

// ---------------- device scratch ----------------
__device__ __align__(256) __half g_qh[BB*NH*TT*HD], g_ql[BB*NH*TT*HD];
__device__ __align__(256) __half g_kh[BB*NH*TT*HD], g_kl[BB*NH*TT*HD];
__device__ __align__(256) __half g_vh[BB*NH*TT*VD];

__device__ __align__(256) __half g_xh [MTOT * DD];
__device__ __align__(256) __half g_W1h[W1_ROWS * DD], g_W1l[W1_ROWS * DD];
__device__ __align__(256) __half g_Wbh[KVB_N * RR],   g_Wbl[KVB_N * RR];
__device__ __align__(256) __half g_Woh[DD * DD],      g_Wol[DD * DD];
__device__ __align__(256) __half g_lth[MTOT * RR];
__device__ __align__(256) __half g_aoh[MTOT * DD];

// ======================= helpers =======================
__device__ __forceinline__ uint32_t smem_u32(const void* p) {
    uint32_t a;
    asm("{ .reg .u64 t; cvta.to.shared.u64 t, %1; cvt.u32.u64 %0, t; }" : "=r"(a) : "l"(p));
    return a;
}
__device__ __forceinline__ void mma16816(float* c, const uint32_t* a, const uint32_t* b) {
    asm volatile("mma.sync.aligned.m16n8k16.row.col.f32.f16.f16.f32 "
        "{%0,%1,%2,%3}, {%4,%5,%6,%7}, {%8,%9}, {%0,%1,%2,%3};"
        : "+f"(c[0]), "+f"(c[1]), "+f"(c[2]), "+f"(c[3])
        : "r"(a[0]), "r"(a[1]), "r"(a[2]), "r"(a[3]), "r"(b[0]), "r"(b[1]));
}
__device__ __forceinline__ void ldsm4(uint32_t* r, uint32_t addr) {
    asm volatile("ldmatrix.sync.aligned.m8n8.x4.shared.b16 {%0,%1,%2,%3}, [%4];"
        : "=r"(r[0]), "=r"(r[1]), "=r"(r[2]), "=r"(r[3]) : "r"(addr));
}
__device__ __forceinline__ void ldsm4t(uint32_t* r, uint32_t addr) {
    asm volatile("ldmatrix.sync.aligned.m8n8.x4.trans.shared.b16 {%0,%1,%2,%3}, [%4];"
        : "=r"(r[0]), "=r"(r[1]), "=r"(r[2]), "=r"(r[3]) : "r"(addr));
}
__device__ __forceinline__ uint32_t packh(float lo, float hi) {
    uint32_t d;
    asm("cvt.rn.f16x2.f32 %0, %1, %2;" : "=r"(d) : "f"(hi), "f"(lo));
    return d;
}
__device__ __forceinline__ uint32_t pack_lo_resid(float v0, float v1) {
    float h0 = __half2float(__float2half(v0));
    float h1 = __half2float(__float2half(v1));
    return packh(v0 - h0, v1 - h1);
}

// ======================= fused conversions =======================
#define QX  (MTOT * DD / 4)
#define QW1 (W1_ROWS * DD / 4)
#define QWB (KVB_N * RR / 4)
#define QWO (DD * DD / 4)
#define QTOT (QX + QW1 + QWB + QWO)

__device__ __forceinline__ void do_hl(const float* s, __half* dh, __half* dl, int e) {
    float4 v = *(const float4*)(s + e);
    __half h0 = __float2half(v.x), h1 = __float2half(v.y);
    __half h2 = __float2half(v.z), h3 = __float2half(v.w);
    ((__half2*)(dh + e))[0] = __half2(h0, h1);
    ((__half2*)(dh + e))[1] = __half2(h2, h3);
    ((__half2*)(dl + e))[0] = __half2(__float2half(v.x - __half2float(h0)),
                                      __float2half(v.y - __half2float(h1)));
    ((__half2*)(dl + e))[1] = __half2(__float2half(v.z - __half2float(h2)),
                                      __float2half(v.w - __half2float(h3)));
}

__global__ __launch_bounds__(256) void cvt_all(
    const float* __restrict__ x,    const float* __restrict__ Wq,
    const float* __restrict__ Wkva, const float* __restrict__ Wkvb,
    const float* __restrict__ Wo)
{
    int qi = blockIdx.x * blockDim.x + threadIdx.x;
    if (qi >= QTOT) return;
    if (qi < QX) {
        int e = qi * 4;
        float4 v = *(const float4*)(x + e);
        ((__half2*)(g_xh + e))[0] = __half2(__float2half(v.x), __float2half(v.y));
        ((__half2*)(g_xh + e))[1] = __half2(__float2half(v.z), __float2half(v.w));
        return;
    }
    qi -= QX;
    if (qi < QW1) {
        int e = qi * 4;
        if (e < DD * DD) { do_hl(Wq, g_W1h, g_W1l, e); }
        else if (e < (DD + 144) * DD) {
            float4 v = *(const float4*)(Wkva + (e - DD * DD));
            __half h0 = __float2half(v.x), h1 = __float2half(v.y);
            __half h2 = __float2half(v.z), h3 = __float2half(v.w);
            ((__half2*)(g_W1h + e))[0] = __half2(h0, h1);
            ((__half2*)(g_W1h + e))[1] = __half2(h2, h3);
            ((__half2*)(g_W1l + e))[0] = __half2(__float2half(v.x - __half2float(h0)),
                                                 __float2half(v.y - __half2float(h1)));
            ((__half2*)(g_W1l + e))[1] = __half2(__float2half(v.z - __half2float(h2)),
                                                 __float2half(v.w - __half2float(h3)));
        } else {
            __half2 z(__half(0.f), __half(0.f));
            ((__half2*)(g_W1h + e))[0] = z; ((__half2*)(g_W1h + e))[1] = z;
            ((__half2*)(g_W1l + e))[0] = z; ((__half2*)(g_W1l + e))[1] = z;
        }
        return;
    }
    qi -= QW1;
    if (qi < QWB) { do_hl(Wkvb, g_Wbh, g_Wbl, qi * 4); return; }
    qi -= QWB;
    do_hl(Wo, g_Woh, g_Wol, qi * 4);
}

// ======================= shared GEMM plumbing =======================
#define GPAD 40
#define GTILE_B (128 * GPAD * 2)
#define GBUF_B  (3 * GTILE_B)
#define NSTAGE 3

#define GEMM_LOAD_CHUNK(ch, buf)                                               \
    do {                                                                       \
        const int k0b = ((ch) << 5) * 2;                                       \
        _Pragma("unroll")                                                      \
        for (int it = 0; it < 6; it++) {                                       \
            int i = tid + it * 256;                                            \
            int mat = i >> 9, rem = i & 511;                                   \
            int row = rem >> 2, seg = rem & 3;                                 \
            const char* src = base[mat] + (size_t)row * ldbytes + k0b + seg * 16; \
            uint32_t dst = smem_base + (buf) * GBUF_B + mat * GTILE_B          \
                         + (row * GPAD + seg * 8) * 2;                         \
            asm volatile("cp.async.cg.shared.global [%0], [%1], 16;" :: "r"(dst), "l"(src)); \
        }                                                                      \
        asm volatile("cp.async.commit_group;");                                \
    } while (0)

// ======================= proj1 =======================
__global__ __launch_bounds__(256, 2) void proj1_gemm(
    const float* __restrict__ cosp, const float* __restrict__ sinp,
    const float* __restrict__ qw,   const float* __restrict__ kvaw)
{
    extern __shared__ __align__(16) char smem[];
    const int tid = threadIdx.x, wid = tid >> 5, lane = tid & 31;
    const int m0 = blockIdx.y * 128, n0 = blockIdx.x * 128;
    uint32_t smem_base = smem_u32(smem);

    const char* base[3] = { (const char*)(g_xh  + (size_t)m0 * DD),
                            (const char*)(g_W1h + (size_t)n0 * DD),
                            (const char*)(g_W1l + (size_t)n0 * DD) };
    const size_t ldbytes = (size_t)DD * 2;
    const int nch = DD >> 5;

    const int lm = lane & 15, lh = lane >> 4;
    const int g = lane >> 3, r8 = lane & 7;
    const int r4 = lane >> 2, c2 = (lane & 3) * 2;

    float acc[16][4];
    #pragma unroll
    for (int i = 0; i < 16; i++)
        #pragma unroll
        for (int e = 0; e < 4; e++) acc[i][e] = 0.f;

    GEMM_LOAD_CHUNK(0, 0);
    GEMM_LOAD_CHUNK(1, 1);

    for (int ch = 0; ch < nch; ch++) {
        asm volatile("cp.async.wait_group 1;");
        __syncthreads();
        if (ch + 2 < nch) { GEMM_LOAD_CHUNK(ch + 2, (ch + 2) % NSTAGE); }
        else asm volatile("cp.async.commit_group;");
        const uint32_t smA  = smem_base + (ch % NSTAGE) * GBUF_B;
        const uint32_t smBh = smA + GTILE_B;
        const uint32_t smBl = smBh + GTILE_B;
        #pragma unroll
        for (int k16 = 0; k16 < 2; k16++) {
            uint32_t a[4];
            ldsm4(a, smA + ((wid * 16 + lm) * GPAD + k16 * 16 + lh * 8) * 2);
            #pragma unroll
            for (int fp = 0; fp < 8; fp++) {
                int row = fp * 16 + ((g >> 1) << 3) + r8;
                int off = (row * GPAD + (g & 1) * 8 + k16 * 16) * 2;
                uint32_t t4[4];
                ldsm4(t4, smBh + off);
                mma16816(acc[fp*2],   a, t4);
                mma16816(acc[fp*2+1], a, t4 + 2);
                ldsm4(t4, smBl + off);
                mma16816(acc[fp*2],   a, t4);
                mma16816(acc[fp*2+1], a, t4 + 2);
            }
        }
    }

    const int bt0 = m0 + wid * 16 + r4;
    const int bt1 = bt0 + 8;
    const int t0 = bt0 & (TT - 1), t1 = bt1 & (TT - 1);
    const int b  = bt0 >> 11;

    if (blockIdx.x < 8) {
        float s00 = 0, s01 = 0, s10 = 0, s11 = 0;
        #pragma unroll
        for (int fn = 0; fn < 16; fn++) {
            float a0 = acc[fn][0]*acc[fn][0] + acc[fn][1]*acc[fn][1];
            float a1 = acc[fn][2]*acc[fn][2] + acc[fn][3]*acc[fn][3];
            if (fn < 8) { s00 += a0; s10 += a1; } else { s01 += a0; s11 += a1; }
        }
        #pragma unroll
        for (int o = 1; o <= 2; o <<= 1) {
            s00 += __shfl_xor_sync(~0u, s00, o);
            s01 += __shfl_xor_sync(~0u, s01, o);
            s10 += __shfl_xor_sync(~0u, s10, o);
            s11 += __shfl_xor_sync(~0u, s11, o);
        }
        float n00 = rsqrtf(s00 * (1.f/HD) + 1e-6f), n01 = rsqrtf(s01 * (1.f/HD) + 1e-6f);
        float n10 = rsqrtf(s10 * (1.f/HD) + 1e-6f), n11 = rsqrtf(s11 * (1.f/HD) + 1e-6f);
        #pragma unroll
        for (int fn = 0; fn < 16; fn++) {
            int d0 = (fn & 7) * 8 + c2;
            float w0 = qw[d0], w1 = qw[d0 + 1];
            float f0 = (fn < 8) ? n00 : n01, f1 = (fn < 8) ? n10 : n11;
            acc[fn][0] *= f0 * w0; acc[fn][1] *= f0 * w1;
            acc[fn][2] *= f1 * w0; acc[fn][3] *= f1 * w1;
        }
        float c00 = cosp[t0*8 + c2], c01 = cosp[t0*8 + c2 + 1];
        float sn00 = sinp[t0*8 + c2], sn01 = sinp[t0*8 + c2 + 1];
        float c10 = cosp[t1*8 + c2], c11 = cosp[t1*8 + c2 + 1];
        float sn10 = sinp[t1*8 + c2], sn11 = sinp[t1*8 + c2 + 1];
        #pragma unroll
        for (int hp = 0; hp < 2; hp++) {
            int f1i = hp * 8 + 6, f2i = f1i + 1;
            float x10 = acc[f1i][0], x11 = acc[f1i][1], x12 = acc[f1i][2], x13 = acc[f1i][3];
            float x20 = acc[f2i][0], x21 = acc[f2i][1], x22 = acc[f2i][2], x23 = acc[f2i][3];
            acc[f1i][0] = x10*c00 - x20*sn00; acc[f1i][1] = x11*c01 - x21*sn01;
            acc[f1i][2] = x12*c10 - x22*sn10; acc[f1i][3] = x13*c11 - x23*sn11;
            acc[f2i][0] = x20*c00 + x10*sn00; acc[f2i][1] = x21*c01 + x11*sn01;
            acc[f2i][2] = x22*c10 + x12*sn10; acc[f2i][3] = x23*c11 + x13*sn11;
        }
        #pragma unroll
        for (int fn = 0; fn < 16; fn++) {
            #pragma unroll
            for (int e = 0; e < 4; e++) acc[fn][e] *= QSCALE;   // 0.125 * log2(e)
        }
        #pragma unroll
        for (int fn = 0; fn < 16; fn++) {
            int hg = (n0 >> 6) + (fn >> 3);
            int d  = (fn & 7) * 8 + c2;
            size_t a0 = (((size_t)(b * NH + hg)) * TT + t0) * HD + d;
            size_t a1 = (((size_t)(b * NH + hg)) * TT + t1) * HD + d;
            *(uint32_t*)(g_qh + a0) = packh(acc[fn][0], acc[fn][1]);
            *(uint32_t*)(g_ql + a0) = pack_lo_resid(acc[fn][0], acc[fn][1]);
            *(uint32_t*)(g_qh + a1) = packh(acc[fn][2], acc[fn][3]);
            *(uint32_t*)(g_ql + a1) = pack_lo_resid(acc[fn][2], acc[fn][3]);
        }
    } else if (blockIdx.x == 8) {
        float s0 = 0, s1 = 0;
        #pragma unroll
        for (int fn = 0; fn < 16; fn++) {
            s0 += acc[fn][0]*acc[fn][0] + acc[fn][1]*acc[fn][1];
            s1 += acc[fn][2]*acc[fn][2] + acc[fn][3]*acc[fn][3];
        }
        #pragma unroll
        for (int o = 1; o <= 2; o <<= 1) {
            s0 += __shfl_xor_sync(~0u, s0, o);
            s1 += __shfl_xor_sync(~0u, s1, o);
        }
        float n0f = rsqrtf(s0 * (1.f/RR) + 1e-6f), n1f = rsqrtf(s1 * (1.f/RR) + 1e-6f);
        #pragma unroll
        for (int fn = 0; fn < 16; fn++) {
            int r = fn * 8 + c2;
            float w0 = kvaw[r], w1 = kvaw[r + 1];
            *(uint32_t*)(g_lth + (size_t)bt0 * RR + r) =
                packh(acc[fn][0] * n0f * w0, acc[fn][1] * n0f * w1);
            *(uint32_t*)(g_lth + (size_t)bt1 * RR + r) =
                packh(acc[fn][2] * n1f * w0, acc[fn][3] * n1f * w1);
        }
    } else {
        float c00 = cosp[t0*8 + c2], c01 = cosp[t0*8 + c2 + 1];
        float sn00 = sinp[t0*8 + c2], sn01 = sinp[t0*8 + c2 + 1];
        float c10 = cosp[t1*8 + c2], c11 = cosp[t1*8 + c2 + 1];
        float sn10 = sinp[t1*8 + c2], sn11 = sinp[t1*8 + c2 + 1];
        float x10 = acc[0][0], x11 = acc[0][1], x12 = acc[0][2], x13 = acc[0][3];
        float x20 = acc[1][0], x21 = acc[1][1], x22 = acc[1][2], x23 = acc[1][3];
        float o10 = x10*c00 - x20*sn00, o11 = x11*c01 - x21*sn01;
        float o12 = x12*c10 - x22*sn10, o13 = x13*c11 - x23*sn11;
        float o20 = x20*c00 + x10*sn00, o21 = x21*c01 + x11*sn01;
        float o22 = x22*c10 + x12*sn10, o23 = x23*c11 + x13*sn11;
        uint32_t h1a = packh(o10, o11), l1a = pack_lo_resid(o10, o11);
        uint32_t h1b = packh(o12, o13), l1b = pack_lo_resid(o12, o13);
        uint32_t h2a = packh(o20, o21), l2a = pack_lo_resid(o20, o21);
        uint32_t h2b = packh(o22, o23), l2b = pack_lo_resid(o22, o23);
        #pragma unroll
        for (int h = 0; h < NH; h++) {
            size_t a0 = (((size_t)(b * NH + h)) * TT + t0) * HD + 48 + c2;
            size_t a1 = (((size_t)(b * NH + h)) * TT + t1) * HD + 48 + c2;
            *(uint32_t*)(g_kh + a0)     = h1a; *(uint32_t*)(g_kl + a0)     = l1a;
            *(uint32_t*)(g_kh + a0 + 8) = h2a; *(uint32_t*)(g_kl + a0 + 8) = l2a;
            *(uint32_t*)(g_kh + a1)     = h1b; *(uint32_t*)(g_kl + a1)     = l1b;
            *(uint32_t*)(g_kh + a1 + 8) = h2b; *(uint32_t*)(g_kl + a1 + 8) = l2b;
        }
    }
}

// ======================= kvb GEMM with fused scatter =======================
__global__ __launch_bounds__(256, 2) void kvb_gemm()
{
    extern __shared__ __align__(16) char smem[];
    const int tid = threadIdx.x, wid = tid >> 5, lane = tid & 31;
    const int warp_m = wid >> 2, warp_n = wid & 3;
    const int m0 = blockIdx.y * 128, n0 = blockIdx.x * 128;
    uint32_t smem_base = smem_u32(smem);

    const char* base[3] = { (const char*)(g_lth + (size_t)m0 * RR),
                            (const char*)(g_Wbh + (size_t)n0 * RR),
                            (const char*)(g_Wbl + (size_t)n0 * RR) };
    const size_t ldbytes = (size_t)RR * 2;
    const int nch = RR >> 5;

    const int lm = lane & 15, lh = lane >> 4;
    const int g = lane >> 3, r = lane & 7;
    const int r4 = lane >> 2, c2 = (lane & 3) * 2;

    float acc[4][4][4];
    #pragma unroll
    for (int i = 0; i < 4; i++)
        #pragma unroll
        for (int j = 0; j < 4; j++)
            #pragma unroll
            for (int e = 0; e < 4; e++) acc[i][j][e] = 0.f;

    GEMM_LOAD_CHUNK(0, 0);
    GEMM_LOAD_CHUNK(1, 1);

    for (int ch = 0; ch < nch; ch++) {
        asm volatile("cp.async.wait_group 1;");
        __syncthreads();
        if (ch + 2 < nch) { GEMM_LOAD_CHUNK(ch + 2, (ch + 2) % NSTAGE); }
        else asm volatile("cp.async.commit_group;");
        const uint32_t smA  = smem_base + (ch % NSTAGE) * GBUF_B;
        const uint32_t smBh = smA + GTILE_B;
        const uint32_t smBl = smBh + GTILE_B;
        #pragma unroll
        for (int k16 = 0; k16 < 2; k16++) {
            uint32_t a[4][4];
            #pragma unroll
            for (int fm = 0; fm < 4; fm++)
                ldsm4(a[fm], smA + ((warp_m * 64 + fm * 16 + lm) * GPAD
                                    + k16 * 16 + lh * 8) * 2);
            uint32_t bh[4][2], bl[4][2];
            #pragma unroll
            for (int fp = 0; fp < 2; fp++) {
                int row = warp_n * 32 + fp * 16 + ((g >> 1) << 3) + r;
                int off = (row * GPAD + (g & 1) * 8 + k16 * 16) * 2;
                uint32_t t4[4];
                ldsm4(t4, smBh + off);
                bh[fp*2][0]=t4[0]; bh[fp*2][1]=t4[1]; bh[fp*2+1][0]=t4[2]; bh[fp*2+1][1]=t4[3];
                ldsm4(t4, smBl + off);
                bl[fp*2][0]=t4[0]; bl[fp*2][1]=t4[1]; bl[fp*2+1][0]=t4[2]; bl[fp*2+1][1]=t4[3];
            }
            #pragma unroll
            for (int fm = 0; fm < 4; fm++)
                #pragma unroll
                for (int fn = 0; fn < 4; fn++) {
                    mma16816(acc[fm][fn], a[fm], bh[fn]);
                    mma16816(acc[fm][fn], a[fm], bl[fn]);
                }
        }
    }

    #pragma unroll
    for (int fm = 0; fm < 4; fm++) {
        int bt0 = m0 + warp_m * 64 + fm * 16 + r4;
        int bt1 = bt0 + 8;
        int t0 = bt0 & (TT - 1), t1 = bt1 & (TT - 1);
        int b  = bt0 >> 11;
        #pragma unroll
        for (int fn = 0; fn < 4; fn++) {
            int n = n0 + warp_n * 32 + fn * 8 + c2;
            int h = n / 112, rr2 = n % 112;
            size_t hb = (size_t)(b * NH + h) * TT;
            if (rr2 < NOPE) {
                size_t a0 = (hb + t0) * HD + rr2, a1 = (hb + t1) * HD + rr2;
                *(uint32_t*)(g_kh + a0) = packh(acc[fm][fn][0], acc[fm][fn][1]);
                *(uint32_t*)(g_kl + a0) = pack_lo_resid(acc[fm][fn][0], acc[fm][fn][1]);
                *(uint32_t*)(g_kh + a1) = packh(acc[fm][fn][2], acc[fm][fn][3]);
                *(uint32_t*)(g_kl + a1) = pack_lo_resid(acc[fm][fn][2], acc[fm][fn][3]);
            } else {
                int d = rr2 - NOPE;
                size_t a0 = (hb + t0) * VD + d, a1 = (hb + t1) * VD + d;
                *(uint32_t*)(g_vh + a0) = packh(acc[fm][fn][0], acc[fm][fn][1]);
                *(uint32_t*)(g_vh + a1) = packh(acc[fm][fn][2], acc[fm][fn][3]);
            }
        }
    }
}

// ======================= Wo GEMM =======================
__global__ __launch_bounds__(256, 2) void wo_gemm(float* __restrict__ C)
{
    extern __shared__ __align__(16) char smem[];
    const int tid = threadIdx.x, wid = tid >> 5, lane = tid & 31;
    const int warp_m = wid >> 2, warp_n = wid & 3;
    const int m0 = blockIdx.y * 128, n0 = blockIdx.x * 128;
    uint32_t smem_base = smem_u32(smem);

    const char* base[3] = { (const char*)(g_aoh + (size_t)m0 * DD),
                            (const char*)(g_Woh + (size_t)n0 * DD),
                            (const char*)(g_Wol + (size_t)n0 * DD) };
    const size_t ldbytes = (size_t)DD * 2;
    const int nch = DD >> 5;

    const int lm = lane & 15, lh = lane >> 4;
    const int g = lane >> 3, r = lane & 7;

    float acc[4][4][4];
    #pragma unroll
    for (int i = 0; i < 4; i++)
        #pragma unroll
        for (int j = 0; j < 4; j++)
            #pragma unroll
            for (int e = 0; e < 4; e++) acc[i][j][e] = 0.f;

    GEMM_LOAD_CHUNK(0, 0);
    GEMM_LOAD_CHUNK(1, 1);

    for (int ch = 0; ch < nch; ch++) {
        asm volatile("cp.async.wait_group 1;");
        __syncthreads();
        if (ch + 2 < nch) { GEMM_LOAD_CHUNK(ch + 2, (ch + 2) % NSTAGE); }
        else asm volatile("cp.async.commit_group;");
        const uint32_t smA  = smem_base + (ch % NSTAGE) * GBUF_B;
        const uint32_t smBh = smA + GTILE_B;
        const uint32_t smBl = smBh + GTILE_B;
        #pragma unroll
        for (int k16 = 0; k16 < 2; k16++) {
            uint32_t a[4][4];
            #pragma unroll
            for (int fm = 0; fm < 4; fm++)
                ldsm4(a[fm], smA + ((warp_m * 64 + fm * 16 + lm) * GPAD
                                    + k16 * 16 + lh * 8) * 2);
            uint32_t bh[4][2], bl[4][2];
            #pragma unroll
            for (int fp = 0; fp < 2; fp++) {
                int row = warp_n * 32 + fp * 16 + ((g >> 1) << 3) + r;
                int off = (row * GPAD + (g & 1) * 8 + k16 * 16) * 2;
                uint32_t t4[4];
                ldsm4(t4, smBh + off);
                bh[fp*2][0]=t4[0]; bh[fp*2][1]=t4[1]; bh[fp*2+1][0]=t4[2]; bh[fp*2+1][1]=t4[3];
                ldsm4(t4, smBl + off);
                bl[fp*2][0]=t4[0]; bl[fp*2][1]=t4[1]; bl[fp*2+1][0]=t4[2]; bl[fp*2+1][1]=t4[3];
            }
            #pragma unroll
            for (int fm = 0; fm < 4; fm++)
                #pragma unroll
                for (int fn = 0; fn < 4; fn++) {
                    mma16816(acc[fm][fn], a[fm], bh[fn]);
                    mma16816(acc[fm][fn], a[fm], bl[fn]);
                }
        }
    }

    const int r4 = lane >> 2, c2 = (lane & 3) * 2;
    #pragma unroll
    for (int fm = 0; fm < 4; fm++) {
        #pragma unroll
        for (int fn = 0; fn < 4; fn++) {
            int m = m0 + warp_m * 64 + fm * 16 + r4;
            int n = n0 + warp_n * 32 + fn * 8 + c2;
            *(float2*)&C[(size_t)m * DD + n] = make_float2(acc[fm][fn][0], acc[fm][fn][1]);
            *(float2*)&C[(size_t)(m + 8) * DD + n] = make_float2(acc[fm][fn][2], acc[fm][fn][3]);
        }
    }
}

// ---------------- flash attention: R9 structure + exp2 ----------------
#define FPAD 72
#define FQLO (3 * 64 * FPAD)    // half offset of persistent Q-lo region

__global__ __launch_bounds__(256, 2) void flash_mma()
{
    __shared__ __align__(16) __half sm[FQLO + 128 * FPAD];   // 46080 B

    const int tid = threadIdx.x, wid = tid >> 5, lane = tid & 31;
    const int bh = blockIdx.y;
    const int b = bh >> 4, h = bh & (NH - 1);
    const int qtile = gridDim.x - 1 - blockIdx.x;
    const int qb = qtile * 128;
    const uint32_t sb = smem_u32(sm);

    const int lm = lane & 15, lh = lane >> 4;
    const int g = lane >> 3, r8 = lane & 7;
    const int r4 = lane >> 2, c2 = (lane & 3) * 2;

    {
        const __half* qhp = g_qh + ((size_t)bh * TT + qb) * HD;
        const __half* qlp = g_ql + ((size_t)bh * TT + qb) * HD;
        for (int i = tid; i < 128 * 8; i += 256) {
            int r = i >> 3, s = i & 7;
            *(uint4*)(sm + r * FPAD + s * 8) = *(const uint4*)(qhp + r * 64 + s * 8);
            *(uint4*)(sm + FQLO + r * FPAD + s * 8) = *(const uint4*)(qlp + r * 64 + s * 8);
        }
    }
    __syncthreads();

    uint32_t qh[4][4];
    #pragma unroll
    for (int ks = 0; ks < 4; ks++)
        ldsm4(qh[ks], sb + ((wid * 16 + lm) * FPAD + ks * 16 + lh * 8) * 2);

    float o[8][4];
    #pragma unroll
    for (int i = 0; i < 8; i++)
        #pragma unroll
        for (int e = 0; e < 4; e++) o[i][e] = 0.f;
    float mrow[2] = { -1e30f, -1e30f };
    float lsum[2] = { 0.f, 0.f };

    const __half* khb = g_kh + (size_t)bh * TT * HD;
    const __half* klb = g_kl + (size_t)bh * TT * HD;
    const __half* vhb = g_vh + (size_t)bh * TT * VD;

    const int ntiles = qtile * 2 + 2;
    const int q0 = qb + wid * 16 + r4;
    const int q1 = q0 + 8;

    const uint32_t oKl = 64 * FPAD * 2;
    const uint32_t oVh = 2 * 64 * FPAD * 2;
    const uint32_t qlo_addr = sb + (FQLO + (wid * 16 + lm) * FPAD + lh * 8) * 2;

    for (int it = 0; it < ntiles; it++) {
        const int j0 = it * 64;
        __syncthreads();
        for (int i = tid; i < 64 * 8; i += 256) {
            int r = i >> 3, s = i & 7;
            size_t gsrc = (size_t)(j0 + r) * 64 + s * 8;
            int dsh = r * FPAD + s * 8;
            *(uint4*)(sm + dsh) = *(const uint4*)(khb + gsrc);
            *(uint4*)(sm + 64 * FPAD + dsh) = *(const uint4*)(klb + gsrc);
            *(uint4*)(sm + 2 * 64 * FPAD + dsh) = *(const uint4*)(vhb + gsrc);
        }
        __syncthreads();

        float s[8][4];
        #pragma unroll
        for (int i = 0; i < 8; i++)
            #pragma unroll
            for (int e = 0; e < 4; e++) s[i][e] = 0.f;

        #pragma unroll
        for (int ks = 0; ks < 4; ks++) {
            uint32_t qlf[4];
            ldsm4(qlf, qlo_addr + ks * 32);
            #pragma unroll
            for (int fp = 0; fp < 4; fp++) {
                const int krow = fp * 16 + ((g >> 1) << 3) + r8;
                uint32_t addr = sb + (krow * FPAD + (g & 1) * 8 + ks * 16) * 2;
                uint32_t bhf[4], blf[4];
                ldsm4(bhf, addr);
                ldsm4(blf, addr + oKl);
                mma16816(s[fp*2],   qh[ks], bhf);
                mma16816(s[fp*2],   qh[ks], blf);
                mma16816(s[fp*2],   qlf,    bhf);
                mma16816(s[fp*2+1], qh[ks], bhf + 2);
                mma16816(s[fp*2+1], qh[ks], blf + 2);
                mma16816(s[fp*2+1], qlf,    bhf + 2);
            }
        }

        const bool need_mask = (it >= ntiles - 2);
        if (need_mask) {
            #pragma unroll
            for (int fn = 0; fn < 8; fn++) {
                #pragma unroll
                for (int e = 0; e < 4; e++) {
                    int kv = j0 + fn * 8 + c2 + (e & 1);
                    int qq = (e < 2) ? q0 : q1;
                    if (kv > qq) s[fn][e] = -1e30f;
                }
            }
        }

        float tm0 = -1e30f, tm1 = -1e30f;
        #pragma unroll
        for (int fn = 0; fn < 8; fn++) {
            tm0 = fmaxf(tm0, fmaxf(s[fn][0], s[fn][1]));
            tm1 = fmaxf(tm1, fmaxf(s[fn][2], s[fn][3]));
        }
        tm0 = fmaxf(tm0, __shfl_xor_sync(~0u, tm0, 1));
        tm0 = fmaxf(tm0, __shfl_xor_sync(~0u, tm0, 2));
        tm1 = fmaxf(tm1, __shfl_xor_sync(~0u, tm1, 1));
        tm1 = fmaxf(tm1, __shfl_xor_sync(~0u, tm1, 2));

        float mn0 = fmaxf(mrow[0], tm0), mn1 = fmaxf(mrow[1], tm1);
        float cr0 = exp2f(mrow[0] - mn0), cr1 = exp2f(mrow[1] - mn1);
        mrow[0] = mn0; mrow[1] = mn1;
        lsum[0] *= cr0; lsum[1] *= cr1;
        #pragma unroll
        for (int fn = 0; fn < 8; fn++) {
            o[fn][0] *= cr0; o[fn][1] *= cr0;
            o[fn][2] *= cr1; o[fn][3] *= cr1;
        }

        #pragma unroll
        for (int fn = 0; fn < 8; fn++) {
            s[fn][0] = exp2f(s[fn][0] - mn0);
            s[fn][1] = exp2f(s[fn][1] - mn0);
            s[fn][2] = exp2f(s[fn][2] - mn1);
            s[fn][3] = exp2f(s[fn][3] - mn1);
            lsum[0] += s[fn][0] + s[fn][1];
            lsum[1] += s[fn][2] + s[fn][3];
        }

        #pragma unroll
        for (int ks = 0; ks < 4; ks++) {
            uint32_t aph[4], apl[4];
            aph[0] = packh(s[ks*2][0], s[ks*2][1]);
            aph[1] = packh(s[ks*2][2], s[ks*2][3]);
            aph[2] = packh(s[ks*2+1][0], s[ks*2+1][1]);
            aph[3] = packh(s[ks*2+1][2], s[ks*2+1][3]);
            apl[0] = pack_lo_resid(s[ks*2][0], s[ks*2][1]);
            apl[1] = pack_lo_resid(s[ks*2][2], s[ks*2][3]);
            apl[2] = pack_lo_resid(s[ks*2+1][0], s[ks*2+1][1]);
            apl[3] = pack_lo_resid(s[ks*2+1][2], s[ks*2+1][3]);

            const int vrow = ks * 16 + (g & 1) * 8 + r8;
            #pragma unroll
            for (int np = 0; np < 4; np++) {
                const int vcol = np * 16 + lh * 8;
                uint32_t addr = sb + oVh + (vrow * FPAD + vcol) * 2;
                uint32_t bvh[4];
                ldsm4t(bvh, addr);
                mma16816(o[np*2],   aph, bvh);
                mma16816(o[np*2],   apl, bvh);
                mma16816(o[np*2+1], aph, bvh + 2);
                mma16816(o[np*2+1], apl, bvh + 2);
            }
        }
    }

    lsum[0] += __shfl_xor_sync(~0u, lsum[0], 1);
    lsum[0] += __shfl_xor_sync(~0u, lsum[0], 2);
    lsum[1] += __shfl_xor_sync(~0u, lsum[1], 1);
    lsum[1] += __shfl_xor_sync(~0u, lsum[1], 2);
    const float inv0 = 1.f / lsum[0], inv1 = 1.f / lsum[1];

    __half* ob0 = g_aoh + ((size_t)(b * TT + q0)) * (NH * VD) + h * VD;
    __half* ob1 = g_aoh + ((size_t)(b * TT + q1)) * (NH * VD) + h * VD;
    #pragma unroll
    for (int fn = 0; fn < 8; fn++) {
        *(uint32_t*)(ob0 + fn * 8 + c2) = packh(o[fn][0] * inv0, o[fn][1] * inv0);
        *(uint32_t*)(ob1 + fn * 8 + c2) = packh(o[fn][2] * inv1, o[fn][3] * inv1);
    }
}

// ---------------- launch ----------------
extern "C" void kernel_launch(void* const* d_in, const int* in_sizes, int n_in,
                              void* d_out, int out_size)
{
    const float* x    = (const float*)d_in[0];
    const float* cosp = (const float*)d_in[1];
    const float* sinp = (const float*)d_in[2];
    const float* Wq   = (const float*)d_in[3];
    const float* qw   = (const float*)d_in[4];
    const float* Wkva = (const float*)d_in[5];
    const float* kvaw = (const float*)d_in[6];
    const float* Wkvb = (const float*)d_in[7];
    const float* Wo   = (const float*)d_in[8];
    float* out = (float*)d_out;

    cudaFuncSetAttribute(proj1_gemm, cudaFuncAttributeMaxDynamicSharedMemorySize, NSTAGE * GBUF_B);
    cudaFuncSetAttribute(kvb_gemm,   cudaFuncAttributeMaxDynamicSharedMemorySize, NSTAGE * GBUF_B);
    cudaFuncSetAttribute(wo_gemm,    cudaFuncAttributeMaxDynamicSharedMemorySize, NSTAGE * GBUF_B);

    cvt_all<<<(QTOT + 255) / 256, 256>>>(x, Wq, Wkva, Wkvb, Wo);

    {
        dim3 g(W1_ROWS / 128, MTOT / 128);
        proj1_gemm<<<g, 256, NSTAGE * GBUF_B>>>(cosp, sinp, qw, kvaw);
    }
    {
        dim3 g(KVB_N / 128, MTOT / 128);
        kvb_gemm<<<g, 256, NSTAGE * GBUF_B>>>();
    }
    {
        dim3 g(TT / 128, BB * NH);
        flash_mma<<<g, 256>>>();
    }
    {
        dim3 g(DD / 128, MTOT / 128);
        wo_gemm<<<g, 256, NSTAGE * GBUF_B>>>(out);
    }
}

// round 14
// speedup vs baseline: 1.1687x; 1.0812x over previous
#include <cuda_runtime.h>
#include <cuda_fp16.h>
#include <math.h>
#include <cstdint>

#define BB 2
#define TT 2048
#define DD 1024
#define NH 16
#define HD 64      // NOPE_D + ROPE_D
#define NOPE 48
#define ROPED 16
#define RR 128
#define VD 64
#define KVB_N (NH * (NOPE + VD))   // 1792
#define MTOT (BB * TT)             // 4096
#define W1_ROWS 1280               // 1024 (Wq) + 128 (latent) + 16 (rope) + 112 pad
#define QSCALE 0.18033688011112042f   // 0.125 * log2(e)

// ---------------- device scratch ----------------
__device__ __align__(256) __half g_qh[BB*NH*TT*HD], g_ql[BB*NH*TT*HD];
__device__ __align__(256) __half g_kh[BB*NH*TT*HD], g_kl[BB*NH*TT*HD];
__device__ __align__(256) __half g_vh[BB*NH*TT*VD];

__device__ __align__(256) __half g_xh [MTOT * DD];
__device__ __align__(256) __half g_W1h[W1_ROWS * DD], g_W1l[W1_ROWS * DD];
__device__ __align__(256) __half g_Wbh[KVB_N * RR],   g_Wbl[KVB_N * RR];
__device__ __align__(256) __half g_Woh[DD * DD],      g_Wol[DD * DD];
__device__ __align__(256) __half g_lth[MTOT * RR];
__device__ __align__(256) __half g_aoh[MTOT * DD];

// ======================= helpers =======================
__device__ __forceinline__ uint32_t smem_u32(const void* p) {
    uint32_t a;
    asm("{ .reg .u64 t; cvta.to.shared.u64 t, %1; cvt.u32.u64 %0, t; }" : "=r"(a) : "l"(p));
    return a;
}
__device__ __forceinline__ void mma16816(float* c, const uint32_t* a, const uint32_t* b) {
    asm volatile("mma.sync.aligned.m16n8k16.row.col.f32.f16.f16.f32 "
        "{%0,%1,%2,%3}, {%4,%5,%6,%7}, {%8,%9}, {%0,%1,%2,%3};"
        : "+f"(c[0]), "+f"(c[1]), "+f"(c[2]), "+f"(c[3])
        : "r"(a[0]), "r"(a[1]), "r"(a[2]), "r"(a[3]), "r"(b[0]), "r"(b[1]));
}
__device__ __forceinline__ void ldsm4(uint32_t* r, uint32_t addr) {
    asm volatile("ldmatrix.sync.aligned.m8n8.x4.shared.b16 {%0,%1,%2,%3}, [%4];"
        : "=r"(r[0]), "=r"(r[1]), "=r"(r[2]), "=r"(r[3]) : "r"(addr));
}
__device__ __forceinline__ void ldsm4t(uint32_t* r, uint32_t addr) {
    asm volatile("ldmatrix.sync.aligned.m8n8.x4.trans.shared.b16 {%0,%1,%2,%3}, [%4];"
        : "=r"(r[0]), "=r"(r[1]), "=r"(r[2]), "=r"(r[3]) : "r"(addr));
}
__device__ __forceinline__ uint32_t packh(float lo, float hi) {
    uint32_t d;
    asm("cvt.rn.f16x2.f32 %0, %1, %2;" : "=r"(d) : "f"(hi), "f"(lo));
    return d;
}
__device__ __forceinline__ uint32_t pack_lo_resid(float v0, float v1) {
    float h0 = __half2float(__float2half(v0));
    float h1 = __half2float(__float2half(v1));
    return packh(v0 - h0, v1 - h1);
}

// ======================= fused conversions =======================
#define QX  (MTOT * DD / 4)
#define QW1 (W1_ROWS * DD / 4)
#define QWB (KVB_N * RR / 4)
#define QWO (DD * DD / 4)
#define QTOT (QX + QW1 + QWB + QWO)

__device__ __forceinline__ void do_hl(const float* s, __half* dh, __half* dl, int e) {
    float4 v = *(const float4*)(s + e);
    __half h0 = __float2half(v.x), h1 = __float2half(v.y);
    __half h2 = __float2half(v.z), h3 = __float2half(v.w);
    ((__half2*)(dh + e))[0] = __half2(h0, h1);
    ((__half2*)(dh + e))[1] = __half2(h2, h3);
    ((__half2*)(dl + e))[0] = __half2(__float2half(v.x - __half2float(h0)),
                                      __float2half(v.y - __half2float(h1)));
    ((__half2*)(dl + e))[1] = __half2(__float2half(v.z - __half2float(h2)),
                                      __float2half(v.w - __half2float(h3)));
}

__global__ __launch_bounds__(256) void cvt_all(
    const float* __restrict__ x,    const float* __restrict__ Wq,
    const float* __restrict__ Wkva, const float* __restrict__ Wkvb,
    const float* __restrict__ Wo)
{
    int qi = blockIdx.x * blockDim.x + threadIdx.x;
    if (qi >= QTOT) return;
    if (qi < QX) {
        int e = qi * 4;
        float4 v = *(const float4*)(x + e);
        ((__half2*)(g_xh + e))[0] = __half2(__float2half(v.x), __float2half(v.y));
        ((__half2*)(g_xh + e))[1] = __half2(__float2half(v.z), __float2half(v.w));
        return;
    }
    qi -= QX;
    if (qi < QW1) {
        int e = qi * 4;
        if (e < DD * DD) { do_hl(Wq, g_W1h, g_W1l, e); }
        else if (e < (DD + 144) * DD) {
            float4 v = *(const float4*)(Wkva + (e - DD * DD));
            __half h0 = __float2half(v.x), h1 = __float2half(v.y);
            __half h2 = __float2half(v.z), h3 = __float2half(v.w);
            ((__half2*)(g_W1h + e))[0] = __half2(h0, h1);
            ((__half2*)(g_W1h + e))[1] = __half2(h2, h3);
            ((__half2*)(g_W1l + e))[0] = __half2(__float2half(v.x - __half2float(h0)),
                                                 __float2half(v.y - __half2float(h1)));
            ((__half2*)(g_W1l + e))[1] = __half2(__float2half(v.z - __half2float(h2)),
                                                 __float2half(v.w - __half2float(h3)));
        } else {
            __half2 z(__half(0.f), __half(0.f));
            ((__half2*)(g_W1h + e))[0] = z; ((__half2*)(g_W1h + e))[1] = z;
            ((__half2*)(g_W1l + e))[0] = z; ((__half2*)(g_W1l + e))[1] = z;
        }
        return;
    }
    qi -= QW1;
    if (qi < QWB) { do_hl(Wkvb, g_Wbh, g_Wbl, qi * 4); return; }
    qi -= QWB;
    do_hl(Wo, g_Woh, g_Wol, qi * 4);
}

// ======================= shared GEMM plumbing =======================
#define GPAD 40
#define GTILE_B (128 * GPAD * 2)
#define GBUF_B  (3 * GTILE_B)
#define NSTAGE 3

#define GEMM_LOAD_CHUNK(ch, buf)                                               \
    do {                                                                       \
        const int k0b = ((ch) << 5) * 2;                                       \
        _Pragma("unroll")                                                      \
        for (int it = 0; it < 6; it++) {                                       \
            int i = tid + it * 256;                                            \
            int mat = i >> 9, rem = i & 511;                                   \
            int row = rem >> 2, seg = rem & 3;                                 \
            const char* src = base[mat] + (size_t)row * ldbytes + k0b + seg * 16; \
            uint32_t dst = smem_base + (buf) * GBUF_B + mat * GTILE_B          \
                         + (row * GPAD + seg * 8) * 2;                         \
            asm volatile("cp.async.cg.shared.global [%0], [%1], 16;" :: "r"(dst), "l"(src)); \
        }                                                                      \
        asm volatile("cp.async.commit_group;");                                \
    } while (0)

// ======================= proj1 =======================
__global__ __launch_bounds__(256, 2) void proj1_gemm(
    const float* __restrict__ cosp, const float* __restrict__ sinp,
    const float* __restrict__ qw,   const float* __restrict__ kvaw)
{
    extern __shared__ __align__(16) char smem[];
    const int tid = threadIdx.x, wid = tid >> 5, lane = tid & 31;
    const int m0 = blockIdx.y * 128, n0 = blockIdx.x * 128;
    uint32_t smem_base = smem_u32(smem);

    const char* base[3] = { (const char*)(g_xh  + (size_t)m0 * DD),
                            (const char*)(g_W1h + (size_t)n0 * DD),
                            (const char*)(g_W1l + (size_t)n0 * DD) };
    const size_t ldbytes = (size_t)DD * 2;
    const int nch = DD >> 5;

    const int lm = lane & 15, lh = lane >> 4;
    const int g = lane >> 3, r8 = lane & 7;
    const int r4 = lane >> 2, c2 = (lane & 3) * 2;

    float acc[16][4];
    #pragma unroll
    for (int i = 0; i < 16; i++)
        #pragma unroll
        for (int e = 0; e < 4; e++) acc[i][e] = 0.f;

    GEMM_LOAD_CHUNK(0, 0);
    GEMM_LOAD_CHUNK(1, 1);

    for (int ch = 0; ch < nch; ch++) {
        asm volatile("cp.async.wait_group 1;");
        __syncthreads();
        if (ch + 2 < nch) { GEMM_LOAD_CHUNK(ch + 2, (ch + 2) % NSTAGE); }
        else asm volatile("cp.async.commit_group;");
        const uint32_t smA  = smem_base + (ch % NSTAGE) * GBUF_B;
        const uint32_t smBh = smA + GTILE_B;
        const uint32_t smBl = smBh + GTILE_B;
        #pragma unroll
        for (int k16 = 0; k16 < 2; k16++) {
            uint32_t a[4];
            ldsm4(a, smA + ((wid * 16 + lm) * GPAD + k16 * 16 + lh * 8) * 2);
            #pragma unroll
            for (int fp = 0; fp < 8; fp++) {
                int row = fp * 16 + ((g >> 1) << 3) + r8;
                int off = (row * GPAD + (g & 1) * 8 + k16 * 16) * 2;
                uint32_t t4[4];
                ldsm4(t4, smBh + off);
                mma16816(acc[fp*2],   a, t4);
                mma16816(acc[fp*2+1], a, t4 + 2);
                ldsm4(t4, smBl + off);
                mma16816(acc[fp*2],   a, t4);
                mma16816(acc[fp*2+1], a, t4 + 2);
            }
        }
    }

    const int bt0 = m0 + wid * 16 + r4;
    const int bt1 = bt0 + 8;
    const int t0 = bt0 & (TT - 1), t1 = bt1 & (TT - 1);
    const int b  = bt0 >> 11;

    if (blockIdx.x < 8) {
        float s00 = 0, s01 = 0, s10 = 0, s11 = 0;
        #pragma unroll
        for (int fn = 0; fn < 16; fn++) {
            float a0 = acc[fn][0]*acc[fn][0] + acc[fn][1]*acc[fn][1];
            float a1 = acc[fn][2]*acc[fn][2] + acc[fn][3]*acc[fn][3];
            if (fn < 8) { s00 += a0; s10 += a1; } else { s01 += a0; s11 += a1; }
        }
        #pragma unroll
        for (int o = 1; o <= 2; o <<= 1) {
            s00 += __shfl_xor_sync(~0u, s00, o);
            s01 += __shfl_xor_sync(~0u, s01, o);
            s10 += __shfl_xor_sync(~0u, s10, o);
            s11 += __shfl_xor_sync(~0u, s11, o);
        }
        float n00 = rsqrtf(s00 * (1.f/HD) + 1e-6f), n01 = rsqrtf(s01 * (1.f/HD) + 1e-6f);
        float n10 = rsqrtf(s10 * (1.f/HD) + 1e-6f), n11 = rsqrtf(s11 * (1.f/HD) + 1e-6f);
        #pragma unroll
        for (int fn = 0; fn < 16; fn++) {
            int d0 = (fn & 7) * 8 + c2;
            float w0 = qw[d0], w1 = qw[d0 + 1];
            float f0 = (fn < 8) ? n00 : n01, f1 = (fn < 8) ? n10 : n11;
            acc[fn][0] *= f0 * w0; acc[fn][1] *= f0 * w1;
            acc[fn][2] *= f1 * w0; acc[fn][3] *= f1 * w1;
        }
        float c00 = cosp[t0*8 + c2], c01 = cosp[t0*8 + c2 + 1];
        float sn00 = sinp[t0*8 + c2], sn01 = sinp[t0*8 + c2 + 1];
        float c10 = cosp[t1*8 + c2], c11 = cosp[t1*8 + c2 + 1];
        float sn10 = sinp[t1*8 + c2], sn11 = sinp[t1*8 + c2 + 1];
        #pragma unroll
        for (int hp = 0; hp < 2; hp++) {
            int f1i = hp * 8 + 6, f2i = f1i + 1;
            float x10 = acc[f1i][0], x11 = acc[f1i][1], x12 = acc[f1i][2], x13 = acc[f1i][3];
            float x20 = acc[f2i][0], x21 = acc[f2i][1], x22 = acc[f2i][2], x23 = acc[f2i][3];
            acc[f1i][0] = x10*c00 - x20*sn00; acc[f1i][1] = x11*c01 - x21*sn01;
            acc[f1i][2] = x12*c10 - x22*sn10; acc[f1i][3] = x13*c11 - x23*sn11;
            acc[f2i][0] = x20*c00 + x10*sn00; acc[f2i][1] = x21*c01 + x11*sn01;
            acc[f2i][2] = x22*c10 + x12*sn10; acc[f2i][3] = x23*c11 + x13*sn11;
        }
        #pragma unroll
        for (int fn = 0; fn < 16; fn++) {
            #pragma unroll
            for (int e = 0; e < 4; e++) acc[fn][e] *= QSCALE;
        }
        #pragma unroll
        for (int fn = 0; fn < 16; fn++) {
            int hg = (n0 >> 6) + (fn >> 3);
            int d  = (fn & 7) * 8 + c2;
            size_t a0 = (((size_t)(b * NH + hg)) * TT + t0) * HD + d;
            size_t a1 = (((size_t)(b * NH + hg)) * TT + t1) * HD + d;
            *(uint32_t*)(g_qh + a0) = packh(acc[fn][0], acc[fn][1]);
            *(uint32_t*)(g_ql + a0) = pack_lo_resid(acc[fn][0], acc[fn][1]);
            *(uint32_t*)(g_qh + a1) = packh(acc[fn][2], acc[fn][3]);
            *(uint32_t*)(g_ql + a1) = pack_lo_resid(acc[fn][2], acc[fn][3]);
        }
    } else if (blockIdx.x == 8) {
        float s0 = 0, s1 = 0;
        #pragma unroll
        for (int fn = 0; fn < 16; fn++) {
            s0 += acc[fn][0]*acc[fn][0] + acc[fn][1]*acc[fn][1];
            s1 += acc[fn][2]*acc[fn][2] + acc[fn][3]*acc[fn][3];
        }
        #pragma unroll
        for (int o = 1; o <= 2; o <<= 1) {
            s0 += __shfl_xor_sync(~0u, s0, o);
            s1 += __shfl_xor_sync(~0u, s1, o);
        }
        float n0f = rsqrtf(s0 * (1.f/RR) + 1e-6f), n1f = rsqrtf(s1 * (1.f/RR) + 1e-6f);
        #pragma unroll
        for (int fn = 0; fn < 16; fn++) {
            int r = fn * 8 + c2;
            float w0 = kvaw[r], w1 = kvaw[r + 1];
            *(uint32_t*)(g_lth + (size_t)bt0 * RR + r) =
                packh(acc[fn][0] * n0f * w0, acc[fn][1] * n0f * w1);
            *(uint32_t*)(g_lth + (size_t)bt1 * RR + r) =
                packh(acc[fn][2] * n1f * w0, acc[fn][3] * n1f * w1);
        }
    } else {
        float c00 = cosp[t0*8 + c2], c01 = cosp[t0*8 + c2 + 1];
        float sn00 = sinp[t0*8 + c2], sn01 = sinp[t0*8 + c2 + 1];
        float c10 = cosp[t1*8 + c2], c11 = cosp[t1*8 + c2 + 1];
        float sn10 = sinp[t1*8 + c2], sn11 = sinp[t1*8 + c2 + 1];
        float x10 = acc[0][0], x11 = acc[0][1], x12 = acc[0][2], x13 = acc[0][3];
        float x20 = acc[1][0], x21 = acc[1][1], x22 = acc[1][2], x23 = acc[1][3];
        float o10 = x10*c00 - x20*sn00, o11 = x11*c01 - x21*sn01;
        float o12 = x12*c10 - x22*sn10, o13 = x13*c11 - x23*sn11;
        float o20 = x20*c00 + x10*sn00, o21 = x21*c01 + x11*sn01;
        float o22 = x22*c10 + x12*sn10, o23 = x23*c11 + x13*sn11;
        uint32_t h1a = packh(o10, o11), l1a = pack_lo_resid(o10, o11);
        uint32_t h1b = packh(o12, o13), l1b = pack_lo_resid(o12, o13);
        uint32_t h2a = packh(o20, o21), l2a = pack_lo_resid(o20, o21);
        uint32_t h2b = packh(o22, o23), l2b = pack_lo_resid(o22, o23);
        #pragma unroll
        for (int h = 0; h < NH; h++) {
            size_t a0 = (((size_t)(b * NH + h)) * TT + t0) * HD + 48 + c2;
            size_t a1 = (((size_t)(b * NH + h)) * TT + t1) * HD + 48 + c2;
            *(uint32_t*)(g_kh + a0)     = h1a; *(uint32_t*)(g_kl + a0)     = l1a;
            *(uint32_t*)(g_kh + a0 + 8) = h2a; *(uint32_t*)(g_kl + a0 + 8) = l2a;
            *(uint32_t*)(g_kh + a1)     = h1b; *(uint32_t*)(g_kl + a1)     = l1b;
            *(uint32_t*)(g_kh + a1 + 8) = h2b; *(uint32_t*)(g_kl + a1 + 8) = l2b;
        }
    }
}

// ======================= kvb GEMM with fused scatter =======================
__global__ __launch_bounds__(256, 2) void kvb_gemm()
{
    extern __shared__ __align__(16) char smem[];
    const int tid = threadIdx.x, wid = tid >> 5, lane = tid & 31;
    const int warp_m = wid >> 2, warp_n = wid & 3;
    const int m0 = blockIdx.y * 128, n0 = blockIdx.x * 128;
    uint32_t smem_base = smem_u32(smem);

    const char* base[3] = { (const char*)(g_lth + (size_t)m0 * RR),
                            (const char*)(g_Wbh + (size_t)n0 * RR),
                            (const char*)(g_Wbl + (size_t)n0 * RR) };
    const size_t ldbytes = (size_t)RR * 2;
    const int nch = RR >> 5;

    const int lm = lane & 15, lh = lane >> 4;
    const int g = lane >> 3, r = lane & 7;
    const int r4 = lane >> 2, c2 = (lane & 3) * 2;

    float acc[4][4][4];
    #pragma unroll
    for (int i = 0; i < 4; i++)
        #pragma unroll
        for (int j = 0; j < 4; j++)
            #pragma unroll
            for (int e = 0; e < 4; e++) acc[i][j][e] = 0.f;

    GEMM_LOAD_CHUNK(0, 0);
    GEMM_LOAD_CHUNK(1, 1);

    for (int ch = 0; ch < nch; ch++) {
        asm volatile("cp.async.wait_group 1;");
        __syncthreads();
        if (ch + 2 < nch) { GEMM_LOAD_CHUNK(ch + 2, (ch + 2) % NSTAGE); }
        else asm volatile("cp.async.commit_group;");
        const uint32_t smA  = smem_base + (ch % NSTAGE) * GBUF_B;
        const uint32_t smBh = smA + GTILE_B;
        const uint32_t smBl = smBh + GTILE_B;
        #pragma unroll
        for (int k16 = 0; k16 < 2; k16++) {
            uint32_t a[4][4];
            #pragma unroll
            for (int fm = 0; fm < 4; fm++)
                ldsm4(a[fm], smA + ((warp_m * 64 + fm * 16 + lm) * GPAD
                                    + k16 * 16 + lh * 8) * 2);
            uint32_t bh[4][2], bl[4][2];
            #pragma unroll
            for (int fp = 0; fp < 2; fp++) {
                int row = warp_n * 32 + fp * 16 + ((g >> 1) << 3) + r;
                int off = (row * GPAD + (g & 1) * 8 + k16 * 16) * 2;
                uint32_t t4[4];
                ldsm4(t4, smBh + off);
                bh[fp*2][0]=t4[0]; bh[fp*2][1]=t4[1]; bh[fp*2+1][0]=t4[2]; bh[fp*2+1][1]=t4[3];
                ldsm4(t4, smBl + off);
                bl[fp*2][0]=t4[0]; bl[fp*2][1]=t4[1]; bl[fp*2+1][0]=t4[2]; bl[fp*2+1][1]=t4[3];
            }
            #pragma unroll
            for (int fm = 0; fm < 4; fm++)
                #pragma unroll
                for (int fn = 0; fn < 4; fn++) {
                    mma16816(acc[fm][fn], a[fm], bh[fn]);
                    mma16816(acc[fm][fn], a[fm], bl[fn]);
                }
        }
    }

    #pragma unroll
    for (int fm = 0; fm < 4; fm++) {
        int bt0 = m0 + warp_m * 64 + fm * 16 + r4;
        int bt1 = bt0 + 8;
        int t0 = bt0 & (TT - 1), t1 = bt1 & (TT - 1);
        int b  = bt0 >> 11;
        #pragma unroll
        for (int fn = 0; fn < 4; fn++) {
            int n = n0 + warp_n * 32 + fn * 8 + c2;
            int h = n / 112, rr2 = n % 112;
            size_t hb = (size_t)(b * NH + h) * TT;
            if (rr2 < NOPE) {
                size_t a0 = (hb + t0) * HD + rr2, a1 = (hb + t1) * HD + rr2;
                *(uint32_t*)(g_kh + a0) = packh(acc[fm][fn][0], acc[fm][fn][1]);
                *(uint32_t*)(g_kl + a0) = pack_lo_resid(acc[fm][fn][0], acc[fm][fn][1]);
                *(uint32_t*)(g_kh + a1) = packh(acc[fm][fn][2], acc[fm][fn][3]);
                *(uint32_t*)(g_kl + a1) = pack_lo_resid(acc[fm][fn][2], acc[fm][fn][3]);
            } else {
                int d = rr2 - NOPE;
                size_t a0 = (hb + t0) * VD + d, a1 = (hb + t1) * VD + d;
                *(uint32_t*)(g_vh + a0) = packh(acc[fm][fn][0], acc[fm][fn][1]);
                *(uint32_t*)(g_vh + a1) = packh(acc[fm][fn][2], acc[fm][fn][3]);
            }
        }
    }
}

// ======================= Wo GEMM =======================
__global__ __launch_bounds__(256, 2) void wo_gemm(float* __restrict__ C)
{
    extern __shared__ __align__(16) char smem[];
    const int tid = threadIdx.x, wid = tid >> 5, lane = tid & 31;
    const int warp_m = wid >> 2, warp_n = wid & 3;
    const int m0 = blockIdx.y * 128, n0 = blockIdx.x * 128;
    uint32_t smem_base = smem_u32(smem);

    const char* base[3] = { (const char*)(g_aoh + (size_t)m0 * DD),
                            (const char*)(g_Woh + (size_t)n0 * DD),
                            (const char*)(g_Wol + (size_t)n0 * DD) };
    const size_t ldbytes = (size_t)DD * 2;
    const int nch = DD >> 5;

    const int lm = lane & 15, lh = lane >> 4;
    const int g = lane >> 3, r = lane & 7;

    float acc[4][4][4];
    #pragma unroll
    for (int i = 0; i < 4; i++)
        #pragma unroll
        for (int j = 0; j < 4; j++)
            #pragma unroll
            for (int e = 0; e < 4; e++) acc[i][j][e] = 0.f;

    GEMM_LOAD_CHUNK(0, 0);
    GEMM_LOAD_CHUNK(1, 1);

    for (int ch = 0; ch < nch; ch++) {
        asm volatile("cp.async.wait_group 1;");
        __syncthreads();
        if (ch + 2 < nch) { GEMM_LOAD_CHUNK(ch + 2, (ch + 2) % NSTAGE); }
        else asm volatile("cp.async.commit_group;");
        const uint32_t smA  = smem_base + (ch % NSTAGE) * GBUF_B;
        const uint32_t smBh = smA + GTILE_B;
        const uint32_t smBl = smBh + GTILE_B;
        #pragma unroll
        for (int k16 = 0; k16 < 2; k16++) {
            uint32_t a[4][4];
            #pragma unroll
            for (int fm = 0; fm < 4; fm++)
                ldsm4(a[fm], smA + ((warp_m * 64 + fm * 16 + lm) * GPAD
                                    + k16 * 16 + lh * 8) * 2);
            uint32_t bh[4][2], bl[4][2];
            #pragma unroll
            for (int fp = 0; fp < 2; fp++) {
                int row = warp_n * 32 + fp * 16 + ((g >> 1) << 3) + r;
                int off = (row * GPAD + (g & 1) * 8 + k16 * 16) * 2;
                uint32_t t4[4];
                ldsm4(t4, smBh + off);
                bh[fp*2][0]=t4[0]; bh[fp*2][1]=t4[1]; bh[fp*2+1][0]=t4[2]; bh[fp*2+1][1]=t4[3];
                ldsm4(t4, smBl + off);
                bl[fp*2][0]=t4[0]; bl[fp*2][1]=t4[1]; bl[fp*2+1][0]=t4[2]; bl[fp*2+1][1]=t4[3];
            }
            #pragma unroll
            for (int fm = 0; fm < 4; fm++)
                #pragma unroll
                for (int fn = 0; fn < 4; fn++) {
                    mma16816(acc[fm][fn], a[fm], bh[fn]);
                    mma16816(acc[fm][fn], a[fm], bl[fn]);
                }
        }
    }

    const int r4 = lane >> 2, c2 = (lane & 3) * 2;
    #pragma unroll
    for (int fm = 0; fm < 4; fm++) {
        #pragma unroll
        for (int fn = 0; fn < 4; fn++) {
            int m = m0 + warp_m * 64 + fm * 16 + r4;
            int n = n0 + warp_n * 32 + fn * 8 + c2;
            *(float2*)&C[(size_t)m * DD + n] = make_float2(acc[fm][fn][0], acc[fm][fn][1]);
            *(float2*)&C[(size_t)(m + 8) * DD + n] = make_float2(acc[fm][fn][2], acc[fm][fn][3]);
        }
    }
}

// ---------------- flash attention: paired q-tiles, single balanced wave ----------------
#define FPAD 72
#define FQLO (3 * 64 * FPAD)    // half offset of persistent Q-lo region

__global__ __launch_bounds__(256, 2) void flash_mma()
{
    __shared__ __align__(16) __half sm[FQLO + 128 * FPAD];   // 46080 B

    const int tid = threadIdx.x, wid = tid >> 5, lane = tid & 31;
    const int bh = blockIdx.y;
    const int b = bh >> 4, h = bh & (NH - 1);
    const uint32_t sb = smem_u32(sm);

    const int lm = lane & 15, lh = lane >> 4;
    const int g = lane >> 3, r8 = lane & 7;
    const int r4 = lane >> 2, c2 = (lane & 3) * 2;

    const __half* khb = g_kh + (size_t)bh * TT * HD;
    const __half* klb = g_kl + (size_t)bh * TT * HD;
    const __half* vhb = g_vh + (size_t)bh * TT * VD;

    const uint32_t oKl = 64 * FPAD * 2;
    const uint32_t oVh = 2 * 64 * FPAD * 2;
    const uint32_t qlo_addr = sb + (FQLO + (wid * 16 + lm) * FPAD + lh * 8) * 2;
    const int npairs = TT / 128 - 1;   // 15

    #pragma unroll 1
    for (int ph = 0; ph < 2; ph++) {
        const int qtile = ph ? (int)blockIdx.x : (npairs - (int)blockIdx.x);
        const int qb = qtile * 128;

        // protect Q smem regions from previous phase's in-flight reads
        __syncthreads();
        {
            const __half* qhp = g_qh + ((size_t)bh * TT + qb) * HD;
            const __half* qlp = g_ql + ((size_t)bh * TT + qb) * HD;
            for (int i = tid; i < 128 * 8; i += 256) {
                int r = i >> 3, s = i & 7;
                *(uint4*)(sm + r * FPAD + s * 8) = *(const uint4*)(qhp + r * 64 + s * 8);
                *(uint4*)(sm + FQLO + r * FPAD + s * 8) = *(const uint4*)(qlp + r * 64 + s * 8);
            }
        }
        __syncthreads();

        uint32_t qh[4][4];
        #pragma unroll
        for (int ks = 0; ks < 4; ks++)
            ldsm4(qh[ks], sb + ((wid * 16 + lm) * FPAD + ks * 16 + lh * 8) * 2);

        float o[8][4];
        #pragma unroll
        for (int i = 0; i < 8; i++)
            #pragma unroll
            for (int e = 0; e < 4; e++) o[i][e] = 0.f;
        float mrow[2] = { -1e30f, -1e30f };
        float lsum[2] = { 0.f, 0.f };

        const int ntiles = qtile * 2 + 2;
        const int q0 = qb + wid * 16 + r4;
        const int q1 = q0 + 8;

        for (int it = 0; it < ntiles; it++) {
            const int j0 = it * 64;
            __syncthreads();
            for (int i = tid; i < 64 * 8; i += 256) {
                int r = i >> 3, s = i & 7;
                size_t gsrc = (size_t)(j0 + r) * 64 + s * 8;
                int dsh = r * FPAD + s * 8;
                *(uint4*)(sm + dsh) = *(const uint4*)(khb + gsrc);
                *(uint4*)(sm + 64 * FPAD + dsh) = *(const uint4*)(klb + gsrc);
                *(uint4*)(sm + 2 * 64 * FPAD + dsh) = *(const uint4*)(vhb + gsrc);
            }
            __syncthreads();

            float s[8][4];
            #pragma unroll
            for (int i = 0; i < 8; i++)
                #pragma unroll
                for (int e = 0; e < 4; e++) s[i][e] = 0.f;

            #pragma unroll
            for (int ks = 0; ks < 4; ks++) {
                uint32_t qlf[4];
                ldsm4(qlf, qlo_addr + ks * 32);
                #pragma unroll
                for (int fp = 0; fp < 4; fp++) {
                    const int krow = fp * 16 + ((g >> 1) << 3) + r8;
                    uint32_t addr = sb + (krow * FPAD + (g & 1) * 8 + ks * 16) * 2;
                    uint32_t bhf[4], blf[4];
                    ldsm4(bhf, addr);
                    ldsm4(blf, addr + oKl);
                    mma16816(s[fp*2],   qh[ks], bhf);
                    mma16816(s[fp*2],   qh[ks], blf);
                    mma16816(s[fp*2],   qlf,    bhf);
                    mma16816(s[fp*2+1], qh[ks], bhf + 2);
                    mma16816(s[fp*2+1], qh[ks], blf + 2);
                    mma16816(s[fp*2+1], qlf,    bhf + 2);
                }
            }

            const bool need_mask = (it >= ntiles - 2);
            if (need_mask) {
                #pragma unroll
                for (int fn = 0; fn < 8; fn++) {
                    #pragma unroll
                    for (int e = 0; e < 4; e++) {
                        int kv = j0 + fn * 8 + c2 + (e & 1);
                        int qq = (e < 2) ? q0 : q1;
                        if (kv > qq) s[fn][e] = -1e30f;
                    }
                }
            }

            float tm0 = -1e30f, tm1 = -1e30f;
            #pragma unroll
            for (int fn = 0; fn < 8; fn++) {
                tm0 = fmaxf(tm0, fmaxf(s[fn][0], s[fn][1]));
                tm1 = fmaxf(tm1, fmaxf(s[fn][2], s[fn][3]));
            }
            tm0 = fmaxf(tm0, __shfl_xor_sync(~0u, tm0, 1));
            tm0 = fmaxf(tm0, __shfl_xor_sync(~0u, tm0, 2));
            tm1 = fmaxf(tm1, __shfl_xor_sync(~0u, tm1, 1));
            tm1 = fmaxf(tm1, __shfl_xor_sync(~0u, tm1, 2));

            float mn0 = fmaxf(mrow[0], tm0), mn1 = fmaxf(mrow[1], tm1);
            float cr0 = exp2f(mrow[0] - mn0), cr1 = exp2f(mrow[1] - mn1);
            mrow[0] = mn0; mrow[1] = mn1;
            lsum[0] *= cr0; lsum[1] *= cr1;
            #pragma unroll
            for (int fn = 0; fn < 8; fn++) {
                o[fn][0] *= cr0; o[fn][1] *= cr0;
                o[fn][2] *= cr1; o[fn][3] *= cr1;
            }

            #pragma unroll
            for (int fn = 0; fn < 8; fn++) {
                s[fn][0] = exp2f(s[fn][0] - mn0);
                s[fn][1] = exp2f(s[fn][1] - mn0);
                s[fn][2] = exp2f(s[fn][2] - mn1);
                s[fn][3] = exp2f(s[fn][3] - mn1);
                lsum[0] += s[fn][0] + s[fn][1];
                lsum[1] += s[fn][2] + s[fn][3];
            }

            #pragma unroll
            for (int ks = 0; ks < 4; ks++) {
                uint32_t aph[4], apl[4];
                aph[0] = packh(s[ks*2][0], s[ks*2][1]);
                aph[1] = packh(s[ks*2][2], s[ks*2][3]);
                aph[2] = packh(s[ks*2+1][0], s[ks*2+1][1]);
                aph[3] = packh(s[ks*2+1][2], s[ks*2+1][3]);
                apl[0] = pack_lo_resid(s[ks*2][0], s[ks*2][1]);
                apl[1] = pack_lo_resid(s[ks*2][2], s[ks*2][3]);
                apl[2] = pack_lo_resid(s[ks*2+1][0], s[ks*2+1][1]);
                apl[3] = pack_lo_resid(s[ks*2+1][2], s[ks*2+1][3]);

                const int vrow = ks * 16 + (g & 1) * 8 + r8;
                #pragma unroll
                for (int np = 0; np < 4; np++) {
                    const int vcol = np * 16 + lh * 8;
                    uint32_t addr = sb + oVh + (vrow * FPAD + vcol) * 2;
                    uint32_t bvh[4];
                    ldsm4t(bvh, addr);
                    mma16816(o[np*2],   aph, bvh);
                    mma16816(o[np*2],   apl, bvh);
                    mma16816(o[np*2+1], aph, bvh + 2);
                    mma16816(o[np*2+1], apl, bvh + 2);
                }
            }
        }

        lsum[0] += __shfl_xor_sync(~0u, lsum[0], 1);
        lsum[0] += __shfl_xor_sync(~0u, lsum[0], 2);
        lsum[1] += __shfl_xor_sync(~0u, lsum[1], 1);
        lsum[1] += __shfl_xor_sync(~0u, lsum[1], 2);
        const float inv0 = 1.f / lsum[0], inv1 = 1.f / lsum[1];

        __half* ob0 = g_aoh + ((size_t)(b * TT + q0)) * (NH * VD) + h * VD;
        __half* ob1 = g_aoh + ((size_t)(b * TT + q1)) * (NH * VD) + h * VD;
        #pragma unroll
        for (int fn = 0; fn < 8; fn++) {
            *(uint32_t*)(ob0 + fn * 8 + c2) = packh(o[fn][0] * inv0, o[fn][1] * inv0);
            *(uint32_t*)(ob1 + fn * 8 + c2) = packh(o[fn][2] * inv1, o[fn][3] * inv1);
        }
    }
}

// ---------------- launch ----------------
extern "C" void kernel_launch(void* const* d_in, const int* in_sizes, int n_in,
                              void* d_out, int out_size)
{
    const float* x    = (const float*)d_in[0];
    const float* cosp = (const float*)d_in[1];
    const float* sinp = (const float*)d_in[2];
    const float* Wq   = (const float*)d_in[3];
    const float* qw   = (const float*)d_in[4];
    const float* Wkva = (const float*)d_in[5];
    const float* kvaw = (const float*)d_in[6];
    const float* Wkvb = (const float*)d_in[7];
    const float* Wo   = (const float*)d_in[8];
    float* out = (float*)d_out;

    cudaFuncSetAttribute(proj1_gemm, cudaFuncAttributeMaxDynamicSharedMemorySize, NSTAGE * GBUF_B);
    cudaFuncSetAttribute(kvb_gemm,   cudaFuncAttributeMaxDynamicSharedMemorySize, NSTAGE * GBUF_B);
    cudaFuncSetAttribute(wo_gemm,    cudaFuncAttributeMaxDynamicSharedMemorySize, NSTAGE * GBUF_B);

    cvt_all<<<(QTOT + 255) / 256, 256>>>(x, Wq, Wkva, Wkvb, Wo);

    {
        dim3 g(W1_ROWS / 128, MTOT / 128);
        proj1_gemm<<<g, 256, NSTAGE * GBUF_B>>>(cosp, sinp, qw, kvaw);
    }
    {
        dim3 g(KVB_N / 128, MTOT / 128);
        kvb_gemm<<<g, 256, NSTAGE * GBUF_B>>>();
    }
    {
        dim3 g(TT / 256, BB * NH);   // 8 x 32 = 256 CTAs, one balanced wave
        flash_mma<<<g, 256>>>();
    }
    {
        dim3 g(DD / 128, MTOT / 128);
        wo_gemm<<<g, 256, NSTAGE * GBUF_B>>>(out);
    }
}

// round 15
// speedup vs baseline: 1.2618x; 1.0797x over previous
#include <cuda_runtime.h>
#include <cuda_fp16.h>
#include <math.h>
#include <cstdint>

#define BB 2
#define TT 2048
#define DD 1024
#define NH 16
#define HD 64      // NOPE_D + ROPE_D
#define NOPE 48
#define ROPED 16
#define RR 128
#define VD 64
#define KVB_N (NH * (NOPE + VD))   // 1792
#define MTOT (BB * TT)             // 4096
#define W1_ROWS 1280               // 1024 (Wq) + 128 (latent) + 16 (rope) + 112 pad
#define QSCALE 0.18033688011112042f   // 0.125 * log2(e)

// ---------------- device scratch ----------------
__device__ __align__(256) __half g_qh[BB*NH*TT*HD], g_ql[BB*NH*TT*HD];
__device__ __align__(256) __half g_kh[BB*NH*TT*HD], g_kl[BB*NH*TT*HD];
__device__ __align__(256) __half g_vh[BB*NH*TT*VD];

__device__ __align__(256) __half g_xh [MTOT * DD];
__device__ __align__(256) __half g_W1h[W1_ROWS * DD], g_W1l[W1_ROWS * DD];
__device__ __align__(256) __half g_Wbh[KVB_N * RR],   g_Wbl[KVB_N * RR];
__device__ __align__(256) __half g_Woh[DD * DD];
__device__ __align__(256) __half g_lth[MTOT * RR];
__device__ __align__(256) __half g_aoh[MTOT * DD];

// ======================= helpers =======================
__device__ __forceinline__ uint32_t smem_u32(const void* p) {
    uint32_t a;
    asm("{ .reg .u64 t; cvta.to.shared.u64 t, %1; cvt.u32.u64 %0, t; }" : "=r"(a) : "l"(p));
    return a;
}
__device__ __forceinline__ void mma16816(float* c, const uint32_t* a, const uint32_t* b) {
    asm volatile("mma.sync.aligned.m16n8k16.row.col.f32.f16.f16.f32 "
        "{%0,%1,%2,%3}, {%4,%5,%6,%7}, {%8,%9}, {%0,%1,%2,%3};"
        : "+f"(c[0]), "+f"(c[1]), "+f"(c[2]), "+f"(c[3])
        : "r"(a[0]), "r"(a[1]), "r"(a[2]), "r"(a[3]), "r"(b[0]), "r"(b[1]));
}
__device__ __forceinline__ void ldsm4(uint32_t* r, uint32_t addr) {
    asm volatile("ldmatrix.sync.aligned.m8n8.x4.shared.b16 {%0,%1,%2,%3}, [%4];"
        : "=r"(r[0]), "=r"(r[1]), "=r"(r[2]), "=r"(r[3]) : "r"(addr));
}
__device__ __forceinline__ void ldsm4t(uint32_t* r, uint32_t addr) {
    asm volatile("ldmatrix.sync.aligned.m8n8.x4.trans.shared.b16 {%0,%1,%2,%3}, [%4];"
        : "=r"(r[0]), "=r"(r[1]), "=r"(r[2]), "=r"(r[3]) : "r"(addr));
}
__device__ __forceinline__ uint32_t packh(float lo, float hi) {
    uint32_t d;
    asm("cvt.rn.f16x2.f32 %0, %1, %2;" : "=r"(d) : "f"(hi), "f"(lo));
    return d;
}
__device__ __forceinline__ uint32_t pack_lo_resid(float v0, float v1) {
    float h0 = __half2float(__float2half(v0));
    float h1 = __half2float(__float2half(v1));
    return packh(v0 - h0, v1 - h1);
}

// ======================= fused conversions =======================
#define QX  (MTOT * DD / 4)
#define QW1 (W1_ROWS * DD / 4)
#define QWB (KVB_N * RR / 4)
#define QWO (DD * DD / 4)
#define QTOT (QX + QW1 + QWB + QWO)

__device__ __forceinline__ void do_hl(const float* s, __half* dh, __half* dl, int e) {
    float4 v = *(const float4*)(s + e);
    __half h0 = __float2half(v.x), h1 = __float2half(v.y);
    __half h2 = __float2half(v.z), h3 = __float2half(v.w);
    ((__half2*)(dh + e))[0] = __half2(h0, h1);
    ((__half2*)(dh + e))[1] = __half2(h2, h3);
    ((__half2*)(dl + e))[0] = __half2(__float2half(v.x - __half2float(h0)),
                                      __float2half(v.y - __half2float(h1)));
    ((__half2*)(dl + e))[1] = __half2(__float2half(v.z - __half2float(h2)),
                                      __float2half(v.w - __half2float(h3)));
}

__global__ __launch_bounds__(256) void cvt_all(
    const float* __restrict__ x,    const float* __restrict__ Wq,
    const float* __restrict__ Wkva, const float* __restrict__ Wkvb,
    const float* __restrict__ Wo)
{
    int qi = blockIdx.x * blockDim.x + threadIdx.x;
    if (qi >= QTOT) return;
    if (qi < QX) {
        int e = qi * 4;
        float4 v = *(const float4*)(x + e);
        ((__half2*)(g_xh + e))[0] = __half2(__float2half(v.x), __float2half(v.y));
        ((__half2*)(g_xh + e))[1] = __half2(__float2half(v.z), __float2half(v.w));
        return;
    }
    qi -= QX;
    if (qi < QW1) {
        int e = qi * 4;
        if (e < DD * DD) { do_hl(Wq, g_W1h, g_W1l, e); }
        else if (e < (DD + 144) * DD) {
            float4 v = *(const float4*)(Wkva + (e - DD * DD));
            __half h0 = __float2half(v.x), h1 = __float2half(v.y);
            __half h2 = __float2half(v.z), h3 = __float2half(v.w);
            ((__half2*)(g_W1h + e))[0] = __half2(h0, h1);
            ((__half2*)(g_W1h + e))[1] = __half2(h2, h3);
            ((__half2*)(g_W1l + e))[0] = __half2(__float2half(v.x - __half2float(h0)),
                                                 __float2half(v.y - __half2float(h1)));
            ((__half2*)(g_W1l + e))[1] = __half2(__float2half(v.z - __half2float(h2)),
                                                 __float2half(v.w - __half2float(h3)));
        } else {
            __half2 z(__half(0.f), __half(0.f));
            ((__half2*)(g_W1h + e))[0] = z; ((__half2*)(g_W1h + e))[1] = z;
            ((__half2*)(g_W1l + e))[0] = z; ((__half2*)(g_W1l + e))[1] = z;
        }
        return;
    }
    qi -= QW1;
    if (qi < QWB) { do_hl(Wkvb, g_Wbh, g_Wbl, qi * 4); return; }
    qi -= QWB;
    {   // Wo: hi only (last-stage GEMM runs single-term)
        int e = qi * 4;
        float4 v = *(const float4*)(Wo + e);
        ((__half2*)(g_Woh + e))[0] = __half2(__float2half(v.x), __float2half(v.y));
        ((__half2*)(g_Woh + e))[1] = __half2(__float2half(v.z), __float2half(v.w));
    }
}

// ======================= shared GEMM plumbing =======================
#define GPAD 40
#define GTILE_B (128 * GPAD * 2)
#define GBUF_B  (3 * GTILE_B)
#define NSTAGE 3

#define GEMM_LOAD_CHUNK(ch, buf)                                               \
    do {                                                                       \
        const int k0b = ((ch) << 5) * 2;                                       \
        _Pragma("unroll")                                                      \
        for (int it = 0; it < 6; it++) {                                       \
            int i = tid + it * 256;                                            \
            int mat = i >> 9, rem = i & 511;                                   \
            int row = rem >> 2, seg = rem & 3;                                 \
            const char* src = base[mat] + (size_t)row * ldbytes + k0b + seg * 16; \
            uint32_t dst = smem_base + (buf) * GBUF_B + mat * GTILE_B          \
                         + (row * GPAD + seg * 8) * 2;                         \
            asm volatile("cp.async.cg.shared.global [%0], [%1], 16;" :: "r"(dst), "l"(src)); \
        }                                                                      \
        asm volatile("cp.async.commit_group;");                                \
    } while (0)

// 2-matrix variant (A, B only)
#define GBUF2_B (2 * GTILE_B)
#define GEMM_LOAD_CHUNK2(ch, buf)                                              \
    do {                                                                       \
        const int k0b = ((ch) << 5) * 2;                                       \
        _Pragma("unroll")                                                      \
        for (int it = 0; it < 4; it++) {                                       \
            int i = tid + it * 256;                                            \
            int mat = i >> 9, rem = i & 511;                                   \
            int row = rem >> 2, seg = rem & 3;                                 \
            const char* src = base[mat] + (size_t)row * ldbytes + k0b + seg * 16; \
            uint32_t dst = smem_base + (buf) * GBUF2_B + mat * GTILE_B         \
                         + (row * GPAD + seg * 8) * 2;                         \
            asm volatile("cp.async.cg.shared.global [%0], [%1], 16;" :: "r"(dst), "l"(src)); \
        }                                                                      \
        asm volatile("cp.async.commit_group;");                                \
    } while (0)

// ======================= proj1 =======================
__global__ __launch_bounds__(256, 2) void proj1_gemm(
    const float* __restrict__ cosp, const float* __restrict__ sinp,
    const float* __restrict__ qw,   const float* __restrict__ kvaw)
{
    extern __shared__ __align__(16) char smem[];
    const int tid = threadIdx.x, wid = tid >> 5, lane = tid & 31;
    const int m0 = blockIdx.y * 128, n0 = blockIdx.x * 128;
    uint32_t smem_base = smem_u32(smem);

    const char* base[3] = { (const char*)(g_xh  + (size_t)m0 * DD),
                            (const char*)(g_W1h + (size_t)n0 * DD),
                            (const char*)(g_W1l + (size_t)n0 * DD) };
    const size_t ldbytes = (size_t)DD * 2;
    const int nch = DD >> 5;

    const int lm = lane & 15, lh = lane >> 4;
    const int g = lane >> 3, r8 = lane & 7;
    const int r4 = lane >> 2, c2 = (lane & 3) * 2;

    float acc[16][4];
    #pragma unroll
    for (int i = 0; i < 16; i++)
        #pragma unroll
        for (int e = 0; e < 4; e++) acc[i][e] = 0.f;

    GEMM_LOAD_CHUNK(0, 0);
    GEMM_LOAD_CHUNK(1, 1);

    for (int ch = 0; ch < nch; ch++) {
        asm volatile("cp.async.wait_group 1;");
        __syncthreads();
        if (ch + 2 < nch) { GEMM_LOAD_CHUNK(ch + 2, (ch + 2) % NSTAGE); }
        else asm volatile("cp.async.commit_group;");
        const uint32_t smA  = smem_base + (ch % NSTAGE) * GBUF_B;
        const uint32_t smBh = smA + GTILE_B;
        const uint32_t smBl = smBh + GTILE_B;
        #pragma unroll
        for (int k16 = 0; k16 < 2; k16++) {
            uint32_t a[4];
            ldsm4(a, smA + ((wid * 16 + lm) * GPAD + k16 * 16 + lh * 8) * 2);
            #pragma unroll
            for (int fp = 0; fp < 8; fp++) {
                int row = fp * 16 + ((g >> 1) << 3) + r8;
                int off = (row * GPAD + (g & 1) * 8 + k16 * 16) * 2;
                uint32_t t4[4];
                ldsm4(t4, smBh + off);
                mma16816(acc[fp*2],   a, t4);
                mma16816(acc[fp*2+1], a, t4 + 2);
                ldsm4(t4, smBl + off);
                mma16816(acc[fp*2],   a, t4);
                mma16816(acc[fp*2+1], a, t4 + 2);
            }
        }
    }

    const int bt0 = m0 + wid * 16 + r4;
    const int bt1 = bt0 + 8;
    const int t0 = bt0 & (TT - 1), t1 = bt1 & (TT - 1);
    const int b  = bt0 >> 11;

    if (blockIdx.x < 8) {
        float s00 = 0, s01 = 0, s10 = 0, s11 = 0;
        #pragma unroll
        for (int fn = 0; fn < 16; fn++) {
            float a0 = acc[fn][0]*acc[fn][0] + acc[fn][1]*acc[fn][1];
            float a1 = acc[fn][2]*acc[fn][2] + acc[fn][3]*acc[fn][3];
            if (fn < 8) { s00 += a0; s10 += a1; } else { s01 += a0; s11 += a1; }
        }
        #pragma unroll
        for (int o = 1; o <= 2; o <<= 1) {
            s00 += __shfl_xor_sync(~0u, s00, o);
            s01 += __shfl_xor_sync(~0u, s01, o);
            s10 += __shfl_xor_sync(~0u, s10, o);
            s11 += __shfl_xor_sync(~0u, s11, o);
        }
        float n00 = rsqrtf(s00 * (1.f/HD) + 1e-6f), n01 = rsqrtf(s01 * (1.f/HD) + 1e-6f);
        float n10 = rsqrtf(s10 * (1.f/HD) + 1e-6f), n11 = rsqrtf(s11 * (1.f/HD) + 1e-6f);
        #pragma unroll
        for (int fn = 0; fn < 16; fn++) {
            int d0 = (fn & 7) * 8 + c2;
            float w0 = qw[d0], w1 = qw[d0 + 1];
            float f0 = (fn < 8) ? n00 : n01, f1 = (fn < 8) ? n10 : n11;
            acc[fn][0] *= f0 * w0; acc[fn][1] *= f0 * w1;
            acc[fn][2] *= f1 * w0; acc[fn][3] *= f1 * w1;
        }
        float c00 = cosp[t0*8 + c2], c01 = cosp[t0*8 + c2 + 1];
        float sn00 = sinp[t0*8 + c2], sn01 = sinp[t0*8 + c2 + 1];
        float c10 = cosp[t1*8 + c2], c11 = cosp[t1*8 + c2 + 1];
        float sn10 = sinp[t1*8 + c2], sn11 = sinp[t1*8 + c2 + 1];
        #pragma unroll
        for (int hp = 0; hp < 2; hp++) {
            int f1i = hp * 8 + 6, f2i = f1i + 1;
            float x10 = acc[f1i][0], x11 = acc[f1i][1], x12 = acc[f1i][2], x13 = acc[f1i][3];
            float x20 = acc[f2i][0], x21 = acc[f2i][1], x22 = acc[f2i][2], x23 = acc[f2i][3];
            acc[f1i][0] = x10*c00 - x20*sn00; acc[f1i][1] = x11*c01 - x21*sn01;
            acc[f1i][2] = x12*c10 - x22*sn10; acc[f1i][3] = x13*c11 - x23*sn11;
            acc[f2i][0] = x20*c00 + x10*sn00; acc[f2i][1] = x21*c01 + x11*sn01;
            acc[f2i][2] = x22*c10 + x12*sn10; acc[f2i][3] = x23*c11 + x13*sn11;
        }
        #pragma unroll
        for (int fn = 0; fn < 16; fn++) {
            #pragma unroll
            for (int e = 0; e < 4; e++) acc[fn][e] *= QSCALE;
        }
        #pragma unroll
        for (int fn = 0; fn < 16; fn++) {
            int hg = (n0 >> 6) + (fn >> 3);
            int d  = (fn & 7) * 8 + c2;
            size_t a0 = (((size_t)(b * NH + hg)) * TT + t0) * HD + d;
            size_t a1 = (((size_t)(b * NH + hg)) * TT + t1) * HD + d;
            *(uint32_t*)(g_qh + a0) = packh(acc[fn][0], acc[fn][1]);
            *(uint32_t*)(g_ql + a0) = pack_lo_resid(acc[fn][0], acc[fn][1]);
            *(uint32_t*)(g_qh + a1) = packh(acc[fn][2], acc[fn][3]);
            *(uint32_t*)(g_ql + a1) = pack_lo_resid(acc[fn][2], acc[fn][3]);
        }
    } else if (blockIdx.x == 8) {
        float s0 = 0, s1 = 0;
        #pragma unroll
        for (int fn = 0; fn < 16; fn++) {
            s0 += acc[fn][0]*acc[fn][0] + acc[fn][1]*acc[fn][1];
            s1 += acc[fn][2]*acc[fn][2] + acc[fn][3]*acc[fn][3];
        }
        #pragma unroll
        for (int o = 1; o <= 2; o <<= 1) {
            s0 += __shfl_xor_sync(~0u, s0, o);
            s1 += __shfl_xor_sync(~0u, s1, o);
        }
        float n0f = rsqrtf(s0 * (1.f/RR) + 1e-6f), n1f = rsqrtf(s1 * (1.f/RR) + 1e-6f);
        #pragma unroll
        for (int fn = 0; fn < 16; fn++) {
            int r = fn * 8 + c2;
            float w0 = kvaw[r], w1 = kvaw[r + 1];
            *(uint32_t*)(g_lth + (size_t)bt0 * RR + r) =
                packh(acc[fn][0] * n0f * w0, acc[fn][1] * n0f * w1);
            *(uint32_t*)(g_lth + (size_t)bt1 * RR + r) =
                packh(acc[fn][2] * n1f * w0, acc[fn][3] * n1f * w1);
        }
    } else {
        float c00 = cosp[t0*8 + c2], c01 = cosp[t0*8 + c2 + 1];
        float sn00 = sinp[t0*8 + c2], sn01 = sinp[t0*8 + c2 + 1];
        float c10 = cosp[t1*8 + c2], c11 = cosp[t1*8 + c2 + 1];
        float sn10 = sinp[t1*8 + c2], sn11 = sinp[t1*8 + c2 + 1];
        float x10 = acc[0][0], x11 = acc[0][1], x12 = acc[0][2], x13 = acc[0][3];
        float x20 = acc[1][0], x21 = acc[1][1], x22 = acc[1][2], x23 = acc[1][3];
        float o10 = x10*c00 - x20*sn00, o11 = x11*c01 - x21*sn01;
        float o12 = x12*c10 - x22*sn10, o13 = x13*c11 - x23*sn11;
        float o20 = x20*c00 + x10*sn00, o21 = x21*c01 + x11*sn01;
        float o22 = x22*c10 + x12*sn10, o23 = x23*c11 + x13*sn11;
        uint32_t h1a = packh(o10, o11), l1a = pack_lo_resid(o10, o11);
        uint32_t h1b = packh(o12, o13), l1b = pack_lo_resid(o12, o13);
        uint32_t h2a = packh(o20, o21), l2a = pack_lo_resid(o20, o21);
        uint32_t h2b = packh(o22, o23), l2b = pack_lo_resid(o22, o23);
        #pragma unroll
        for (int h = 0; h < NH; h++) {
            size_t a0 = (((size_t)(b * NH + h)) * TT + t0) * HD + 48 + c2;
            size_t a1 = (((size_t)(b * NH + h)) * TT + t1) * HD + 48 + c2;
            *(uint32_t*)(g_kh + a0)     = h1a; *(uint32_t*)(g_kl + a0)     = l1a;
            *(uint32_t*)(g_kh + a0 + 8) = h2a; *(uint32_t*)(g_kl + a0 + 8) = l2a;
            *(uint32_t*)(g_kh + a1)     = h1b; *(uint32_t*)(g_kl + a1)     = l1b;
            *(uint32_t*)(g_kh + a1 + 8) = h2b; *(uint32_t*)(g_kl + a1 + 8) = l2b;
        }
    }
}

// ======================= kvb GEMM with fused scatter =======================
__global__ __launch_bounds__(256, 2) void kvb_gemm()
{
    extern __shared__ __align__(16) char smem[];
    const int tid = threadIdx.x, wid = tid >> 5, lane = tid & 31;
    const int warp_m = wid >> 2, warp_n = wid & 3;
    const int m0 = blockIdx.y * 128, n0 = blockIdx.x * 128;
    uint32_t smem_base = smem_u32(smem);

    const char* base[3] = { (const char*)(g_lth + (size_t)m0 * RR),
                            (const char*)(g_Wbh + (size_t)n0 * RR),
                            (const char*)(g_Wbl + (size_t)n0 * RR) };
    const size_t ldbytes = (size_t)RR * 2;
    const int nch = RR >> 5;

    const int lm = lane & 15, lh = lane >> 4;
    const int g = lane >> 3, r = lane & 7;
    const int r4 = lane >> 2, c2 = (lane & 3) * 2;

    float acc[4][4][4];
    #pragma unroll
    for (int i = 0; i < 4; i++)
        #pragma unroll
        for (int j = 0; j < 4; j++)
            #pragma unroll
            for (int e = 0; e < 4; e++) acc[i][j][e] = 0.f;

    GEMM_LOAD_CHUNK(0, 0);
    GEMM_LOAD_CHUNK(1, 1);

    for (int ch = 0; ch < nch; ch++) {
        asm volatile("cp.async.wait_group 1;");
        __syncthreads();
        if (ch + 2 < nch) { GEMM_LOAD_CHUNK(ch + 2, (ch + 2) % NSTAGE); }
        else asm volatile("cp.async.commit_group;");
        const uint32_t smA  = smem_base + (ch % NSTAGE) * GBUF_B;
        const uint32_t smBh = smA + GTILE_B;
        const uint32_t smBl = smBh + GTILE_B;
        #pragma unroll
        for (int k16 = 0; k16 < 2; k16++) {
            uint32_t a[4][4];
            #pragma unroll
            for (int fm = 0; fm < 4; fm++)
                ldsm4(a[fm], smA + ((warp_m * 64 + fm * 16 + lm) * GPAD
                                    + k16 * 16 + lh * 8) * 2);
            uint32_t bh[4][2], bl[4][2];
            #pragma unroll
            for (int fp = 0; fp < 2; fp++) {
                int row = warp_n * 32 + fp * 16 + ((g >> 1) << 3) + r;
                int off = (row * GPAD + (g & 1) * 8 + k16 * 16) * 2;
                uint32_t t4[4];
                ldsm4(t4, smBh + off);
                bh[fp*2][0]=t4[0]; bh[fp*2][1]=t4[1]; bh[fp*2+1][0]=t4[2]; bh[fp*2+1][1]=t4[3];
                ldsm4(t4, smBl + off);
                bl[fp*2][0]=t4[0]; bl[fp*2][1]=t4[1]; bl[fp*2+1][0]=t4[2]; bl[fp*2+1][1]=t4[3];
            }
            #pragma unroll
            for (int fm = 0; fm < 4; fm++)
                #pragma unroll
                for (int fn = 0; fn < 4; fn++) {
                    mma16816(acc[fm][fn], a[fm], bh[fn]);
                    mma16816(acc[fm][fn], a[fm], bl[fn]);
                }
        }
    }

    #pragma unroll
    for (int fm = 0; fm < 4; fm++) {
        int bt0 = m0 + warp_m * 64 + fm * 16 + r4;
        int bt1 = bt0 + 8;
        int t0 = bt0 & (TT - 1), t1 = bt1 & (TT - 1);
        int b  = bt0 >> 11;
        #pragma unroll
        for (int fn = 0; fn < 4; fn++) {
            int n = n0 + warp_n * 32 + fn * 8 + c2;
            int h = n / 112, rr2 = n % 112;
            size_t hb = (size_t)(b * NH + h) * TT;
            if (rr2 < NOPE) {
                size_t a0 = (hb + t0) * HD + rr2, a1 = (hb + t1) * HD + rr2;
                *(uint32_t*)(g_kh + a0) = packh(acc[fm][fn][0], acc[fm][fn][1]);
                *(uint32_t*)(g_kl + a0) = pack_lo_resid(acc[fm][fn][0], acc[fm][fn][1]);
                *(uint32_t*)(g_kh + a1) = packh(acc[fm][fn][2], acc[fm][fn][3]);
                *(uint32_t*)(g_kl + a1) = pack_lo_resid(acc[fm][fn][2], acc[fm][fn][3]);
            } else {
                int d = rr2 - NOPE;
                size_t a0 = (hb + t0) * VD + d, a1 = (hb + t1) * VD + d;
                *(uint32_t*)(g_vh + a0) = packh(acc[fm][fn][0], acc[fm][fn][1]);
                *(uint32_t*)(g_vh + a1) = packh(acc[fm][fn][2], acc[fm][fn][3]);
            }
        }
    }
}

// ======================= Wo GEMM (single-term fp16 B) =======================
__global__ __launch_bounds__(256, 2) void wo_gemm(float* __restrict__ C)
{
    extern __shared__ __align__(16) char smem[];
    const int tid = threadIdx.x, wid = tid >> 5, lane = tid & 31;
    const int warp_m = wid >> 2, warp_n = wid & 3;
    const int m0 = blockIdx.y * 128, n0 = blockIdx.x * 128;
    uint32_t smem_base = smem_u32(smem);

    const char* base[2] = { (const char*)(g_aoh + (size_t)m0 * DD),
                            (const char*)(g_Woh + (size_t)n0 * DD) };
    const size_t ldbytes = (size_t)DD * 2;
    const int nch = DD >> 5;

    const int lm = lane & 15, lh = lane >> 4;
    const int g = lane >> 3, r = lane & 7;

    float acc[4][4][4];
    #pragma unroll
    for (int i = 0; i < 4; i++)
        #pragma unroll
        for (int j = 0; j < 4; j++)
            #pragma unroll
            for (int e = 0; e < 4; e++) acc[i][j][e] = 0.f;

    GEMM_LOAD_CHUNK2(0, 0);
    GEMM_LOAD_CHUNK2(1, 1);

    for (int ch = 0; ch < nch; ch++) {
        asm volatile("cp.async.wait_group 1;");
        __syncthreads();
        if (ch + 2 < nch) { GEMM_LOAD_CHUNK2(ch + 2, (ch + 2) % NSTAGE); }
        else asm volatile("cp.async.commit_group;");
        const uint32_t smA  = smem_base + (ch % NSTAGE) * GBUF2_B;
        const uint32_t smBh = smA + GTILE_B;
        #pragma unroll
        for (int k16 = 0; k16 < 2; k16++) {
            uint32_t a[4][4];
            #pragma unroll
            for (int fm = 0; fm < 4; fm++)
                ldsm4(a[fm], smA + ((warp_m * 64 + fm * 16 + lm) * GPAD
                                    + k16 * 16 + lh * 8) * 2);
            uint32_t bh[4][2];
            #pragma unroll
            for (int fp = 0; fp < 2; fp++) {
                int row = warp_n * 32 + fp * 16 + ((g >> 1) << 3) + r;
                int off = (row * GPAD + (g & 1) * 8 + k16 * 16) * 2;
                uint32_t t4[4];
                ldsm4(t4, smBh + off);
                bh[fp*2][0]=t4[0]; bh[fp*2][1]=t4[1]; bh[fp*2+1][0]=t4[2]; bh[fp*2+1][1]=t4[3];
            }
            #pragma unroll
            for (int fm = 0; fm < 4; fm++)
                #pragma unroll
                for (int fn = 0; fn < 4; fn++)
                    mma16816(acc[fm][fn], a[fm], bh[fn]);
        }
    }

    const int r4 = lane >> 2, c2 = (lane & 3) * 2;
    #pragma unroll
    for (int fm = 0; fm < 4; fm++) {
        #pragma unroll
        for (int fn = 0; fn < 4; fn++) {
            int m = m0 + warp_m * 64 + fm * 16 + r4;
            int n = n0 + warp_n * 32 + fn * 8 + c2;
            *(float2*)&C[(size_t)m * DD + n] = make_float2(acc[fm][fn][0], acc[fm][fn][1]);
            *(float2*)&C[(size_t)(m + 8) * DD + n] = make_float2(acc[fm][fn][2], acc[fm][fn][3]);
        }
    }
}

// ---------------- flash attention: paired q-tiles, single balanced wave ----------------
#define FPAD 72
#define FQLO (3 * 64 * FPAD)

__global__ __launch_bounds__(256, 2) void flash_mma()
{
    __shared__ __align__(16) __half sm[FQLO + 128 * FPAD];

    const int tid = threadIdx.x, wid = tid >> 5, lane = tid & 31;
    const int bh = blockIdx.y;
    const int b = bh >> 4, h = bh & (NH - 1);
    const uint32_t sb = smem_u32(sm);

    const int lm = lane & 15, lh = lane >> 4;
    const int g = lane >> 3, r8 = lane & 7;
    const int r4 = lane >> 2, c2 = (lane & 3) * 2;

    const __half* khb = g_kh + (size_t)bh * TT * HD;
    const __half* klb = g_kl + (size_t)bh * TT * HD;
    const __half* vhb = g_vh + (size_t)bh * TT * VD;

    const uint32_t oKl = 64 * FPAD * 2;
    const uint32_t oVh = 2 * 64 * FPAD * 2;
    const uint32_t qlo_addr = sb + (FQLO + (wid * 16 + lm) * FPAD + lh * 8) * 2;
    const int npairs = TT / 128 - 1;   // 15

    #pragma unroll 1
    for (int ph = 0; ph < 2; ph++) {
        const int qtile = ph ? (int)blockIdx.x : (npairs - (int)blockIdx.x);
        const int qb = qtile * 128;

        __syncthreads();
        {
            const __half* qhp = g_qh + ((size_t)bh * TT + qb) * HD;
            const __half* qlp = g_ql + ((size_t)bh * TT + qb) * HD;
            for (int i = tid; i < 128 * 8; i += 256) {
                int r = i >> 3, s = i & 7;
                *(uint4*)(sm + r * FPAD + s * 8) = *(const uint4*)(qhp + r * 64 + s * 8);
                *(uint4*)(sm + FQLO + r * FPAD + s * 8) = *(const uint4*)(qlp + r * 64 + s * 8);
            }
        }
        __syncthreads();

        uint32_t qh[4][4];
        #pragma unroll
        for (int ks = 0; ks < 4; ks++)
            ldsm4(qh[ks], sb + ((wid * 16 + lm) * FPAD + ks * 16 + lh * 8) * 2);

        float o[8][4];
        #pragma unroll
        for (int i = 0; i < 8; i++)
            #pragma unroll
            for (int e = 0; e < 4; e++) o[i][e] = 0.f;
        float mrow[2] = { -1e30f, -1e30f };
        float lsum[2] = { 0.f, 0.f };

        const int ntiles = qtile * 2 + 2;
        const int q0 = qb + wid * 16 + r4;
        const int q1 = q0 + 8;

        for (int it = 0; it < ntiles; it++) {
            const int j0 = it * 64;
            __syncthreads();
            for (int i = tid; i < 64 * 8; i += 256) {
                int r = i >> 3, s = i & 7;
                size_t gsrc = (size_t)(j0 + r) * 64 + s * 8;
                int dsh = r * FPAD + s * 8;
                *(uint4*)(sm + dsh) = *(const uint4*)(khb + gsrc);
                *(uint4*)(sm + 64 * FPAD + dsh) = *(const uint4*)(klb + gsrc);
                *(uint4*)(sm + 2 * 64 * FPAD + dsh) = *(const uint4*)(vhb + gsrc);
            }
            __syncthreads();

            float s[8][4];
            #pragma unroll
            for (int i = 0; i < 8; i++)
                #pragma unroll
                for (int e = 0; e < 4; e++) s[i][e] = 0.f;

            #pragma unroll
            for (int ks = 0; ks < 4; ks++) {
                uint32_t qlf[4];
                ldsm4(qlf, qlo_addr + ks * 32);
                #pragma unroll
                for (int fp = 0; fp < 4; fp++) {
                    const int krow = fp * 16 + ((g >> 1) << 3) + r8;
                    uint32_t addr = sb + (krow * FPAD + (g & 1) * 8 + ks * 16) * 2;
                    uint32_t bhf[4], blf[4];
                    ldsm4(bhf, addr);
                    ldsm4(blf, addr + oKl);
                    mma16816(s[fp*2],   qh[ks], bhf);
                    mma16816(s[fp*2],   qh[ks], blf);
                    mma16816(s[fp*2],   qlf,    bhf);
                    mma16816(s[fp*2+1], qh[ks], bhf + 2);
                    mma16816(s[fp*2+1], qh[ks], blf + 2);
                    mma16816(s[fp*2+1], qlf,    bhf + 2);
                }
            }

            const bool need_mask = (it >= ntiles - 2);
            if (need_mask) {
                #pragma unroll
                for (int fn = 0; fn < 8; fn++) {
                    #pragma unroll
                    for (int e = 0; e < 4; e++) {
                        int kv = j0 + fn * 8 + c2 + (e & 1);
                        int qq = (e < 2) ? q0 : q1;
                        if (kv > qq) s[fn][e] = -1e30f;
                    }
                }
            }

            float tm0 = -1e30f, tm1 = -1e30f;
            #pragma unroll
            for (int fn = 0; fn < 8; fn++) {
                tm0 = fmaxf(tm0, fmaxf(s[fn][0], s[fn][1]));
                tm1 = fmaxf(tm1, fmaxf(s[fn][2], s[fn][3]));
            }
            tm0 = fmaxf(tm0, __shfl_xor_sync(~0u, tm0, 1));
            tm0 = fmaxf(tm0, __shfl_xor_sync(~0u, tm0, 2));
            tm1 = fmaxf(tm1, __shfl_xor_sync(~0u, tm1, 1));
            tm1 = fmaxf(tm1, __shfl_xor_sync(~0u, tm1, 2));

            float mn0 = fmaxf(mrow[0], tm0), mn1 = fmaxf(mrow[1], tm1);
            float cr0 = exp2f(mrow[0] - mn0), cr1 = exp2f(mrow[1] - mn1);
            mrow[0] = mn0; mrow[1] = mn1;
            lsum[0] *= cr0; lsum[1] *= cr1;
            #pragma unroll
            for (int fn = 0; fn < 8; fn++) {
                o[fn][0] *= cr0; o[fn][1] *= cr0;
                o[fn][2] *= cr1; o[fn][3] *= cr1;
            }

            #pragma unroll
            for (int fn = 0; fn < 8; fn++) {
                s[fn][0] = exp2f(s[fn][0] - mn0);
                s[fn][1] = exp2f(s[fn][1] - mn0);
                s[fn][2] = exp2f(s[fn][2] - mn1);
                s[fn][3] = exp2f(s[fn][3] - mn1);
                lsum[0] += s[fn][0] + s[fn][1];
                lsum[1] += s[fn][2] + s[fn][3];
            }

            #pragma unroll
            for (int ks = 0; ks < 4; ks++) {
                uint32_t aph[4], apl[4];
                aph[0] = packh(s[ks*2][0], s[ks*2][1]);
                aph[1] = packh(s[ks*2][2], s[ks*2][3]);
                aph[2] = packh(s[ks*2+1][0], s[ks*2+1][1]);
                aph[3] = packh(s[ks*2+1][2], s[ks*2+1][3]);
                apl[0] = pack_lo_resid(s[ks*2][0], s[ks*2][1]);
                apl[1] = pack_lo_resid(s[ks*2][2], s[ks*2][3]);
                apl[2] = pack_lo_resid(s[ks*2+1][0], s[ks*2+1][1]);
                apl[3] = pack_lo_resid(s[ks*2+1][2], s[ks*2+1][3]);

                const int vrow = ks * 16 + (g & 1) * 8 + r8;
                #pragma unroll
                for (int np = 0; np < 4; np++) {
                    const int vcol = np * 16 + lh * 8;
                    uint32_t addr = sb + oVh + (vrow * FPAD + vcol) * 2;
                    uint32_t bvh[4];
                    ldsm4t(bvh, addr);
                    mma16816(o[np*2],   aph, bvh);
                    mma16816(o[np*2],   apl, bvh);
                    mma16816(o[np*2+1], aph, bvh + 2);
                    mma16816(o[np*2+1], apl, bvh + 2);
                }
            }
        }

        lsum[0] += __shfl_xor_sync(~0u, lsum[0], 1);
        lsum[0] += __shfl_xor_sync(~0u, lsum[0], 2);
        lsum[1] += __shfl_xor_sync(~0u, lsum[1], 1);
        lsum[1] += __shfl_xor_sync(~0u, lsum[1], 2);
        const float inv0 = 1.f / lsum[0], inv1 = 1.f / lsum[1];

        __half* ob0 = g_aoh + ((size_t)(b * TT + q0)) * (NH * VD) + h * VD;
        __half* ob1 = g_aoh + ((size_t)(b * TT + q1)) * (NH * VD) + h * VD;
        #pragma unroll
        for (int fn = 0; fn < 8; fn++) {
            *(uint32_t*)(ob0 + fn * 8 + c2) = packh(o[fn][0] * inv0, o[fn][1] * inv0);
            *(uint32_t*)(ob1 + fn * 8 + c2) = packh(o[fn][2] * inv1, o[fn][3] * inv1);
        }
    }
}

// ---------------- launch ----------------
extern "C" void kernel_launch(void* const* d_in, const int* in_sizes, int n_in,
                              void* d_out, int out_size)
{
    const float* x    = (const float*)d_in[0];
    const float* cosp = (const float*)d_in[1];
    const float* sinp = (const float*)d_in[2];
    const float* Wq   = (const float*)d_in[3];
    const float* qw   = (const float*)d_in[4];
    const float* Wkva = (const float*)d_in[5];
    const float* kvaw = (const float*)d_in[6];
    const float* Wkvb = (const float*)d_in[7];
    const float* Wo   = (const float*)d_in[8];
    float* out = (float*)d_out;

    cudaFuncSetAttribute(proj1_gemm, cudaFuncAttributeMaxDynamicSharedMemorySize, NSTAGE * GBUF_B);
    cudaFuncSetAttribute(kvb_gemm,   cudaFuncAttributeMaxDynamicSharedMemorySize, NSTAGE * GBUF_B);
    cudaFuncSetAttribute(wo_gemm,    cudaFuncAttributeMaxDynamicSharedMemorySize, NSTAGE * GBUF2_B);

    cvt_all<<<(QTOT + 255) / 256, 256>>>(x, Wq, Wkva, Wkvb, Wo);

    {
        dim3 g(W1_ROWS / 128, MTOT / 128);
        proj1_gemm<<<g, 256, NSTAGE * GBUF_B>>>(cosp, sinp, qw, kvaw);
    }
    {
        dim3 g(KVB_N / 128, MTOT / 128);
        kvb_gemm<<<g, 256, NSTAGE * GBUF_B>>>();
    }
    {
        dim3 g(TT / 256, BB * NH);
        flash_mma<<<g, 256>>>();
    }
    {
        dim3 g(DD / 128, MTOT / 128);
        wo_gemm<<<g, 256, NSTAGE * GBUF2_B>>>(out);
    }
}

// round 16
// speedup vs baseline: 1.3642x; 1.0811x over previous
#include <cuda_runtime.h>
#include <cuda_fp16.h>
#include <math.h>
#include <cstdint>

#define BB 2
#define TT 2048
#define DD 1024
#define NH 16
#define HD 64      // NOPE_D + ROPE_D
#define NOPE 48
#define ROPED 16
#define RR 128
#define VD 64
#define KVB_N (NH * (NOPE + VD))   // 1792
#define MTOT (BB * TT)             // 4096
#define W1_ROWS 1280               // 1024 (Wq) + 128 (latent) + 16 (rope) + 112 pad
#define QSCALE 0.18033688011112042f   // 0.125 * log2(e)

// ---------------- device scratch ----------------
__device__ __align__(256) __half g_qh[BB*NH*TT*HD], g_ql[BB*NH*TT*HD];
__device__ __align__(256) __half g_kh[BB*NH*TT*HD];
__device__ __align__(256) __half g_vh[BB*NH*TT*VD];

__device__ __align__(256) __half g_xh [MTOT * DD];
__device__ __align__(256) __half g_W1h[W1_ROWS * DD], g_W1l[W1_ROWS * DD];
__device__ __align__(256) __half g_Wbh[KVB_N * RR];
__device__ __align__(256) __half g_Woh[DD * DD];
__device__ __align__(256) __half g_lth[MTOT * RR];
__device__ __align__(256) __half g_aoh[MTOT * DD];

// ======================= helpers =======================
__device__ __forceinline__ uint32_t smem_u32(const void* p) {
    uint32_t a;
    asm("{ .reg .u64 t; cvta.to.shared.u64 t, %1; cvt.u32.u64 %0, t; }" : "=r"(a) : "l"(p));
    return a;
}
__device__ __forceinline__ void mma16816(float* c, const uint32_t* a, const uint32_t* b) {
    asm volatile("mma.sync.aligned.m16n8k16.row.col.f32.f16.f16.f32 "
        "{%0,%1,%2,%3}, {%4,%5,%6,%7}, {%8,%9}, {%0,%1,%2,%3};"
        : "+f"(c[0]), "+f"(c[1]), "+f"(c[2]), "+f"(c[3])
        : "r"(a[0]), "r"(a[1]), "r"(a[2]), "r"(a[3]), "r"(b[0]), "r"(b[1]));
}
__device__ __forceinline__ void ldsm4(uint32_t* r, uint32_t addr) {
    asm volatile("ldmatrix.sync.aligned.m8n8.x4.shared.b16 {%0,%1,%2,%3}, [%4];"
        : "=r"(r[0]), "=r"(r[1]), "=r"(r[2]), "=r"(r[3]) : "r"(addr));
}
__device__ __forceinline__ void ldsm4t(uint32_t* r, uint32_t addr) {
    asm volatile("ldmatrix.sync.aligned.m8n8.x4.trans.shared.b16 {%0,%1,%2,%3}, [%4];"
        : "=r"(r[0]), "=r"(r[1]), "=r"(r[2]), "=r"(r[3]) : "r"(addr));
}
__device__ __forceinline__ uint32_t packh(float lo, float hi) {
    uint32_t d;
    asm("cvt.rn.f16x2.f32 %0, %1, %2;" : "=r"(d) : "f"(hi), "f"(lo));
    return d;
}
__device__ __forceinline__ uint32_t pack_lo_resid(float v0, float v1) {
    float h0 = __half2float(__float2half(v0));
    float h1 = __half2float(__float2half(v1));
    return packh(v0 - h0, v1 - h1);
}

// ======================= fused conversions =======================
#define QX  (MTOT * DD / 4)
#define QW1 (W1_ROWS * DD / 4)
#define QWB (KVB_N * RR / 4)
#define QWO (DD * DD / 4)
#define QTOT (QX + QW1 + QWB + QWO)

__device__ __forceinline__ void do_hl(const float* s, __half* dh, __half* dl, int e) {
    float4 v = *(const float4*)(s + e);
    __half h0 = __float2half(v.x), h1 = __float2half(v.y);
    __half h2 = __float2half(v.z), h3 = __float2half(v.w);
    ((__half2*)(dh + e))[0] = __half2(h0, h1);
    ((__half2*)(dh + e))[1] = __half2(h2, h3);
    ((__half2*)(dl + e))[0] = __half2(__float2half(v.x - __half2float(h0)),
                                      __float2half(v.y - __half2float(h1)));
    ((__half2*)(dl + e))[1] = __half2(__float2half(v.z - __half2float(h2)),
                                      __float2half(v.w - __half2float(h3)));
}
__device__ __forceinline__ void do_h(const float* s, __half* dh, int e) {
    float4 v = *(const float4*)(s + e);
    ((__half2*)(dh + e))[0] = __half2(__float2half(v.x), __float2half(v.y));
    ((__half2*)(dh + e))[1] = __half2(__float2half(v.z), __float2half(v.w));
}

__global__ __launch_bounds__(256) void cvt_all(
    const float* __restrict__ x,    const float* __restrict__ Wq,
    const float* __restrict__ Wkva, const float* __restrict__ Wkvb,
    const float* __restrict__ Wo)
{
    int qi = blockIdx.x * blockDim.x + threadIdx.x;
    if (qi >= QTOT) return;
    if (qi < QX) { do_h(x, g_xh, qi * 4); return; }
    qi -= QX;
    if (qi < QW1) {
        int e = qi * 4;
        if (e < DD * DD) { do_hl(Wq, g_W1h, g_W1l, e); }
        else if (e < (DD + 144) * DD) {
            float4 v = *(const float4*)(Wkva + (e - DD * DD));
            __half h0 = __float2half(v.x), h1 = __float2half(v.y);
            __half h2 = __float2half(v.z), h3 = __float2half(v.w);
            ((__half2*)(g_W1h + e))[0] = __half2(h0, h1);
            ((__half2*)(g_W1h + e))[1] = __half2(h2, h3);
            ((__half2*)(g_W1l + e))[0] = __half2(__float2half(v.x - __half2float(h0)),
                                                 __float2half(v.y - __half2float(h1)));
            ((__half2*)(g_W1l + e))[1] = __half2(__float2half(v.z - __half2float(h2)),
                                                 __float2half(v.w - __half2float(h3)));
        } else {
            __half2 z(__half(0.f), __half(0.f));
            ((__half2*)(g_W1h + e))[0] = z; ((__half2*)(g_W1h + e))[1] = z;
            ((__half2*)(g_W1l + e))[0] = z; ((__half2*)(g_W1l + e))[1] = z;
        }
        return;
    }
    qi -= QW1;
    if (qi < QWB) { do_h(Wkvb, g_Wbh, qi * 4); return; }   // hi only (k/v fp16 floor)
    qi -= QWB;
    do_h(Wo, g_Woh, qi * 4);                               // hi only (last stage)
}

// ======================= shared GEMM plumbing =======================
#define GPAD 40
#define GTILE_B (128 * GPAD * 2)
#define GBUF_B  (3 * GTILE_B)
#define NSTAGE 3

#define GEMM_LOAD_CHUNK(ch, buf)                                               \
    do {                                                                       \
        const int k0b = ((ch) << 5) * 2;                                       \
        _Pragma("unroll")                                                      \
        for (int it = 0; it < 6; it++) {                                       \
            int i = tid + it * 256;                                            \
            int mat = i >> 9, rem = i & 511;                                   \
            int row = rem >> 2, seg = rem & 3;                                 \
            const char* src = base[mat] + (size_t)row * ldbytes + k0b + seg * 16; \
            uint32_t dst = smem_base + (buf) * GBUF_B + mat * GTILE_B          \
                         + (row * GPAD + seg * 8) * 2;                         \
            asm volatile("cp.async.cg.shared.global [%0], [%1], 16;" :: "r"(dst), "l"(src)); \
        }                                                                      \
        asm volatile("cp.async.commit_group;");                                \
    } while (0)

#define GBUF2_B (2 * GTILE_B)
#define GEMM_LOAD_CHUNK2(ch, buf)                                              \
    do {                                                                       \
        const int k0b = ((ch) << 5) * 2;                                       \
        _Pragma("unroll")                                                      \
        for (int it = 0; it < 4; it++) {                                       \
            int i = tid + it * 256;                                            \
            int mat = i >> 9, rem = i & 511;                                   \
            int row = rem >> 2, seg = rem & 3;                                 \
            const char* src = base[mat] + (size_t)row * ldbytes + k0b + seg * 16; \
            uint32_t dst = smem_base + (buf) * GBUF2_B + mat * GTILE_B         \
                         + (row * GPAD + seg * 8) * 2;                         \
            asm volatile("cp.async.cg.shared.global [%0], [%1], 16;" :: "r"(dst), "l"(src)); \
        }                                                                      \
        asm volatile("cp.async.commit_group;");                                \
    } while (0)

// ======================= proj1 =======================
__global__ __launch_bounds__(256, 2) void proj1_gemm(
    const float* __restrict__ cosp, const float* __restrict__ sinp,
    const float* __restrict__ qw,   const float* __restrict__ kvaw)
{
    extern __shared__ __align__(16) char smem[];
    const int tid = threadIdx.x, wid = tid >> 5, lane = tid & 31;
    const int m0 = blockIdx.y * 128, n0 = blockIdx.x * 128;
    uint32_t smem_base = smem_u32(smem);

    const char* base[3] = { (const char*)(g_xh  + (size_t)m0 * DD),
                            (const char*)(g_W1h + (size_t)n0 * DD),
                            (const char*)(g_W1l + (size_t)n0 * DD) };
    const size_t ldbytes = (size_t)DD * 2;
    const int nch = DD >> 5;

    const int lm = lane & 15, lh = lane >> 4;
    const int g = lane >> 3, r8 = lane & 7;
    const int r4 = lane >> 2, c2 = (lane & 3) * 2;

    float acc[16][4];
    #pragma unroll
    for (int i = 0; i < 16; i++)
        #pragma unroll
        for (int e = 0; e < 4; e++) acc[i][e] = 0.f;

    GEMM_LOAD_CHUNK(0, 0);
    GEMM_LOAD_CHUNK(1, 1);

    for (int ch = 0; ch < nch; ch++) {
        asm volatile("cp.async.wait_group 1;");
        __syncthreads();
        if (ch + 2 < nch) { GEMM_LOAD_CHUNK(ch + 2, (ch + 2) % NSTAGE); }
        else asm volatile("cp.async.commit_group;");
        const uint32_t smA  = smem_base + (ch % NSTAGE) * GBUF_B;
        const uint32_t smBh = smA + GTILE_B;
        const uint32_t smBl = smBh + GTILE_B;
        #pragma unroll
        for (int k16 = 0; k16 < 2; k16++) {
            uint32_t a[4];
            ldsm4(a, smA + ((wid * 16 + lm) * GPAD + k16 * 16 + lh * 8) * 2);
            #pragma unroll
            for (int fp = 0; fp < 8; fp++) {
                int row = fp * 16 + ((g >> 1) << 3) + r8;
                int off = (row * GPAD + (g & 1) * 8 + k16 * 16) * 2;
                uint32_t t4[4];
                ldsm4(t4, smBh + off);
                mma16816(acc[fp*2],   a, t4);
                mma16816(acc[fp*2+1], a, t4 + 2);
                ldsm4(t4, smBl + off);
                mma16816(acc[fp*2],   a, t4);
                mma16816(acc[fp*2+1], a, t4 + 2);
            }
        }
    }

    const int bt0 = m0 + wid * 16 + r4;
    const int bt1 = bt0 + 8;
    const int t0 = bt0 & (TT - 1), t1 = bt1 & (TT - 1);
    const int b  = bt0 >> 11;

    if (blockIdx.x < 8) {
        float s00 = 0, s01 = 0, s10 = 0, s11 = 0;
        #pragma unroll
        for (int fn = 0; fn < 16; fn++) {
            float a0 = acc[fn][0]*acc[fn][0] + acc[fn][1]*acc[fn][1];
            float a1 = acc[fn][2]*acc[fn][2] + acc[fn][3]*acc[fn][3];
            if (fn < 8) { s00 += a0; s10 += a1; } else { s01 += a0; s11 += a1; }
        }
        #pragma unroll
        for (int o = 1; o <= 2; o <<= 1) {
            s00 += __shfl_xor_sync(~0u, s00, o);
            s01 += __shfl_xor_sync(~0u, s01, o);
            s10 += __shfl_xor_sync(~0u, s10, o);
            s11 += __shfl_xor_sync(~0u, s11, o);
        }
        float n00 = rsqrtf(s00 * (1.f/HD) + 1e-6f), n01 = rsqrtf(s01 * (1.f/HD) + 1e-6f);
        float n10 = rsqrtf(s10 * (1.f/HD) + 1e-6f), n11 = rsqrtf(s11 * (1.f/HD) + 1e-6f);
        #pragma unroll
        for (int fn = 0; fn < 16; fn++) {
            int d0 = (fn & 7) * 8 + c2;
            float w0 = qw[d0], w1 = qw[d0 + 1];
            float f0 = (fn < 8) ? n00 : n01, f1 = (fn < 8) ? n10 : n11;
            acc[fn][0] *= f0 * w0; acc[fn][1] *= f0 * w1;
            acc[fn][2] *= f1 * w0; acc[fn][3] *= f1 * w1;
        }
        float c00 = cosp[t0*8 + c2], c01 = cosp[t0*8 + c2 + 1];
        float sn00 = sinp[t0*8 + c2], sn01 = sinp[t0*8 + c2 + 1];
        float c10 = cosp[t1*8 + c2], c11 = cosp[t1*8 + c2 + 1];
        float sn10 = sinp[t1*8 + c2], sn11 = sinp[t1*8 + c2 + 1];
        #pragma unroll
        for (int hp = 0; hp < 2; hp++) {
            int f1i = hp * 8 + 6, f2i = f1i + 1;
            float x10 = acc[f1i][0], x11 = acc[f1i][1], x12 = acc[f1i][2], x13 = acc[f1i][3];
            float x20 = acc[f2i][0], x21 = acc[f2i][1], x22 = acc[f2i][2], x23 = acc[f2i][3];
            acc[f1i][0] = x10*c00 - x20*sn00; acc[f1i][1] = x11*c01 - x21*sn01;
            acc[f1i][2] = x12*c10 - x22*sn10; acc[f1i][3] = x13*c11 - x23*sn11;
            acc[f2i][0] = x20*c00 + x10*sn00; acc[f2i][1] = x21*c01 + x11*sn01;
            acc[f2i][2] = x22*c10 + x12*sn10; acc[f2i][3] = x23*c11 + x13*sn11;
        }
        #pragma unroll
        for (int fn = 0; fn < 16; fn++) {
            #pragma unroll
            for (int e = 0; e < 4; e++) acc[fn][e] *= QSCALE;
        }
        #pragma unroll
        for (int fn = 0; fn < 16; fn++) {
            int hg = (n0 >> 6) + (fn >> 3);
            int d  = (fn & 7) * 8 + c2;
            size_t a0 = (((size_t)(b * NH + hg)) * TT + t0) * HD + d;
            size_t a1 = (((size_t)(b * NH + hg)) * TT + t1) * HD + d;
            *(uint32_t*)(g_qh + a0) = packh(acc[fn][0], acc[fn][1]);
            *(uint32_t*)(g_ql + a0) = pack_lo_resid(acc[fn][0], acc[fn][1]);
            *(uint32_t*)(g_qh + a1) = packh(acc[fn][2], acc[fn][3]);
            *(uint32_t*)(g_ql + a1) = pack_lo_resid(acc[fn][2], acc[fn][3]);
        }
    } else if (blockIdx.x == 8) {
        float s0 = 0, s1 = 0;
        #pragma unroll
        for (int fn = 0; fn < 16; fn++) {
            s0 += acc[fn][0]*acc[fn][0] + acc[fn][1]*acc[fn][1];
            s1 += acc[fn][2]*acc[fn][2] + acc[fn][3]*acc[fn][3];
        }
        #pragma unroll
        for (int o = 1; o <= 2; o <<= 1) {
            s0 += __shfl_xor_sync(~0u, s0, o);
            s1 += __shfl_xor_sync(~0u, s1, o);
        }
        float n0f = rsqrtf(s0 * (1.f/RR) + 1e-6f), n1f = rsqrtf(s1 * (1.f/RR) + 1e-6f);
        #pragma unroll
        for (int fn = 0; fn < 16; fn++) {
            int r = fn * 8 + c2;
            float w0 = kvaw[r], w1 = kvaw[r + 1];
            *(uint32_t*)(g_lth + (size_t)bt0 * RR + r) =
                packh(acc[fn][0] * n0f * w0, acc[fn][1] * n0f * w1);
            *(uint32_t*)(g_lth + (size_t)bt1 * RR + r) =
                packh(acc[fn][2] * n1f * w0, acc[fn][3] * n1f * w1);
        }
    } else {
        float c00 = cosp[t0*8 + c2], c01 = cosp[t0*8 + c2 + 1];
        float sn00 = sinp[t0*8 + c2], sn01 = sinp[t0*8 + c2 + 1];
        float c10 = cosp[t1*8 + c2], c11 = cosp[t1*8 + c2 + 1];
        float sn10 = sinp[t1*8 + c2], sn11 = sinp[t1*8 + c2 + 1];
        float x10 = acc[0][0], x11 = acc[0][1], x12 = acc[0][2], x13 = acc[0][3];
        float x20 = acc[1][0], x21 = acc[1][1], x22 = acc[1][2], x23 = acc[1][3];
        float o10 = x10*c00 - x20*sn00, o11 = x11*c01 - x21*sn01;
        float o12 = x12*c10 - x22*sn10, o13 = x13*c11 - x23*sn11;
        float o20 = x20*c00 + x10*sn00, o21 = x21*c01 + x11*sn01;
        float o22 = x22*c10 + x12*sn10, o23 = x23*c11 + x13*sn11;
        uint32_t h1a = packh(o10, o11);
        uint32_t h1b = packh(o12, o13);
        uint32_t h2a = packh(o20, o21);
        uint32_t h2b = packh(o22, o23);
        #pragma unroll
        for (int h = 0; h < NH; h++) {
            size_t a0 = (((size_t)(b * NH + h)) * TT + t0) * HD + 48 + c2;
            size_t a1 = (((size_t)(b * NH + h)) * TT + t1) * HD + 48 + c2;
            *(uint32_t*)(g_kh + a0)     = h1a;
            *(uint32_t*)(g_kh + a0 + 8) = h2a;
            *(uint32_t*)(g_kh + a1)     = h1b;
            *(uint32_t*)(g_kh + a1 + 8) = h2b;
        }
    }
}

// ======================= kvb GEMM (single-term) with fused scatter =======================
__global__ __launch_bounds__(256, 2) void kvb_gemm()
{
    extern __shared__ __align__(16) char smem[];
    const int tid = threadIdx.x, wid = tid >> 5, lane = tid & 31;
    const int warp_m = wid >> 2, warp_n = wid & 3;
    const int m0 = blockIdx.y * 128, n0 = blockIdx.x * 128;
    uint32_t smem_base = smem_u32(smem);

    const char* base[2] = { (const char*)(g_lth + (size_t)m0 * RR),
                            (const char*)(g_Wbh + (size_t)n0 * RR) };
    const size_t ldbytes = (size_t)RR * 2;
    const int nch = RR >> 5;

    const int lm = lane & 15, lh = lane >> 4;
    const int g = lane >> 3, r = lane & 7;
    const int r4 = lane >> 2, c2 = (lane & 3) * 2;

    float acc[4][4][4];
    #pragma unroll
    for (int i = 0; i < 4; i++)
        #pragma unroll
        for (int j = 0; j < 4; j++)
            #pragma unroll
            for (int e = 0; e < 4; e++) acc[i][j][e] = 0.f;

    GEMM_LOAD_CHUNK2(0, 0);
    GEMM_LOAD_CHUNK2(1, 1);

    for (int ch = 0; ch < nch; ch++) {
        asm volatile("cp.async.wait_group 1;");
        __syncthreads();
        if (ch + 2 < nch) { GEMM_LOAD_CHUNK2(ch + 2, (ch + 2) % NSTAGE); }
        else asm volatile("cp.async.commit_group;");
        const uint32_t smA  = smem_base + (ch % NSTAGE) * GBUF2_B;
        const uint32_t smBh = smA + GTILE_B;
        #pragma unroll
        for (int k16 = 0; k16 < 2; k16++) {
            uint32_t a[4][4];
            #pragma unroll
            for (int fm = 0; fm < 4; fm++)
                ldsm4(a[fm], smA + ((warp_m * 64 + fm * 16 + lm) * GPAD
                                    + k16 * 16 + lh * 8) * 2);
            uint32_t bh[4][2];
            #pragma unroll
            for (int fp = 0; fp < 2; fp++) {
                int row = warp_n * 32 + fp * 16 + ((g >> 1) << 3) + r;
                int off = (row * GPAD + (g & 1) * 8 + k16 * 16) * 2;
                uint32_t t4[4];
                ldsm4(t4, smBh + off);
                bh[fp*2][0]=t4[0]; bh[fp*2][1]=t4[1]; bh[fp*2+1][0]=t4[2]; bh[fp*2+1][1]=t4[3];
            }
            #pragma unroll
            for (int fm = 0; fm < 4; fm++)
                #pragma unroll
                for (int fn = 0; fn < 4; fn++)
                    mma16816(acc[fm][fn], a[fm], bh[fn]);
        }
    }

    #pragma unroll
    for (int fm = 0; fm < 4; fm++) {
        int bt0 = m0 + warp_m * 64 + fm * 16 + r4;
        int bt1 = bt0 + 8;
        int t0 = bt0 & (TT - 1), t1 = bt1 & (TT - 1);
        int b  = bt0 >> 11;
        #pragma unroll
        for (int fn = 0; fn < 4; fn++) {
            int n = n0 + warp_n * 32 + fn * 8 + c2;
            int h = n / 112, rr2 = n % 112;
            size_t hb = (size_t)(b * NH + h) * TT;
            if (rr2 < NOPE) {
                size_t a0 = (hb + t0) * HD + rr2, a1 = (hb + t1) * HD + rr2;
                *(uint32_t*)(g_kh + a0) = packh(acc[fm][fn][0], acc[fm][fn][1]);
                *(uint32_t*)(g_kh + a1) = packh(acc[fm][fn][2], acc[fm][fn][3]);
            } else {
                int d = rr2 - NOPE;
                size_t a0 = (hb + t0) * VD + d, a1 = (hb + t1) * VD + d;
                *(uint32_t*)(g_vh + a0) = packh(acc[fm][fn][0], acc[fm][fn][1]);
                *(uint32_t*)(g_vh + a1) = packh(acc[fm][fn][2], acc[fm][fn][3]);
            }
        }
    }
}

// ======================= Wo GEMM (single-term fp16 B) =======================
__global__ __launch_bounds__(256, 2) void wo_gemm(float* __restrict__ C)
{
    extern __shared__ __align__(16) char smem[];
    const int tid = threadIdx.x, wid = tid >> 5, lane = tid & 31;
    const int warp_m = wid >> 2, warp_n = wid & 3;
    const int m0 = blockIdx.y * 128, n0 = blockIdx.x * 128;
    uint32_t smem_base = smem_u32(smem);

    const char* base[2] = { (const char*)(g_aoh + (size_t)m0 * DD),
                            (const char*)(g_Woh + (size_t)n0 * DD) };
    const size_t ldbytes = (size_t)DD * 2;
    const int nch = DD >> 5;

    const int lm = lane & 15, lh = lane >> 4;
    const int g = lane >> 3, r = lane & 7;

    float acc[4][4][4];
    #pragma unroll
    for (int i = 0; i < 4; i++)
        #pragma unroll
        for (int j = 0; j < 4; j++)
            #pragma unroll
            for (int e = 0; e < 4; e++) acc[i][j][e] = 0.f;

    GEMM_LOAD_CHUNK2(0, 0);
    GEMM_LOAD_CHUNK2(1, 1);

    for (int ch = 0; ch < nch; ch++) {
        asm volatile("cp.async.wait_group 1;");
        __syncthreads();
        if (ch + 2 < nch) { GEMM_LOAD_CHUNK2(ch + 2, (ch + 2) % NSTAGE); }
        else asm volatile("cp.async.commit_group;");
        const uint32_t smA  = smem_base + (ch % NSTAGE) * GBUF2_B;
        const uint32_t smBh = smA + GTILE_B;
        #pragma unroll
        for (int k16 = 0; k16 < 2; k16++) {
            uint32_t a[4][4];
            #pragma unroll
            for (int fm = 0; fm < 4; fm++)
                ldsm4(a[fm], smA + ((warp_m * 64 + fm * 16 + lm) * GPAD
                                    + k16 * 16 + lh * 8) * 2);
            uint32_t bh[4][2];
            #pragma unroll
            for (int fp = 0; fp < 2; fp++) {
                int row = warp_n * 32 + fp * 16 + ((g >> 1) << 3) + r;
                int off = (row * GPAD + (g & 1) * 8 + k16 * 16) * 2;
                uint32_t t4[4];
                ldsm4(t4, smBh + off);
                bh[fp*2][0]=t4[0]; bh[fp*2][1]=t4[1]; bh[fp*2+1][0]=t4[2]; bh[fp*2+1][1]=t4[3];
            }
            #pragma unroll
            for (int fm = 0; fm < 4; fm++)
                #pragma unroll
                for (int fn = 0; fn < 4; fn++)
                    mma16816(acc[fm][fn], a[fm], bh[fn]);
        }
    }

    const int r4 = lane >> 2, c2 = (lane & 3) * 2;
    #pragma unroll
    for (int fm = 0; fm < 4; fm++) {
        #pragma unroll
        for (int fn = 0; fn < 4; fn++) {
            int m = m0 + warp_m * 64 + fm * 16 + r4;
            int n = n0 + warp_n * 32 + fn * 8 + c2;
            *(float2*)&C[(size_t)m * DD + n] = make_float2(acc[fm][fn][0], acc[fm][fn][1]);
            *(float2*)&C[(size_t)(m + 8) * DD + n] = make_float2(acc[fm][fn][2], acc[fm][fn][3]);
        }
    }
}

// ---------------- flash attention: paired q-tiles, S 2-term (K fp16) ----------------
#define FPAD 72
#define FOVH (64 * FPAD)         // V-hi half-offset
#define FQLO (2 * 64 * FPAD)     // persistent Q-lo half-offset

__global__ __launch_bounds__(256, 2) void flash_mma()
{
    __shared__ __align__(16) __half sm[FQLO + 128 * FPAD];   // 36864 B

    const int tid = threadIdx.x, wid = tid >> 5, lane = tid & 31;
    const int bh = blockIdx.y;
    const int b = bh >> 4, h = bh & (NH - 1);
    const uint32_t sb = smem_u32(sm);

    const int lm = lane & 15, lh = lane >> 4;
    const int g = lane >> 3, r8 = lane & 7;
    const int r4 = lane >> 2, c2 = (lane & 3) * 2;

    const __half* khb = g_kh + (size_t)bh * TT * HD;
    const __half* vhb = g_vh + (size_t)bh * TT * VD;

    const uint32_t qlo_addr = sb + (FQLO + (wid * 16 + lm) * FPAD + lh * 8) * 2;
    const int npairs = TT / 128 - 1;   // 15

    #pragma unroll 1
    for (int ph = 0; ph < 2; ph++) {
        const int qtile = ph ? (int)blockIdx.x : (npairs - (int)blockIdx.x);
        const int qb = qtile * 128;

        __syncthreads();
        {   // stage Q-hi across Kh+Vh regions (128 rows), Q-lo persistent
            const __half* qhp = g_qh + ((size_t)bh * TT + qb) * HD;
            const __half* qlp = g_ql + ((size_t)bh * TT + qb) * HD;
            for (int i = tid; i < 128 * 8; i += 256) {
                int r = i >> 3, s = i & 7;
                *(uint4*)(sm + r * FPAD + s * 8) = *(const uint4*)(qhp + r * 64 + s * 8);
                *(uint4*)(sm + FQLO + r * FPAD + s * 8) = *(const uint4*)(qlp + r * 64 + s * 8);
            }
        }
        __syncthreads();

        uint32_t qh[4][4];
        #pragma unroll
        for (int ks = 0; ks < 4; ks++)
            ldsm4(qh[ks], sb + ((wid * 16 + lm) * FPAD + ks * 16 + lh * 8) * 2);

        float o[8][4];
        #pragma unroll
        for (int i = 0; i < 8; i++)
            #pragma unroll
            for (int e = 0; e < 4; e++) o[i][e] = 0.f;
        float mrow[2] = { -1e30f, -1e30f };
        float lsum[2] = { 0.f, 0.f };

        const int ntiles = qtile * 2 + 2;
        const int q0 = qb + wid * 16 + r4;
        const int q1 = q0 + 8;

        for (int it = 0; it < ntiles; it++) {
            const int j0 = it * 64;
            __syncthreads();
            for (int i = tid; i < 64 * 4; i += 256) {   // 2 mats x 64 rows x 8 segs / 2
                int r = (i >> 3) & 63, s = i & 7;
                int mat = i >> 9;
                // i in [0,512): 2 iterations per thread cover K then V
                (void)mat;
            }
            // explicit 2-matrix staging: 1024 uint4 over 256 threads = 4 each
            for (int i = tid; i < 2 * 64 * 8; i += 256) {
                int mat = i >> 9, rem = i & 511;
                int r = rem >> 3, s = rem & 7;
                const __half* srcb = mat ? vhb : khb;
                size_t gsrc = (size_t)(j0 + r) * 64 + s * 8;
                *(uint4*)(sm + mat * FOVH + r * FPAD + s * 8) = *(const uint4*)(srcb + gsrc);
            }
            __syncthreads();

            float s[8][4];
            #pragma unroll
            for (int i = 0; i < 8; i++)
                #pragma unroll
                for (int e = 0; e < 4; e++) s[i][e] = 0.f;

            #pragma unroll
            for (int ks = 0; ks < 4; ks++) {
                uint32_t qlf[4];
                ldsm4(qlf, qlo_addr + ks * 32);
                #pragma unroll
                for (int fp = 0; fp < 4; fp++) {
                    const int krow = fp * 16 + ((g >> 1) << 3) + r8;
                    uint32_t addr = sb + (krow * FPAD + (g & 1) * 8 + ks * 16) * 2;
                    uint32_t bhf[4];
                    ldsm4(bhf, addr);
                    mma16816(s[fp*2],   qh[ks], bhf);
                    mma16816(s[fp*2],   qlf,    bhf);
                    mma16816(s[fp*2+1], qh[ks], bhf + 2);
                    mma16816(s[fp*2+1], qlf,    bhf + 2);
                }
            }

            const bool need_mask = (it >= ntiles - 2);
            if (need_mask) {
                #pragma unroll
                for (int fn = 0; fn < 8; fn++) {
                    #pragma unroll
                    for (int e = 0; e < 4; e++) {
                        int kv = j0 + fn * 8 + c2 + (e & 1);
                        int qq = (e < 2) ? q0 : q1;
                        if (kv > qq) s[fn][e] = -1e30f;
                    }
                }
            }

            float tm0 = -1e30f, tm1 = -1e30f;
            #pragma unroll
            for (int fn = 0; fn < 8; fn++) {
                tm0 = fmaxf(tm0, fmaxf(s[fn][0], s[fn][1]));
                tm1 = fmaxf(tm1, fmaxf(s[fn][2], s[fn][3]));
            }
            tm0 = fmaxf(tm0, __shfl_xor_sync(~0u, tm0, 1));
            tm0 = fmaxf(tm0, __shfl_xor_sync(~0u, tm0, 2));
            tm1 = fmaxf(tm1, __shfl_xor_sync(~0u, tm1, 1));
            tm1 = fmaxf(tm1, __shfl_xor_sync(~0u, tm1, 2));

            float mn0 = fmaxf(mrow[0], tm0), mn1 = fmaxf(mrow[1], tm1);
            float cr0 = exp2f(mrow[0] - mn0), cr1 = exp2f(mrow[1] - mn1);
            mrow[0] = mn0; mrow[1] = mn1;
            lsum[0] *= cr0; lsum[1] *= cr1;
            #pragma unroll
            for (int fn = 0; fn < 8; fn++) {
                o[fn][0] *= cr0; o[fn][1] *= cr0;
                o[fn][2] *= cr1; o[fn][3] *= cr1;
            }

            #pragma unroll
            for (int fn = 0; fn < 8; fn++) {
                s[fn][0] = exp2f(s[fn][0] - mn0);
                s[fn][1] = exp2f(s[fn][1] - mn0);
                s[fn][2] = exp2f(s[fn][2] - mn1);
                s[fn][3] = exp2f(s[fn][3] - mn1);
                lsum[0] += s[fn][0] + s[fn][1];
                lsum[1] += s[fn][2] + s[fn][3];
            }

            #pragma unroll
            for (int ks = 0; ks < 4; ks++) {
                uint32_t aph[4], apl[4];
                aph[0] = packh(s[ks*2][0], s[ks*2][1]);
                aph[1] = packh(s[ks*2][2], s[ks*2][3]);
                aph[2] = packh(s[ks*2+1][0], s[ks*2+1][1]);
                aph[3] = packh(s[ks*2+1][2], s[ks*2+1][3]);
                apl[0] = pack_lo_resid(s[ks*2][0], s[ks*2][1]);
                apl[1] = pack_lo_resid(s[ks*2][2], s[ks*2][3]);
                apl[2] = pack_lo_resid(s[ks*2+1][0], s[ks*2+1][1]);
                apl[3] = pack_lo_resid(s[ks*2+1][2], s[ks*2+1][3]);

                const int vrow = ks * 16 + (g & 1) * 8 + r8;
                #pragma unroll
                for (int np = 0; np < 4; np++) {
                    const int vcol = np * 16 + lh * 8;
                    uint32_t addr = sb + (FOVH + vrow * FPAD + vcol) * 2;
                    uint32_t bvh[4];
                    ldsm4t(bvh, addr);
                    mma16816(o[np*2],   aph, bvh);
                    mma16816(o[np*2],   apl, bvh);
                    mma16816(o[np*2+1], aph, bvh + 2);
                    mma16816(o[np*2+1], apl, bvh + 2);
                }
            }
        }

        lsum[0] += __shfl_xor_sync(~0u, lsum[0], 1);
        lsum[0] += __shfl_xor_sync(~0u, lsum[0], 2);
        lsum[1] += __shfl_xor_sync(~0u, lsum[1], 1);
        lsum[1] += __shfl_xor_sync(~0u, lsum[1], 2);
        const float inv0 = 1.f / lsum[0], inv1 = 1.f / lsum[1];

        __half* ob0 = g_aoh + ((size_t)(b * TT + q0)) * (NH * VD) + h * VD;
        __half* ob1 = g_aoh + ((size_t)(b * TT + q1)) * (NH * VD) + h * VD;
        #pragma unroll
        for (int fn = 0; fn < 8; fn++) {
            *(uint32_t*)(ob0 + fn * 8 + c2) = packh(o[fn][0] * inv0, o[fn][1] * inv0);
            *(uint32_t*)(ob1 + fn * 8 + c2) = packh(o[fn][2] * inv1, o[fn][3] * inv1);
        }
    }
}

// ---------------- launch ----------------
extern "C" void kernel_launch(void* const* d_in, const int* in_sizes, int n_in,
                              void* d_out, int out_size)
{
    const float* x    = (const float*)d_in[0];
    const float* cosp = (const float*)d_in[1];
    const float* sinp = (const float*)d_in[2];
    const float* Wq   = (const float*)d_in[3];
    const float* qw   = (const float*)d_in[4];
    const float* Wkva = (const float*)d_in[5];
    const float* kvaw = (const float*)d_in[6];
    const float* Wkvb = (const float*)d_in[7];
    const float* Wo   = (const float*)d_in[8];
    float* out = (float*)d_out;

    cudaFuncSetAttribute(proj1_gemm, cudaFuncAttributeMaxDynamicSharedMemorySize, NSTAGE * GBUF_B);
    cudaFuncSetAttribute(kvb_gemm,   cudaFuncAttributeMaxDynamicSharedMemorySize, NSTAGE * GBUF2_B);
    cudaFuncSetAttribute(wo_gemm,    cudaFuncAttributeMaxDynamicSharedMemorySize, NSTAGE * GBUF2_B);

    cvt_all<<<(QTOT + 255) / 256, 256>>>(x, Wq, Wkva, Wkvb, Wo);

    {
        dim3 g(W1_ROWS / 128, MTOT / 128);
        proj1_gemm<<<g, 256, NSTAGE * GBUF_B>>>(cosp, sinp, qw, kvaw);
    }
    {
        dim3 g(KVB_N / 128, MTOT / 128);
        kvb_gemm<<<g, 256, NSTAGE * GBUF2_B>>>();
    }
    {
        dim3 g(TT / 256, BB * NH);
        flash_mma<<<g, 256>>>();
    }
    {
        dim3 g(DD / 128, MTOT / 128);
        wo_gemm<<<g, 256, NSTAGE * GBUF2_B>>>(out);
    }
}

// round 17
// speedup vs baseline: 1.5456x; 1.1330x over previous
#include <cuda_runtime.h>
#include <cuda_fp16.h>
#include <math.h>
#include <cstdint>

#define BB 2
#define TT 2048
#define DD 1024
#define NH 16
#define HD 64      // NOPE_D + ROPE_D
#define NOPE 48
#define ROPED 16
#define RR 128
#define VD 64
#define KVB_N (NH * (NOPE + VD))   // 1792
#define MTOT (BB * TT)             // 4096
#define W1_ROWS 1280               // 1024 (Wq) + 128 (latent) + 16 (rope) + 112 pad
#define QSCALE 0.18033688011112042f   // 0.125 * log2(e)

// ---------------- device scratch ----------------
__device__ __align__(256) __half g_qh[BB*NH*TT*HD], g_ql[BB*NH*TT*HD];
__device__ __align__(256) __half g_kh[BB*NH*TT*HD];
__device__ __align__(256) __half g_vh[BB*NH*TT*VD];

__device__ __align__(256) __half g_xh [MTOT * DD];
__device__ __align__(256) __half g_W1h[W1_ROWS * DD];
__device__ __align__(256) __half g_Wbh[KVB_N * RR];
__device__ __align__(256) __half g_Woh[DD * DD];
__device__ __align__(256) __half g_lth[MTOT * RR];
__device__ __align__(256) __half g_aoh[MTOT * DD];

// ======================= helpers =======================
__device__ __forceinline__ uint32_t smem_u32(const void* p) {
    uint32_t a;
    asm("{ .reg .u64 t; cvta.to.shared.u64 t, %1; cvt.u32.u64 %0, t; }" : "=r"(a) : "l"(p));
    return a;
}
__device__ __forceinline__ void mma16816(float* c, const uint32_t* a, const uint32_t* b) {
    asm volatile("mma.sync.aligned.m16n8k16.row.col.f32.f16.f16.f32 "
        "{%0,%1,%2,%3}, {%4,%5,%6,%7}, {%8,%9}, {%0,%1,%2,%3};"
        : "+f"(c[0]), "+f"(c[1]), "+f"(c[2]), "+f"(c[3])
        : "r"(a[0]), "r"(a[1]), "r"(a[2]), "r"(a[3]), "r"(b[0]), "r"(b[1]));
}
__device__ __forceinline__ void ldsm4(uint32_t* r, uint32_t addr) {
    asm volatile("ldmatrix.sync.aligned.m8n8.x4.shared.b16 {%0,%1,%2,%3}, [%4];"
        : "=r"(r[0]), "=r"(r[1]), "=r"(r[2]), "=r"(r[3]) : "r"(addr));
}
__device__ __forceinline__ void ldsm4t(uint32_t* r, uint32_t addr) {
    asm volatile("ldmatrix.sync.aligned.m8n8.x4.trans.shared.b16 {%0,%1,%2,%3}, [%4];"
        : "=r"(r[0]), "=r"(r[1]), "=r"(r[2]), "=r"(r[3]) : "r"(addr));
}
__device__ __forceinline__ uint32_t packh(float lo, float hi) {
    uint32_t d;
    asm("cvt.rn.f16x2.f32 %0, %1, %2;" : "=r"(d) : "f"(hi), "f"(lo));
    return d;
}
__device__ __forceinline__ uint32_t pack_lo_resid(float v0, float v1) {
    float h0 = __half2float(__float2half(v0));
    float h1 = __half2float(__float2half(v1));
    return packh(v0 - h0, v1 - h1);
}

// ======================= fused conversions =======================
#define QX  (MTOT * DD / 4)
#define QW1 (W1_ROWS * DD / 4)
#define QWB (KVB_N * RR / 4)
#define QWO (DD * DD / 4)
#define QTOT (QX + QW1 + QWB + QWO)

__device__ __forceinline__ void do_h(const float* s, __half* dh, int e) {
    float4 v = *(const float4*)(s + e);
    ((__half2*)(dh + e))[0] = __half2(__float2half(v.x), __float2half(v.y));
    ((__half2*)(dh + e))[1] = __half2(__float2half(v.z), __float2half(v.w));
}

__global__ __launch_bounds__(256) void cvt_all(
    const float* __restrict__ x,    const float* __restrict__ Wq,
    const float* __restrict__ Wkva, const float* __restrict__ Wkvb,
    const float* __restrict__ Wo)
{
    int qi = blockIdx.x * blockDim.x + threadIdx.x;
    if (qi >= QTOT) return;
    if (qi < QX) { do_h(x, g_xh, qi * 4); return; }
    qi -= QX;
    if (qi < QW1) {
        int e = qi * 4;
        if (e < DD * DD) { do_h(Wq, g_W1h, e); }
        else if (e < (DD + 144) * DD) {
            float4 v = *(const float4*)(Wkva + (e - DD * DD));
            ((__half2*)(g_W1h + e))[0] = __half2(__float2half(v.x), __float2half(v.y));
            ((__half2*)(g_W1h + e))[1] = __half2(__float2half(v.z), __float2half(v.w));
        } else {
            __half2 z(__half(0.f), __half(0.f));
            ((__half2*)(g_W1h + e))[0] = z; ((__half2*)(g_W1h + e))[1] = z;
        }
        return;
    }
    qi -= QW1;
    if (qi < QWB) { do_h(Wkvb, g_Wbh, qi * 4); return; }
    qi -= QWB;
    do_h(Wo, g_Woh, qi * 4);
}

// ======================= shared GEMM plumbing =======================
#define GPAD 40
#define GTILE_B (128 * GPAD * 2)
#define NSTAGE 3
#define GBUF2_B (2 * GTILE_B)
#define GEMM_LOAD_CHUNK2(ch, buf)                                              \
    do {                                                                       \
        const int k0b = ((ch) << 5) * 2;                                       \
        _Pragma("unroll")                                                      \
        for (int it = 0; it < 4; it++) {                                       \
            int i = tid + it * 256;                                            \
            int mat = i >> 9, rem = i & 511;                                   \
            int row = rem >> 2, seg = rem & 3;                                 \
            const char* src = base[mat] + (size_t)row * ldbytes + k0b + seg * 16; \
            uint32_t dst = smem_base + (buf) * GBUF2_B + mat * GTILE_B         \
                         + (row * GPAD + seg * 8) * 2;                         \
            asm volatile("cp.async.cg.shared.global [%0], [%1], 16;" :: "r"(dst), "l"(src)); \
        }                                                                      \
        asm volatile("cp.async.commit_group;");                                \
    } while (0)

// ======================= proj1 (single-term) =======================
__global__ __launch_bounds__(256, 2) void proj1_gemm(
    const float* __restrict__ cosp, const float* __restrict__ sinp,
    const float* __restrict__ qw,   const float* __restrict__ kvaw)
{
    extern __shared__ __align__(16) char smem[];
    const int tid = threadIdx.x, wid = tid >> 5, lane = tid & 31;
    const int m0 = blockIdx.y * 128, n0 = blockIdx.x * 128;
    uint32_t smem_base = smem_u32(smem);

    const char* base[2] = { (const char*)(g_xh  + (size_t)m0 * DD),
                            (const char*)(g_W1h + (size_t)n0 * DD) };
    const size_t ldbytes = (size_t)DD * 2;
    const int nch = DD >> 5;

    const int lm = lane & 15, lh = lane >> 4;
    const int g = lane >> 3, r8 = lane & 7;
    const int r4 = lane >> 2, c2 = (lane & 3) * 2;

    float acc[16][4];
    #pragma unroll
    for (int i = 0; i < 16; i++)
        #pragma unroll
        for (int e = 0; e < 4; e++) acc[i][e] = 0.f;

    GEMM_LOAD_CHUNK2(0, 0);
    GEMM_LOAD_CHUNK2(1, 1);

    for (int ch = 0; ch < nch; ch++) {
        asm volatile("cp.async.wait_group 1;");
        __syncthreads();
        if (ch + 2 < nch) { GEMM_LOAD_CHUNK2(ch + 2, (ch + 2) % NSTAGE); }
        else asm volatile("cp.async.commit_group;");
        const uint32_t smA  = smem_base + (ch % NSTAGE) * GBUF2_B;
        const uint32_t smBh = smA + GTILE_B;
        #pragma unroll
        for (int k16 = 0; k16 < 2; k16++) {
            uint32_t a[4];
            ldsm4(a, smA + ((wid * 16 + lm) * GPAD + k16 * 16 + lh * 8) * 2);
            #pragma unroll
            for (int fp = 0; fp < 8; fp++) {
                int row = fp * 16 + ((g >> 1) << 3) + r8;
                int off = (row * GPAD + (g & 1) * 8 + k16 * 16) * 2;
                uint32_t t4[4];
                ldsm4(t4, smBh + off);
                mma16816(acc[fp*2],   a, t4);
                mma16816(acc[fp*2+1], a, t4 + 2);
            }
        }
    }

    const int bt0 = m0 + wid * 16 + r4;
    const int bt1 = bt0 + 8;
    const int t0 = bt0 & (TT - 1), t1 = bt1 & (TT - 1);
    const int b  = bt0 >> 11;

    if (blockIdx.x < 8) {
        float s00 = 0, s01 = 0, s10 = 0, s11 = 0;
        #pragma unroll
        for (int fn = 0; fn < 16; fn++) {
            float a0 = acc[fn][0]*acc[fn][0] + acc[fn][1]*acc[fn][1];
            float a1 = acc[fn][2]*acc[fn][2] + acc[fn][3]*acc[fn][3];
            if (fn < 8) { s00 += a0; s10 += a1; } else { s01 += a0; s11 += a1; }
        }
        #pragma unroll
        for (int o = 1; o <= 2; o <<= 1) {
            s00 += __shfl_xor_sync(~0u, s00, o);
            s01 += __shfl_xor_sync(~0u, s01, o);
            s10 += __shfl_xor_sync(~0u, s10, o);
            s11 += __shfl_xor_sync(~0u, s11, o);
        }
        float n00 = rsqrtf(s00 * (1.f/HD) + 1e-6f), n01 = rsqrtf(s01 * (1.f/HD) + 1e-6f);
        float n10 = rsqrtf(s10 * (1.f/HD) + 1e-6f), n11 = rsqrtf(s11 * (1.f/HD) + 1e-6f);
        #pragma unroll
        for (int fn = 0; fn < 16; fn++) {
            int d0 = (fn & 7) * 8 + c2;
            float w0 = qw[d0], w1 = qw[d0 + 1];
            float f0 = (fn < 8) ? n00 : n01, f1 = (fn < 8) ? n10 : n11;
            acc[fn][0] *= f0 * w0; acc[fn][1] *= f0 * w1;
            acc[fn][2] *= f1 * w0; acc[fn][3] *= f1 * w1;
        }
        float c00 = cosp[t0*8 + c2], c01 = cosp[t0*8 + c2 + 1];
        float sn00 = sinp[t0*8 + c2], sn01 = sinp[t0*8 + c2 + 1];
        float c10 = cosp[t1*8 + c2], c11 = cosp[t1*8 + c2 + 1];
        float sn10 = sinp[t1*8 + c2], sn11 = sinp[t1*8 + c2 + 1];
        #pragma unroll
        for (int hp = 0; hp < 2; hp++) {
            int f1i = hp * 8 + 6, f2i = f1i + 1;
            float x10 = acc[f1i][0], x11 = acc[f1i][1], x12 = acc[f1i][2], x13 = acc[f1i][3];
            float x20 = acc[f2i][0], x21 = acc[f2i][1], x22 = acc[f2i][2], x23 = acc[f2i][3];
            acc[f1i][0] = x10*c00 - x20*sn00; acc[f1i][1] = x11*c01 - x21*sn01;
            acc[f1i][2] = x12*c10 - x22*sn10; acc[f1i][3] = x13*c11 - x23*sn11;
            acc[f2i][0] = x20*c00 + x10*sn00; acc[f2i][1] = x21*c01 + x11*sn01;
            acc[f2i][2] = x22*c10 + x12*sn10; acc[f2i][3] = x23*c11 + x13*sn11;
        }
        #pragma unroll
        for (int fn = 0; fn < 16; fn++) {
            #pragma unroll
            for (int e = 0; e < 4; e++) acc[fn][e] *= QSCALE;
        }
        #pragma unroll
        for (int fn = 0; fn < 16; fn++) {
            int hg = (n0 >> 6) + (fn >> 3);
            int d  = (fn & 7) * 8 + c2;
            size_t a0 = (((size_t)(b * NH + hg)) * TT + t0) * HD + d;
            size_t a1 = (((size_t)(b * NH + hg)) * TT + t1) * HD + d;
            *(uint32_t*)(g_qh + a0) = packh(acc[fn][0], acc[fn][1]);
            *(uint32_t*)(g_ql + a0) = pack_lo_resid(acc[fn][0], acc[fn][1]);
            *(uint32_t*)(g_qh + a1) = packh(acc[fn][2], acc[fn][3]);
            *(uint32_t*)(g_ql + a1) = pack_lo_resid(acc[fn][2], acc[fn][3]);
        }
    } else if (blockIdx.x == 8) {
        float s0 = 0, s1 = 0;
        #pragma unroll
        for (int fn = 0; fn < 16; fn++) {
            s0 += acc[fn][0]*acc[fn][0] + acc[fn][1]*acc[fn][1];
            s1 += acc[fn][2]*acc[fn][2] + acc[fn][3]*acc[fn][3];
        }
        #pragma unroll
        for (int o = 1; o <= 2; o <<= 1) {
            s0 += __shfl_xor_sync(~0u, s0, o);
            s1 += __shfl_xor_sync(~0u, s1, o);
        }
        float n0f = rsqrtf(s0 * (1.f/RR) + 1e-6f), n1f = rsqrtf(s1 * (1.f/RR) + 1e-6f);
        #pragma unroll
        for (int fn = 0; fn < 16; fn++) {
            int r = fn * 8 + c2;
            float w0 = kvaw[r], w1 = kvaw[r + 1];
            *(uint32_t*)(g_lth + (size_t)bt0 * RR + r) =
                packh(acc[fn][0] * n0f * w0, acc[fn][1] * n0f * w1);
            *(uint32_t*)(g_lth + (size_t)bt1 * RR + r) =
                packh(acc[fn][2] * n1f * w0, acc[fn][3] * n1f * w1);
        }
    } else {
        float c00 = cosp[t0*8 + c2], c01 = cosp[t0*8 + c2 + 1];
        float sn00 = sinp[t0*8 + c2], sn01 = sinp[t0*8 + c2 + 1];
        float c10 = cosp[t1*8 + c2], c11 = cosp[t1*8 + c2 + 1];
        float sn10 = sinp[t1*8 + c2], sn11 = sinp[t1*8 + c2 + 1];
        float x10 = acc[0][0], x11 = acc[0][1], x12 = acc[0][2], x13 = acc[0][3];
        float x20 = acc[1][0], x21 = acc[1][1], x22 = acc[1][2], x23 = acc[1][3];
        float o10 = x10*c00 - x20*sn00, o11 = x11*c01 - x21*sn01;
        float o12 = x12*c10 - x22*sn10, o13 = x13*c11 - x23*sn11;
        float o20 = x20*c00 + x10*sn00, o21 = x21*c01 + x11*sn01;
        float o22 = x22*c10 + x12*sn10, o23 = x23*c11 + x13*sn11;
        uint32_t h1a = packh(o10, o11);
        uint32_t h1b = packh(o12, o13);
        uint32_t h2a = packh(o20, o21);
        uint32_t h2b = packh(o22, o23);
        #pragma unroll
        for (int h = 0; h < NH; h++) {
            size_t a0 = (((size_t)(b * NH + h)) * TT + t0) * HD + 48 + c2;
            size_t a1 = (((size_t)(b * NH + h)) * TT + t1) * HD + 48 + c2;
            *(uint32_t*)(g_kh + a0)     = h1a;
            *(uint32_t*)(g_kh + a0 + 8) = h2a;
            *(uint32_t*)(g_kh + a1)     = h1b;
            *(uint32_t*)(g_kh + a1 + 8) = h2b;
        }
    }
}

// ======================= kvb GEMM (single-term) with fused scatter =======================
__global__ __launch_bounds__(256, 2) void kvb_gemm()
{
    extern __shared__ __align__(16) char smem[];
    const int tid = threadIdx.x, wid = tid >> 5, lane = tid & 31;
    const int warp_m = wid >> 2, warp_n = wid & 3;
    const int m0 = blockIdx.y * 128, n0 = blockIdx.x * 128;
    uint32_t smem_base = smem_u32(smem);

    const char* base[2] = { (const char*)(g_lth + (size_t)m0 * RR),
                            (const char*)(g_Wbh + (size_t)n0 * RR) };
    const size_t ldbytes = (size_t)RR * 2;
    const int nch = RR >> 5;

    const int lm = lane & 15, lh = lane >> 4;
    const int g = lane >> 3, r = lane & 7;
    const int r4 = lane >> 2, c2 = (lane & 3) * 2;

    float acc[4][4][4];
    #pragma unroll
    for (int i = 0; i < 4; i++)
        #pragma unroll
        for (int j = 0; j < 4; j++)
            #pragma unroll
            for (int e = 0; e < 4; e++) acc[i][j][e] = 0.f;

    GEMM_LOAD_CHUNK2(0, 0);
    GEMM_LOAD_CHUNK2(1, 1);

    for (int ch = 0; ch < nch; ch++) {
        asm volatile("cp.async.wait_group 1;");
        __syncthreads();
        if (ch + 2 < nch) { GEMM_LOAD_CHUNK2(ch + 2, (ch + 2) % NSTAGE); }
        else asm volatile("cp.async.commit_group;");
        const uint32_t smA  = smem_base + (ch % NSTAGE) * GBUF2_B;
        const uint32_t smBh = smA + GTILE_B;
        #pragma unroll
        for (int k16 = 0; k16 < 2; k16++) {
            uint32_t a[4][4];
            #pragma unroll
            for (int fm = 0; fm < 4; fm++)
                ldsm4(a[fm], smA + ((warp_m * 64 + fm * 16 + lm) * GPAD
                                    + k16 * 16 + lh * 8) * 2);
            uint32_t bh[4][2];
            #pragma unroll
            for (int fp = 0; fp < 2; fp++) {
                int row = warp_n * 32 + fp * 16 + ((g >> 1) << 3) + r;
                int off = (row * GPAD + (g & 1) * 8 + k16 * 16) * 2;
                uint32_t t4[4];
                ldsm4(t4, smBh + off);
                bh[fp*2][0]=t4[0]; bh[fp*2][1]=t4[1]; bh[fp*2+1][0]=t4[2]; bh[fp*2+1][1]=t4[3];
            }
            #pragma unroll
            for (int fm = 0; fm < 4; fm++)
                #pragma unroll
                for (int fn = 0; fn < 4; fn++)
                    mma16816(acc[fm][fn], a[fm], bh[fn]);
        }
    }

    #pragma unroll
    for (int fm = 0; fm < 4; fm++) {
        int bt0 = m0 + warp_m * 64 + fm * 16 + r4;
        int bt1 = bt0 + 8;
        int t0 = bt0 & (TT - 1), t1 = bt1 & (TT - 1);
        int b  = bt0 >> 11;
        #pragma unroll
        for (int fn = 0; fn < 4; fn++) {
            int n = n0 + warp_n * 32 + fn * 8 + c2;
            int h = n / 112, rr2 = n % 112;
            size_t hb = (size_t)(b * NH + h) * TT;
            if (rr2 < NOPE) {
                size_t a0 = (hb + t0) * HD + rr2, a1 = (hb + t1) * HD + rr2;
                *(uint32_t*)(g_kh + a0) = packh(acc[fm][fn][0], acc[fm][fn][1]);
                *(uint32_t*)(g_kh + a1) = packh(acc[fm][fn][2], acc[fm][fn][3]);
            } else {
                int d = rr2 - NOPE;
                size_t a0 = (hb + t0) * VD + d, a1 = (hb + t1) * VD + d;
                *(uint32_t*)(g_vh + a0) = packh(acc[fm][fn][0], acc[fm][fn][1]);
                *(uint32_t*)(g_vh + a1) = packh(acc[fm][fn][2], acc[fm][fn][3]);
            }
        }
    }
}

// ======================= Wo GEMM (single-term fp16 B) =======================
__global__ __launch_bounds__(256, 2) void wo_gemm(float* __restrict__ C)
{
    extern __shared__ __align__(16) char smem[];
    const int tid = threadIdx.x, wid = tid >> 5, lane = tid & 31;
    const int warp_m = wid >> 2, warp_n = wid & 3;
    const int m0 = blockIdx.y * 128, n0 = blockIdx.x * 128;
    uint32_t smem_base = smem_u32(smem);

    const char* base[2] = { (const char*)(g_aoh + (size_t)m0 * DD),
                            (const char*)(g_Woh + (size_t)n0 * DD) };
    const size_t ldbytes = (size_t)DD * 2;
    const int nch = DD >> 5;

    const int lm = lane & 15, lh = lane >> 4;
    const int g = lane >> 3, r = lane & 7;

    float acc[4][4][4];
    #pragma unroll
    for (int i = 0; i < 4; i++)
        #pragma unroll
        for (int j = 0; j < 4; j++)
            #pragma unroll
            for (int e = 0; e < 4; e++) acc[i][j][e] = 0.f;

    GEMM_LOAD_CHUNK2(0, 0);
    GEMM_LOAD_CHUNK2(1, 1);

    for (int ch = 0; ch < nch; ch++) {
        asm volatile("cp.async.wait_group 1;");
        __syncthreads();
        if (ch + 2 < nch) { GEMM_LOAD_CHUNK2(ch + 2, (ch + 2) % NSTAGE); }
        else asm volatile("cp.async.commit_group;");
        const uint32_t smA  = smem_base + (ch % NSTAGE) * GBUF2_B;
        const uint32_t smBh = smA + GTILE_B;
        #pragma unroll
        for (int k16 = 0; k16 < 2; k16++) {
            uint32_t a[4][4];
            #pragma unroll
            for (int fm = 0; fm < 4; fm++)
                ldsm4(a[fm], smA + ((warp_m * 64 + fm * 16 + lm) * GPAD
                                    + k16 * 16 + lh * 8) * 2);
            uint32_t bh[4][2];
            #pragma unroll
            for (int fp = 0; fp < 2; fp++) {
                int row = warp_n * 32 + fp * 16 + ((g >> 1) << 3) + r;
                int off = (row * GPAD + (g & 1) * 8 + k16 * 16) * 2;
                uint32_t t4[4];
                ldsm4(t4, smBh + off);
                bh[fp*2][0]=t4[0]; bh[fp*2][1]=t4[1]; bh[fp*2+1][0]=t4[2]; bh[fp*2+1][1]=t4[3];
            }
            #pragma unroll
            for (int fm = 0; fm < 4; fm++)
                #pragma unroll
                for (int fn = 0; fn < 4; fn++)
                    mma16816(acc[fm][fn], a[fm], bh[fn]);
        }
    }

    const int r4 = lane >> 2, c2 = (lane & 3) * 2;
    #pragma unroll
    for (int fm = 0; fm < 4; fm++) {
        #pragma unroll
        for (int fn = 0; fn < 4; fn++) {
            int m = m0 + warp_m * 64 + fm * 16 + r4;
            int n = n0 + warp_n * 32 + fn * 8 + c2;
            *(float2*)&C[(size_t)m * DD + n] = make_float2(acc[fm][fn][0], acc[fm][fn][1]);
            *(float2*)&C[(size_t)(m + 8) * DD + n] = make_float2(acc[fm][fn][2], acc[fm][fn][3]);
        }
    }
}

// ---------------- flash attention: paired q-tiles, S 2-term (K fp16) ----------------
#define FPAD 72
#define FOVH (64 * FPAD)         // V-hi half-offset
#define FQLO (2 * 64 * FPAD)     // persistent Q-lo half-offset

__global__ __launch_bounds__(256, 2) void flash_mma()
{
    __shared__ __align__(16) __half sm[FQLO + 128 * FPAD];   // 36864 B

    const int tid = threadIdx.x, wid = tid >> 5, lane = tid & 31;
    const int bh = blockIdx.y;
    const int b = bh >> 4, h = bh & (NH - 1);
    const uint32_t sb = smem_u32(sm);

    const int lm = lane & 15, lh = lane >> 4;
    const int g = lane >> 3, r8 = lane & 7;
    const int r4 = lane >> 2, c2 = (lane & 3) * 2;

    const __half* khb = g_kh + (size_t)bh * TT * HD;
    const __half* vhb = g_vh + (size_t)bh * TT * VD;

    const uint32_t qlo_addr = sb + (FQLO + (wid * 16 + lm) * FPAD + lh * 8) * 2;
    const int npairs = TT / 128 - 1;   // 15

    #pragma unroll 1
    for (int ph = 0; ph < 2; ph++) {
        const int qtile = ph ? (int)blockIdx.x : (npairs - (int)blockIdx.x);
        const int qb = qtile * 128;

        __syncthreads();
        {
            const __half* qhp = g_qh + ((size_t)bh * TT + qb) * HD;
            const __half* qlp = g_ql + ((size_t)bh * TT + qb) * HD;
            for (int i = tid; i < 128 * 8; i += 256) {
                int r = i >> 3, s = i & 7;
                *(uint4*)(sm + r * FPAD + s * 8) = *(const uint4*)(qhp + r * 64 + s * 8);
                *(uint4*)(sm + FQLO + r * FPAD + s * 8) = *(const uint4*)(qlp + r * 64 + s * 8);
            }
        }
        __syncthreads();

        uint32_t qh[4][4];
        #pragma unroll
        for (int ks = 0; ks < 4; ks++)
            ldsm4(qh[ks], sb + ((wid * 16 + lm) * FPAD + ks * 16 + lh * 8) * 2);

        float o[8][4];
        #pragma unroll
        for (int i = 0; i < 8; i++)
            #pragma unroll
            for (int e = 0; e < 4; e++) o[i][e] = 0.f;
        float mrow[2] = { -1e30f, -1e30f };
        float lsum[2] = { 0.f, 0.f };

        const int ntiles = qtile * 2 + 2;
        const int q0 = qb + wid * 16 + r4;
        const int q1 = q0 + 8;

        for (int it = 0; it < ntiles; it++) {
            const int j0 = it * 64;
            __syncthreads();
            for (int i = tid; i < 2 * 64 * 8; i += 256) {
                int mat = i >> 9, rem = i & 511;
                int r = rem >> 3, s = rem & 7;
                const __half* srcb = mat ? vhb : khb;
                size_t gsrc = (size_t)(j0 + r) * 64 + s * 8;
                *(uint4*)(sm + mat * FOVH + r * FPAD + s * 8) = *(const uint4*)(srcb + gsrc);
            }
            __syncthreads();

            float s[8][4];
            #pragma unroll
            for (int i = 0; i < 8; i++)
                #pragma unroll
                for (int e = 0; e < 4; e++) s[i][e] = 0.f;

            #pragma unroll
            for (int ks = 0; ks < 4; ks++) {
                uint32_t qlf[4];
                ldsm4(qlf, qlo_addr + ks * 32);
                #pragma unroll
                for (int fp = 0; fp < 4; fp++) {
                    const int krow = fp * 16 + ((g >> 1) << 3) + r8;
                    uint32_t addr = sb + (krow * FPAD + (g & 1) * 8 + ks * 16) * 2;
                    uint32_t bhf[4];
                    ldsm4(bhf, addr);
                    mma16816(s[fp*2],   qh[ks], bhf);
                    mma16816(s[fp*2],   qlf,    bhf);
                    mma16816(s[fp*2+1], qh[ks], bhf + 2);
                    mma16816(s[fp*2+1], qlf,    bhf + 2);
                }
            }

            const bool need_mask = (it >= ntiles - 2);
            if (need_mask) {
                #pragma unroll
                for (int fn = 0; fn < 8; fn++) {
                    #pragma unroll
                    for (int e = 0; e < 4; e++) {
                        int kv = j0 + fn * 8 + c2 + (e & 1);
                        int qq = (e < 2) ? q0 : q1;
                        if (kv > qq) s[fn][e] = -1e30f;
                    }
                }
            }

            float tm0 = -1e30f, tm1 = -1e30f;
            #pragma unroll
            for (int fn = 0; fn < 8; fn++) {
                tm0 = fmaxf(tm0, fmaxf(s[fn][0], s[fn][1]));
                tm1 = fmaxf(tm1, fmaxf(s[fn][2], s[fn][3]));
            }
            tm0 = fmaxf(tm0, __shfl_xor_sync(~0u, tm0, 1));
            tm0 = fmaxf(tm0, __shfl_xor_sync(~0u, tm0, 2));
            tm1 = fmaxf(tm1, __shfl_xor_sync(~0u, tm1, 1));
            tm1 = fmaxf(tm1, __shfl_xor_sync(~0u, tm1, 2));

            float mn0 = fmaxf(mrow[0], tm0), mn1 = fmaxf(mrow[1], tm1);
            float cr0 = exp2f(mrow[0] - mn0), cr1 = exp2f(mrow[1] - mn1);
            mrow[0] = mn0; mrow[1] = mn1;
            lsum[0] *= cr0; lsum[1] *= cr1;
            #pragma unroll
            for (int fn = 0; fn < 8; fn++) {
                o[fn][0] *= cr0; o[fn][1] *= cr0;
                o[fn][2] *= cr1; o[fn][3] *= cr1;
            }

            #pragma unroll
            for (int fn = 0; fn < 8; fn++) {
                s[fn][0] = exp2f(s[fn][0] - mn0);
                s[fn][1] = exp2f(s[fn][1] - mn0);
                s[fn][2] = exp2f(s[fn][2] - mn1);
                s[fn][3] = exp2f(s[fn][3] - mn1);
                lsum[0] += s[fn][0] + s[fn][1];
                lsum[1] += s[fn][2] + s[fn][3];
            }

            #pragma unroll
            for (int ks = 0; ks < 4; ks++) {
                uint32_t aph[4], apl[4];
                aph[0] = packh(s[ks*2][0], s[ks*2][1]);
                aph[1] = packh(s[ks*2][2], s[ks*2][3]);
                aph[2] = packh(s[ks*2+1][0], s[ks*2+1][1]);
                aph[3] = packh(s[ks*2+1][2], s[ks*2+1][3]);
                apl[0] = pack_lo_resid(s[ks*2][0], s[ks*2][1]);
                apl[1] = pack_lo_resid(s[ks*2][2], s[ks*2][3]);
                apl[2] = pack_lo_resid(s[ks*2+1][0], s[ks*2+1][1]);
                apl[3] = pack_lo_resid(s[ks*2+1][2], s[ks*2+1][3]);

                const int vrow = ks * 16 + (g & 1) * 8 + r8;
                #pragma unroll
                for (int np = 0; np < 4; np++) {
                    const int vcol = np * 16 + lh * 8;
                    uint32_t addr = sb + (FOVH + vrow * FPAD + vcol) * 2;
                    uint32_t bvh[4];
                    ldsm4t(bvh, addr);
                    mma16816(o[np*2],   aph, bvh);
                    mma16816(o[np*2],   apl, bvh);
                    mma16816(o[np*2+1], aph, bvh + 2);
                    mma16816(o[np*2+1], apl, bvh + 2);
                }
            }
        }

        lsum[0] += __shfl_xor_sync(~0u, lsum[0], 1);
        lsum[0] += __shfl_xor_sync(~0u, lsum[0], 2);
        lsum[1] += __shfl_xor_sync(~0u, lsum[1], 1);
        lsum[1] += __shfl_xor_sync(~0u, lsum[1], 2);
        const float inv0 = 1.f / lsum[0], inv1 = 1.f / lsum[1];

        __half* ob0 = g_aoh + ((size_t)(b * TT + q0)) * (NH * VD) + h * VD;
        __half* ob1 = g_aoh + ((size_t)(b * TT + q1)) * (NH * VD) + h * VD;
        #pragma unroll
        for (int fn = 0; fn < 8; fn++) {
            *(uint32_t*)(ob0 + fn * 8 + c2) = packh(o[fn][0] * inv0, o[fn][1] * inv0);
            *(uint32_t*)(ob1 + fn * 8 + c2) = packh(o[fn][2] * inv1, o[fn][3] * inv1);
        }
    }
}

// ---------------- launch ----------------
extern "C" void kernel_launch(void* const* d_in, const int* in_sizes, int n_in,
                              void* d_out, int out_size)
{
    const float* x    = (const float*)d_in[0];
    const float* cosp = (const float*)d_in[1];
    const float* sinp = (const float*)d_in[2];
    const float* Wq   = (const float*)d_in[3];
    const float* qw   = (const float*)d_in[4];
    const float* Wkva = (const float*)d_in[5];
    const float* kvaw = (const float*)d_in[6];
    const float* Wkvb = (const float*)d_in[7];
    const float* Wo   = (const float*)d_in[8];
    float* out = (float*)d_out;

    cudaFuncSetAttribute(proj1_gemm, cudaFuncAttributeMaxDynamicSharedMemorySize, NSTAGE * GBUF2_B);
    cudaFuncSetAttribute(kvb_gemm,   cudaFuncAttributeMaxDynamicSharedMemorySize, NSTAGE * GBUF2_B);
    cudaFuncSetAttribute(wo_gemm,    cudaFuncAttributeMaxDynamicSharedMemorySize, NSTAGE * GBUF2_B);

    cvt_all<<<(QTOT + 255) / 256, 256>>>(x, Wq, Wkva, Wkvb, Wo);

    {
        dim3 g(W1_ROWS / 128, MTOT / 128);
        proj1_gemm<<<g, 256, NSTAGE * GBUF2_B>>>(cosp, sinp, qw, kvaw);
    }
    {
        dim3 g(KVB_N / 128, MTOT / 128);
        kvb_gemm<<<g, 256, NSTAGE * GBUF2_B>>>();
    }
    {
        dim3 g(TT / 256, BB * NH);
        flash_mma<<<g, 256>>>();
    }
    {
        dim3 g(DD / 128, MTOT / 128);
        wo_gemm<<<g, 256, NSTAGE * GBUF2_B>>>(out);
    }
}